// round 10
// baseline (speedup 1.0000x reference)
#include <cuda_runtime.h>
#include <cuda_bf16.h>
#include <math.h>
#include <stdint.h>

#define HEADS 4
#define CD    128
#define TOK   200704          // B * 3136
#define SH    136             // smem stride (bf16) for 128-wide tiles
#define HS2   264             // smem stride (bf16) for 256-wide hidden chunk
#define SV    72              // smem stride (bf16) for vT (64-wide)

// ---------------- scratch ----------------
__device__ float  g_y[(size_t)TOK * CD];          // x + attn_out
__device__ uint2  g_wqkvF[48 * 8 * 32];
__device__ uint2  g_woF  [16 * 8 * 32];
__device__ uint2  g_w1F  [64 * 8 * 32];
__device__ uint2  g_w2F  [16 * 32 * 32];
__device__ float4 g_bm4[64 * HEADS * 4 * 8 * 32];

// ---------------- helpers ----------------
__device__ __forceinline__ void mma_bf16(float d[4], const unsigned a[4], const unsigned b[2]) {
    asm volatile("mma.sync.aligned.m16n8k16.row.col.f32.bf16.bf16.f32 "
                 "{%0,%1,%2,%3}, {%4,%5,%6,%7}, {%8,%9}, {%0,%1,%2,%3};\n"
                 : "+f"(d[0]), "+f"(d[1]), "+f"(d[2]), "+f"(d[3])
                 : "r"(a[0]), "r"(a[1]), "r"(a[2]), "r"(a[3]), "r"(b[0]), "r"(b[1]));
}
__device__ __forceinline__ void mma_bf16_u2(float d[4], const unsigned a[4], uint2 b) {
    asm volatile("mma.sync.aligned.m16n8k16.row.col.f32.bf16.bf16.f32 "
                 "{%0,%1,%2,%3}, {%4,%5,%6,%7}, {%8,%9}, {%0,%1,%2,%3};\n"
                 : "+f"(d[0]), "+f"(d[1]), "+f"(d[2]), "+f"(d[3])
                 : "r"(a[0]), "r"(a[1]), "r"(a[2]), "r"(a[3]), "r"(b.x), "r"(b.y));
}
__device__ __forceinline__ void ldsm4(unsigned a[4], uint32_t addr) {
    asm volatile("ldmatrix.sync.aligned.m8n8.x4.shared.b16 {%0,%1,%2,%3}, [%4];"
                 : "=r"(a[0]), "=r"(a[1]), "=r"(a[2]), "=r"(a[3]) : "r"(addr));
}
__device__ __forceinline__ void ldsm2(unsigned b[2], uint32_t addr) {
    asm volatile("ldmatrix.sync.aligned.m8n8.x2.shared.b16 {%0,%1}, [%2];"
                 : "=r"(b[0]), "=r"(b[1]) : "r"(addr));
}
__device__ __forceinline__ uint32_t smemA_base(const void* p, int stride, int lane) {
    return (uint32_t)__cvta_generic_to_shared(p) +
           (uint32_t)(((lane & 15) * stride + ((lane >> 4) << 3)) * 2);
}
__device__ __forceinline__ uint32_t smemB_base(const void* p, int stride, int lane) {
    return (uint32_t)__cvta_generic_to_shared(p) +
           (uint32_t)(((lane & 7) * stride + (lane & 8)) * 2);
}
__device__ __forceinline__ unsigned pack_bf2(float lo, float hi) {
    unsigned r;
    asm("cvt.rn.bf16x2.f32 %0, %1, %2;" : "=r"(r) : "f"(hi), "f"(lo));
    return r;
}
__device__ __forceinline__ float gelu_fast(float v) {
    float u2 = v * v;
    float u = v * (1.5957691216f + 0.1426926424f * u2);
    float e = __expf(u);
    return __fdividef(v * e, e + 1.f);
}
__device__ __forceinline__ int region_of(int p) { return p < 49 ? 0 : (p < 53 ? 1 : 2); }

// ---------------- K0a: pack weights into fragment layout ----------------
__global__ void pack_weights(const float* __restrict__ wq, const float* __restrict__ wk,
                             const float* __restrict__ wv, const float* __restrict__ wo,
                             const float* __restrict__ w1, const float* __restrict__ w2) {
    int i = blockIdx.x * blockDim.x + threadIdx.x;   // 49152 threads
    if (i < 12288) {
        int lane = i & 31, kt = (i >> 5) & 7, nt = i >> 8;
        int n = nt * 8 + (lane >> 2), kk = kt * 16 + 2 * (lane & 3);
        const float* wsrc = (n < 128) ? wq : (n < 256) ? wk : wv;
        int nn = n & 127;
        uint2 v;
        v.x = pack_bf2(wsrc[kk * 128 + nn],       wsrc[(kk + 1) * 128 + nn]);
        v.y = pack_bf2(wsrc[(kk + 8) * 128 + nn], wsrc[(kk + 9) * 128 + nn]);
        g_wqkvF[i] = v;
    } else if (i < 16384) {
        int j = i - 12288;
        int lane = j & 31, kt = (j >> 5) & 7, nt = j >> 8;
        int n = nt * 8 + (lane >> 2), kk = kt * 16 + 2 * (lane & 3);
        uint2 v;
        v.x = pack_bf2(wo[kk * 128 + n],       wo[(kk + 1) * 128 + n]);
        v.y = pack_bf2(wo[(kk + 8) * 128 + n], wo[(kk + 9) * 128 + n]);
        g_woF[j] = v;
    } else if (i < 32768) {
        int j = i - 16384;
        int lane = j & 31, kt = (j >> 5) & 7, nt = j >> 8;
        int n = nt * 8 + (lane >> 2), kk = kt * 16 + 2 * (lane & 3);
        uint2 v;
        v.x = pack_bf2(w1[kk * 512 + n],       w1[(kk + 1) * 512 + n]);
        v.y = pack_bf2(w1[(kk + 8) * 512 + n], w1[(kk + 9) * 512 + n]);
        g_w1F[j] = v;
    } else {
        int j = i - 32768;
        int lane = j & 31, kt = (j >> 5) & 31, nt = j >> 10;
        int n = nt * 8 + (lane >> 2), kk = kt * 16 + 2 * (lane & 3);
        uint2 v;
        v.x = pack_bf2(w2[kk * 128 + n],       w2[(kk + 1) * 128 + n]);
        v.y = pack_bf2(w2[(kk + 8) * 128 + n], w2[(kk + 9) * 128 + n]);
        g_w2F[j] = v;
    }
}

// ---------------- K0b: bias+mask table ----------------
__device__ __forceinline__ float bm_val(const float* __restrict__ rel, int w, int h, int q, int k) {
    if (q >= 49 || k >= 49) return -1e30f;
    int qi = q / 7, qj = q % 7, ki = k / 7, kj = k % 7;
    int r0 = (ki - qi) % 13; if (r0 < 0) r0 += 13;
    int r1 = (kj - qj) % 13; if (r1 < 0) r1 += 13;
    float bias = rel[(r0 * 13 + r1) * HEADS + h];
    int wr = w >> 3, wc = w & 7;
    int idq = region_of(wr * 7 + qi) * 3 + region_of(wc * 7 + qj);
    int idk = region_of(wr * 7 + ki) * 3 + region_of(wc * 7 + kj);
    return bias + (idq == idk ? 0.f : -100.f);
}
__global__ void build_bm(const float* __restrict__ rel) {
    int i = blockIdx.x * blockDim.x + threadIdx.x;   // 262144
    int lane = i & 31, nt = (i >> 5) & 7, mtile = (i >> 8) & 3, h = (i >> 10) & 3, w = i >> 12;
    int g = lane >> 2, s = lane & 3;
    int rA = mtile * 16 + g, rB = rA + 8, cc = nt * 8 + 2 * s;
    float4 v;
    v.x = bm_val(rel, w, h, rA, cc);
    v.y = bm_val(rel, w, h, rA, cc + 1);
    v.z = bm_val(rel, w, h, rB, cc);
    v.w = bm_val(rel, w, h, rB, cc + 1);
    g_bm4[i] = v;
}

// ---------------- K1: fused LN1 + window attention + O-proj + residual ----------------
__global__ void __launch_bounds__(256, 2) attn_kernel(const float* __restrict__ x,
                                                      const float* __restrict__ gam,
                                                      const float* __restrict__ bet,
                                                      const float* __restrict__ bq,
                                                      const float* __restrict__ bk,
                                                      const float* __restrict__ bv,
                                                      const float* __restrict__ bo) {
    extern __shared__ char smraw[];
    __nv_bfloat16* hS = (__nv_bfloat16*)smraw;
    __nv_bfloat16* qS = (__nv_bfloat16*)(smraw + 17408);
    __nv_bfloat16* kS = (__nv_bfloat16*)(smraw + 34816);
    __nv_bfloat16* vT = (__nv_bfloat16*)(smraw + 52224);
    __nv_bfloat16* oS = hS;

    const int win = blockIdx.x, b = win >> 6, w = win & 63;
    const int wr = w >> 3, wc = w & 7;
    const int warp = threadIdx.x >> 5, lane = threadIdx.x & 31;
    const int g = lane >> 2, s = lane & 3;

    {
        const float4 gm = *(const float4*)(gam + lane * 4);
        const float4 bt = *(const float4*)(bet + lane * 4);
        for (int n = warp; n < 64; n += 8) {
            __nv_bfloat16* dst = hS + n * SH;
            if (n >= 49) {
                ((unsigned*)dst)[lane]      = 0u;
                ((unsigned*)dst)[lane + 32] = 0u;
                continue;
            }
            const int i = n / 7, j = n % 7;
            const int sh = (wr * 7 + i + 3) % 56, sw = (wc * 7 + j + 3) % 56;
            const float* src = x + ((size_t)b * 3136 + sh * 56 + sw) * CD;
            float4 v = *(const float4*)(src + lane * 4);
            float sum = v.x + v.y + v.z + v.w;
            float sq  = v.x * v.x + v.y * v.y + v.z * v.z + v.w * v.w;
            #pragma unroll
            for (int o = 16; o; o >>= 1) {
                sum += __shfl_xor_sync(0xffffffffu, sum, o);
                sq  += __shfl_xor_sync(0xffffffffu, sq, o);
            }
            const float mu = sum * (1.f / 128.f);
            const float inv = rsqrtf(sq * (1.f / 128.f) - mu * mu + 1e-5f);
            uint2 o2;
            o2.x = pack_bf2((v.x - mu) * inv * gm.x + bt.x, (v.y - mu) * inv * gm.y + bt.y);
            o2.y = pack_bf2((v.z - mu) * inv * gm.z + bt.z, (v.w - mu) * inv * gm.w + bt.w);
            *(uint2*)(dst + lane * 4) = o2;
        }
    }
    __syncthreads();

    const uint32_t hA = smemA_base(hS, SH, lane);
    const uint32_t qA = smemA_base(qS, SH, lane);
    const uint32_t kB = smemB_base(kS, SH, lane);
    const uint32_t vB = smemB_base(vT, SV, lane);
    const uint2* wqp = g_wqkvF + warp * 6 * 8 * 32 + lane;
    const uint2* wop = g_woF   + warp * 2 * 8 * 32 + lane;

    const float invs = 0.17677669529663687f;
    #pragma unroll
    for (int pass = 0; pass < 2; pass++) {
        uint2 bfr[3][8];
        #pragma unroll
        for (int nt = 0; nt < 3; nt++)
            #pragma unroll
            for (int ks = 0; ks < 8; ks++)
                bfr[nt][ks] = wqp[((pass * 3 + nt) * 8 + ks) * 32];

        float acc[4][3][4];
        #pragma unroll
        for (int mt = 0; mt < 4; mt++)
            #pragma unroll
            for (int nt = 0; nt < 3; nt++)
                #pragma unroll
                for (int r = 0; r < 4; r++) acc[mt][nt][r] = 0.f;
        #pragma unroll
        for (int ks = 0; ks < 8; ks++) {
            #pragma unroll
            for (int mt = 0; mt < 4; mt++) {
                unsigned afr[4];
                ldsm4(afr, hA + (mt * 16 * SH + ks * 16) * 2);
                #pragma unroll
                for (int nt = 0; nt < 3; nt++) mma_bf16_u2(acc[mt][nt], afr, bfr[nt][ks]);
            }
        }
        #pragma unroll
        for (int mt = 0; mt < 4; mt++) {
            #pragma unroll
            for (int nt = 0; nt < 3; nt++) {
                const int nb = warp * 48 + (pass * 3 + nt) * 8;
                const int c0 = nb + 2 * s;
                const int r0 = mt * 16 + g;
                float v0 = acc[mt][nt][0], v1 = acc[mt][nt][1], v2 = acc[mt][nt][2], v3 = acc[mt][nt][3];
                if (nb < 128) {
                    float b0 = bq[c0], b1 = bq[c0 + 1];
                    *(unsigned*)(qS + r0 * SH + c0)       = pack_bf2((v0 + b0) * invs, (v1 + b1) * invs);
                    *(unsigned*)(qS + (r0 + 8) * SH + c0) = pack_bf2((v2 + b0) * invs, (v3 + b1) * invs);
                } else if (nb < 256) {
                    int cc = c0 - 128;
                    float b0 = bk[cc], b1 = bk[cc + 1];
                    *(unsigned*)(kS + r0 * SH + cc)       = pack_bf2(v0 + b0, v1 + b1);
                    *(unsigned*)(kS + (r0 + 8) * SH + cc) = pack_bf2(v2 + b0, v3 + b1);
                } else {
                    int d0 = c0 - 256;
                    float b0 = bv[d0], b1 = bv[d0 + 1];
                    vT[d0 * SV + r0]           = __float2bfloat16_rn(v0 + b0);
                    vT[(d0 + 1) * SV + r0]     = __float2bfloat16_rn(v1 + b1);
                    vT[d0 * SV + r0 + 8]       = __float2bfloat16_rn(v2 + b0);
                    vT[(d0 + 1) * SV + r0 + 8] = __float2bfloat16_rn(v3 + b1);
                }
            }
        }
    }
    __syncthreads();

    const int hw = warp >> 1, mh = warp & 1;
    float lac[2][8][4];
    #pragma unroll
    for (int mt = 0; mt < 2; mt++)
        #pragma unroll
        for (int nt = 0; nt < 8; nt++)
            #pragma unroll
            for (int r = 0; r < 4; r++) lac[mt][nt][r] = 0.f;

    {
        const uint32_t qBase = qA + (mh * 32 * SH + hw * 32) * 2;
        const uint32_t kBase = kB + (hw * 32) * 2;
        #pragma unroll
        for (int ks = 0; ks < 2; ks++) {
            unsigned bfr[8][2];
            #pragma unroll
            for (int nt = 0; nt < 8; nt++) ldsm2(bfr[nt], kBase + (nt * 8 * SH + ks * 16) * 2);
            #pragma unroll
            for (int mt = 0; mt < 2; mt++) {
                unsigned afr[4];
                ldsm4(afr, qBase + (mt * 16 * SH + ks * 16) * 2);
                #pragma unroll
                for (int nt = 0; nt < 8; nt++) mma_bf16(lac[mt][nt], afr, bfr[nt]);
            }
        }
    }

    const float4* bmp = g_bm4 + (((size_t)(w * HEADS + hw) * 4 + mh * 2) * 8) * 32 + lane;
    #pragma unroll
    for (int mt = 0; mt < 2; mt++) {
        float mA = -1e30f, mB = -1e30f;
        #pragma unroll
        for (int nt = 0; nt < 8; nt++) {
            float4 bv4 = bmp[(mt * 8 + nt) * 32];
            lac[mt][nt][0] += bv4.x;
            lac[mt][nt][1] += bv4.y;
            lac[mt][nt][2] += bv4.z;
            lac[mt][nt][3] += bv4.w;
            mA = fmaxf(mA, fmaxf(lac[mt][nt][0], lac[mt][nt][1]));
            mB = fmaxf(mB, fmaxf(lac[mt][nt][2], lac[mt][nt][3]));
        }
        mA = fmaxf(mA, __shfl_xor_sync(0xffffffffu, mA, 1));
        mA = fmaxf(mA, __shfl_xor_sync(0xffffffffu, mA, 2));
        mB = fmaxf(mB, __shfl_xor_sync(0xffffffffu, mB, 1));
        mB = fmaxf(mB, __shfl_xor_sync(0xffffffffu, mB, 2));
        float sA = 0.f, sB = 0.f;
        #pragma unroll
        for (int nt = 0; nt < 8; nt++) {
            lac[mt][nt][0] = __expf(lac[mt][nt][0] - mA);
            lac[mt][nt][1] = __expf(lac[mt][nt][1] - mA);
            lac[mt][nt][2] = __expf(lac[mt][nt][2] - mB);
            lac[mt][nt][3] = __expf(lac[mt][nt][3] - mB);
            sA += lac[mt][nt][0] + lac[mt][nt][1];
            sB += lac[mt][nt][2] + lac[mt][nt][3];
        }
        sA += __shfl_xor_sync(0xffffffffu, sA, 1);
        sA += __shfl_xor_sync(0xffffffffu, sA, 2);
        sB += __shfl_xor_sync(0xffffffffu, sB, 1);
        sB += __shfl_xor_sync(0xffffffffu, sB, 2);
        const float iA = 1.f / sA, iB = 1.f / sB;
        #pragma unroll
        for (int nt = 0; nt < 8; nt++) {
            lac[mt][nt][0] *= iA; lac[mt][nt][1] *= iA;
            lac[mt][nt][2] *= iB; lac[mt][nt][3] *= iB;
        }
    }

    float oac[2][4][4];
    #pragma unroll
    for (int mt = 0; mt < 2; mt++)
        #pragma unroll
        for (int nt = 0; nt < 4; nt++)
            #pragma unroll
            for (int r = 0; r < 4; r++) oac[mt][nt][r] = 0.f;

    {
        const uint32_t vBase = vB + (hw * 32 * SV) * 2;
        #pragma unroll
        for (int kt = 0; kt < 4; kt++) {
            unsigned bfr[4][2];
            #pragma unroll
            for (int nt = 0; nt < 4; nt++) ldsm2(bfr[nt], vBase + (nt * 8 * SV + kt * 16) * 2);
            #pragma unroll
            for (int mt = 0; mt < 2; mt++) {
                unsigned pa[4];
                pa[0] = pack_bf2(lac[mt][2 * kt][0],     lac[mt][2 * kt][1]);
                pa[1] = pack_bf2(lac[mt][2 * kt][2],     lac[mt][2 * kt][3]);
                pa[2] = pack_bf2(lac[mt][2 * kt + 1][0], lac[mt][2 * kt + 1][1]);
                pa[3] = pack_bf2(lac[mt][2 * kt + 1][2], lac[mt][2 * kt + 1][3]);
                #pragma unroll
                for (int nt = 0; nt < 4; nt++) mma_bf16(oac[mt][nt], pa, bfr[nt]);
            }
        }
    }

    uint2 bfo[2][8];
    #pragma unroll
    for (int nt = 0; nt < 2; nt++)
        #pragma unroll
        for (int ks = 0; ks < 8; ks++)
            bfo[nt][ks] = wop[(nt * 8 + ks) * 32];

    #pragma unroll
    for (int mt = 0; mt < 2; mt++) {
        #pragma unroll
        for (int nt = 0; nt < 4; nt++) {
            const int r0 = mh * 32 + mt * 16 + g;
            const int c0 = hw * 32 + nt * 8 + 2 * s;
            *(unsigned*)(oS + r0 * SH + c0)       = pack_bf2(oac[mt][nt][0], oac[mt][nt][1]);
            *(unsigned*)(oS + (r0 + 8) * SH + c0) = pack_bf2(oac[mt][nt][2], oac[mt][nt][3]);
        }
    }
    __syncthreads();

    float fac[4][2][4];
    #pragma unroll
    for (int mt = 0; mt < 4; mt++)
        #pragma unroll
        for (int nt = 0; nt < 2; nt++)
            #pragma unroll
            for (int r = 0; r < 4; r++) fac[mt][nt][r] = 0.f;

    #pragma unroll
    for (int ks = 0; ks < 8; ks++) {
        #pragma unroll
        for (int mt = 0; mt < 4; mt++) {
            unsigned afr[4];
            ldsm4(afr, hA + (mt * 16 * SH + ks * 16) * 2);
            #pragma unroll
            for (int nt = 0; nt < 2; nt++) mma_bf16_u2(fac[mt][nt], afr, bfo[nt][ks]);
        }
    }

    #pragma unroll
    for (int mt = 0; mt < 4; mt++) {
        #pragma unroll
        for (int nt = 0; nt < 2; nt++) {
            const int c = warp * 16 + nt * 8 + 2 * s;
            const float bo0 = bo[c], bo1 = bo[c + 1];
            const int r0 = mt * 16 + g, r1 = r0 + 8;
            if (r0 < 49) {
                size_t p = ((size_t)b * 3136 + w * 49 + r0) * CD + c;
                float2 xr = *(const float2*)(x + p);
                float2 o;
                o.x = fac[mt][nt][0] + bo0 + xr.x;
                o.y = fac[mt][nt][1] + bo1 + xr.y;
                *(float2*)(g_y + p) = o;
            }
            if (r1 < 49) {
                size_t p = ((size_t)b * 3136 + w * 49 + r1) * CD + c;
                float2 xr = *(const float2*)(x + p);
                float2 o;
                o.x = fac[mt][nt][2] + bo0 + xr.x;
                o.y = fac[mt][nt][3] + bo1 + xr.y;
                *(float2*)(g_y + p) = o;
            }
        }
    }
}

// ---------------- K2: fused LN2 + MLP + residual (3 CTAs/SM, 256-wide hidden chunks) ----------------
__global__ void __launch_bounds__(256, 3) mlp_kernel(const float* __restrict__ g2,
                                                     const float* __restrict__ be2,
                                                     const float* __restrict__ b1,
                                                     const float* __restrict__ b2,
                                                     float* __restrict__ out) {
    extern __shared__ char smraw[];
    __nv_bfloat16* mS = (__nv_bfloat16*)smraw;                   // 64 x SH   (17408 B)
    __nv_bfloat16* hS = (__nv_bfloat16*)(smraw + 17408);         // 64 x HS2  (33792 B)

    const int t0 = blockIdx.x * 64;
    const int warp = threadIdx.x >> 5, lane = threadIdx.x & 31;
    const int wm = warp >> 2, wn = warp & 3;          // 2x4 warp grid

    // ---- LN2 into mS
    {
        const float4 gm = *(const float4*)(g2 + lane * 4);
        const float4 bt = *(const float4*)(be2 + lane * 4);
        for (int r = warp; r < 64; r += 8) {
            const float* src = g_y + ((size_t)(t0 + r)) * CD;
            float4 v = *(const float4*)(src + lane * 4);
            float sum = v.x + v.y + v.z + v.w;
            float sq  = v.x * v.x + v.y * v.y + v.z * v.z + v.w * v.w;
            #pragma unroll
            for (int o = 16; o; o >>= 1) {
                sum += __shfl_xor_sync(0xffffffffu, sum, o);
                sq  += __shfl_xor_sync(0xffffffffu, sq, o);
            }
            const float mu = sum * (1.f / 128.f);
            const float inv = rsqrtf(sq * (1.f / 128.f) - mu * mu + 1e-5f);
            uint2 o2;
            o2.x = pack_bf2((v.x - mu) * inv * gm.x + bt.x, (v.y - mu) * inv * gm.y + bt.y);
            o2.y = pack_bf2((v.z - mu) * inv * gm.z + bt.z, (v.w - mu) * inv * gm.w + bt.w);
            *(uint2*)(mS + r * SH + lane * 4) = o2;
        }
    }
    __syncthreads();

    const int g = lane >> 2, s = lane & 3;
    const uint32_t mA = smemA_base(mS, SH,  lane) + (wm * 32 * SH)  * 2;
    const uint32_t hA = smemA_base(hS, HS2, lane) + (wm * 32 * HS2) * 2;
    const uint2* w1p = g_w1F + lane;
    const uint2* w2p = g_w2F + lane;

    float fac[2][4][4];
    #pragma unroll
    for (int mt = 0; mt < 2; mt++)
        #pragma unroll
        for (int nt = 0; nt < 4; nt++)
            #pragma unroll
            for (int r = 0; r < 4; r++) fac[mt][nt][r] = 0.f;

    #pragma unroll
    for (int sup = 0; sup < 2; sup++) {
        // ---- GEMM1 for this 256-wide hidden super-chunk: 2 sub-chunks per warp
        #pragma unroll
        for (int sc = 0; sc < 2; sc++) {
            const int ntb = sup * 32 + sc * 16 + wn * 4;      // global ntile (of 64)
            float acc[2][4][4];
            #pragma unroll
            for (int mt = 0; mt < 2; mt++)
                #pragma unroll
                for (int nt = 0; nt < 4; nt++)
                    #pragma unroll
                    for (int r = 0; r < 4; r++) acc[mt][nt][r] = 0.f;

            uint2 bf[2][4];
            #pragma unroll
            for (int nt = 0; nt < 4; nt++) bf[0][nt] = w1p[((ntb + nt) * 8 + 0) * 32];
            #pragma unroll
            for (int ks = 0; ks < 8; ks++) {
                if (ks < 7) {
                    #pragma unroll
                    for (int nt = 0; nt < 4; nt++)
                        bf[(ks + 1) & 1][nt] = w1p[((ntb + nt) * 8 + ks + 1) * 32];
                }
                #pragma unroll
                for (int mt = 0; mt < 2; mt++) {
                    unsigned afr[4];
                    ldsm4(afr, mA + (mt * 16 * SH + ks * 16) * 2);
                    #pragma unroll
                    for (int nt = 0; nt < 4; nt++) mma_bf16_u2(acc[mt][nt], afr, bf[ks & 1][nt]);
                }
            }

            // bias + fast GELU -> hS (local col within 256-wide chunk)
            #pragma unroll
            for (int mt = 0; mt < 2; mt++) {
                #pragma unroll
                for (int nt = 0; nt < 4; nt++) {
                    const int cg = (ntb + nt) * 8 + 2 * s;          // global hidden col
                    const int cl = cg - sup * 256;                  // local col 0..255
                    const float bb0 = b1[cg], bb1 = b1[cg + 1];
                    const int r0 = wm * 32 + mt * 16 + g;
                    *(unsigned*)(hS + r0 * HS2 + cl) =
                        pack_bf2(gelu_fast(acc[mt][nt][0] + bb0), gelu_fast(acc[mt][nt][1] + bb1));
                    *(unsigned*)(hS + (r0 + 8) * HS2 + cl) =
                        pack_bf2(gelu_fast(acc[mt][nt][2] + bb0), gelu_fast(acc[mt][nt][3] + bb1));
                }
            }
        }
        __syncthreads();

        // ---- GEMM2 partial over this K=256 chunk
        #pragma unroll
        for (int kb = 0; kb < 2; kb++) {
            uint2 cf[2][4];
            #pragma unroll
            for (int nt = 0; nt < 4; nt++)
                cf[0][nt] = w2p[(wn * 4 + nt) * 1024 + (sup * 16 + kb * 8 + 0) * 32];
            #pragma unroll
            for (int ks = 0; ks < 8; ks++) {
                if (ks < 7) {
                    #pragma unroll
                    for (int nt = 0; nt < 4; nt++)
                        cf[(ks + 1) & 1][nt] = w2p[(wn * 4 + nt) * 1024 + (sup * 16 + kb * 8 + ks + 1) * 32];
                }
                const int kl = kb * 8 + ks;      // local ktile 0..15
                #pragma unroll
                for (int mt = 0; mt < 2; mt++) {
                    unsigned afr[4];
                    ldsm4(afr, hA + (mt * 16 * HS2 + kl * 16) * 2);
                    #pragma unroll
                    for (int nt = 0; nt < 4; nt++) mma_bf16_u2(fac[mt][nt], afr, cf[ks & 1][nt]);
                }
            }
        }
        if (sup == 0) __syncthreads();    // hS reused by next super-chunk
    }

    // epilogue: + b2 + residual g_y -> out
    #pragma unroll
    for (int mt = 0; mt < 2; mt++) {
        #pragma unroll
        for (int nt = 0; nt < 4; nt++) {
            const int c = wn * 32 + nt * 8 + 2 * s;
            const float bb0 = b2[c], bb1 = b2[c + 1];
            const int r0 = wm * 32 + mt * 16 + g;
            size_t p0 = ((size_t)(t0 + r0)) * CD + c;
            size_t p1 = ((size_t)(t0 + r0 + 8)) * CD + c;
            float2 y0 = *(const float2*)(g_y + p0);
            float2 y1 = *(const float2*)(g_y + p1);
            float2 o0, o1;
            o0.x = fac[mt][nt][0] + bb0 + y0.x;
            o0.y = fac[mt][nt][1] + bb1 + y0.y;
            o1.x = fac[mt][nt][2] + bb0 + y1.x;
            o1.y = fac[mt][nt][3] + bb1 + y1.y;
            *(float2*)(out + p0) = o0;
            *(float2*)(out + p1) = o1;
        }
    }
}

// ---------------- launch ----------------
extern "C" void kernel_launch(void* const* d_in, const int* in_sizes, int n_in,
                              void* d_out, int out_size) {
    const float* x   = (const float*)d_in[0];
    const float* wq  = (const float*)d_in[1];
    const float* bq  = (const float*)d_in[2];
    const float* wk  = (const float*)d_in[3];
    const float* bk  = (const float*)d_in[4];
    const float* wv  = (const float*)d_in[5];
    const float* bv  = (const float*)d_in[6];
    const float* wo  = (const float*)d_in[7];
    const float* bo  = (const float*)d_in[8];
    const float* rel = (const float*)d_in[9];
    const float* g1  = (const float*)d_in[10];
    const float* be1 = (const float*)d_in[11];
    const float* g2  = (const float*)d_in[12];
    const float* be2 = (const float*)d_in[13];
    const float* w1  = (const float*)d_in[14];
    const float* b1  = (const float*)d_in[15];
    const float* w2  = (const float*)d_in[16];
    const float* b2  = (const float*)d_in[17];
    float* out = (float*)d_out;

    cudaFuncSetAttribute(attn_kernel, cudaFuncAttributeMaxDynamicSharedMemorySize, 70656);
    cudaFuncSetAttribute(mlp_kernel,  cudaFuncAttributeMaxDynamicSharedMemorySize, 51200);

    pack_weights<<<192, 256>>>(wq, wk, wv, wo, w1, w2);
    build_bm<<<1024, 256>>>(rel);
    attn_kernel<<<4096, 256, 70656>>>(x, g1, be1, bq, bk, bv, bo);
    mlp_kernel<<<3136, 256, 51200>>>(g2, be2, b1, b2, out);
}

// round 11
// speedup vs baseline: 1.1980x; 1.1980x over previous
#include <cuda_runtime.h>
#include <cuda_bf16.h>
#include <math.h>
#include <stdint.h>

#define HEADS 4
#define CD    128
#define TOK   200704          // B * 3136
#define SH    136             // smem stride (bf16) for 128-wide tiles
#define SH2   520             // smem stride (bf16) for 512-wide hidden
#define SV    72              // smem stride (bf16) for vT (64-wide)

// ---------------- scratch ----------------
__device__ float  g_y[(size_t)TOK * CD];          // x + attn_out
__device__ uint2  g_wqkvF[48 * 8 * 32];
__device__ uint2  g_woF  [16 * 8 * 32];
__device__ uint2  g_w1F  [64 * 8 * 32];
__device__ uint2  g_w2F  [16 * 32 * 32];
__device__ float4 g_bm4[64 * HEADS * 4 * 8 * 32];

// ---------------- helpers ----------------
__device__ __forceinline__ void mma_bf16(float d[4], const unsigned a[4], const unsigned b[2]) {
    asm volatile("mma.sync.aligned.m16n8k16.row.col.f32.bf16.bf16.f32 "
                 "{%0,%1,%2,%3}, {%4,%5,%6,%7}, {%8,%9}, {%0,%1,%2,%3};\n"
                 : "+f"(d[0]), "+f"(d[1]), "+f"(d[2]), "+f"(d[3])
                 : "r"(a[0]), "r"(a[1]), "r"(a[2]), "r"(a[3]), "r"(b[0]), "r"(b[1]));
}
__device__ __forceinline__ void mma_bf16_u2(float d[4], const unsigned a[4], uint2 b) {
    asm volatile("mma.sync.aligned.m16n8k16.row.col.f32.bf16.bf16.f32 "
                 "{%0,%1,%2,%3}, {%4,%5,%6,%7}, {%8,%9}, {%0,%1,%2,%3};\n"
                 : "+f"(d[0]), "+f"(d[1]), "+f"(d[2]), "+f"(d[3])
                 : "r"(a[0]), "r"(a[1]), "r"(a[2]), "r"(a[3]), "r"(b.x), "r"(b.y));
}
__device__ __forceinline__ void ldsm4(unsigned a[4], uint32_t addr) {
    asm volatile("ldmatrix.sync.aligned.m8n8.x4.shared.b16 {%0,%1,%2,%3}, [%4];"
                 : "=r"(a[0]), "=r"(a[1]), "=r"(a[2]), "=r"(a[3]) : "r"(addr));
}
__device__ __forceinline__ void ldsm2(unsigned b[2], uint32_t addr) {
    asm volatile("ldmatrix.sync.aligned.m8n8.x2.shared.b16 {%0,%1}, [%2];"
                 : "=r"(b[0]), "=r"(b[1]) : "r"(addr));
}
__device__ __forceinline__ uint32_t smemA_base(const void* p, int stride, int lane) {
    return (uint32_t)__cvta_generic_to_shared(p) +
           (uint32_t)(((lane & 15) * stride + ((lane >> 4) << 3)) * 2);
}
__device__ __forceinline__ uint32_t smemB_base(const void* p, int stride, int lane) {
    return (uint32_t)__cvta_generic_to_shared(p) +
           (uint32_t)(((lane & 7) * stride + (lane & 8)) * 2);
}
__device__ __forceinline__ unsigned pack_bf2(float lo, float hi) {
    unsigned r;
    asm("cvt.rn.bf16x2.f32 %0, %1, %2;" : "=r"(r) : "f"(hi), "f"(lo));
    return r;
}
__device__ __forceinline__ float gelu_fast(float v) {
    float u2 = v * v;
    float u = v * (1.5957691216f + 0.1426926424f * u2);
    float e = __expf(u);
    return __fdividef(v * e, e + 1.f);
}
__device__ __forceinline__ int region_of(int p) { return p < 49 ? 0 : (p < 53 ? 1 : 2); }

// ---------------- K0a: pack weights into fragment layout ----------------
__global__ void pack_weights(const float* __restrict__ wq, const float* __restrict__ wk,
                             const float* __restrict__ wv, const float* __restrict__ wo,
                             const float* __restrict__ w1, const float* __restrict__ w2) {
    int i = blockIdx.x * blockDim.x + threadIdx.x;   // 49152 threads
    if (i < 12288) {
        int lane = i & 31, kt = (i >> 5) & 7, nt = i >> 8;
        int n = nt * 8 + (lane >> 2), kk = kt * 16 + 2 * (lane & 3);
        const float* wsrc = (n < 128) ? wq : (n < 256) ? wk : wv;
        int nn = n & 127;
        uint2 v;
        v.x = pack_bf2(wsrc[kk * 128 + nn],       wsrc[(kk + 1) * 128 + nn]);
        v.y = pack_bf2(wsrc[(kk + 8) * 128 + nn], wsrc[(kk + 9) * 128 + nn]);
        g_wqkvF[i] = v;
    } else if (i < 16384) {
        int j = i - 12288;
        int lane = j & 31, kt = (j >> 5) & 7, nt = j >> 8;
        int n = nt * 8 + (lane >> 2), kk = kt * 16 + 2 * (lane & 3);
        uint2 v;
        v.x = pack_bf2(wo[kk * 128 + n],       wo[(kk + 1) * 128 + n]);
        v.y = pack_bf2(wo[(kk + 8) * 128 + n], wo[(kk + 9) * 128 + n]);
        g_woF[j] = v;
    } else if (i < 32768) {
        int j = i - 16384;
        int lane = j & 31, kt = (j >> 5) & 7, nt = j >> 8;
        int n = nt * 8 + (lane >> 2), kk = kt * 16 + 2 * (lane & 3);
        uint2 v;
        v.x = pack_bf2(w1[kk * 512 + n],       w1[(kk + 1) * 512 + n]);
        v.y = pack_bf2(w1[(kk + 8) * 512 + n], w1[(kk + 9) * 512 + n]);
        g_w1F[j] = v;
    } else {
        int j = i - 32768;
        int lane = j & 31, kt = (j >> 5) & 31, nt = j >> 10;
        int n = nt * 8 + (lane >> 2), kk = kt * 16 + 2 * (lane & 3);
        uint2 v;
        v.x = pack_bf2(w2[kk * 128 + n],       w2[(kk + 1) * 128 + n]);
        v.y = pack_bf2(w2[(kk + 8) * 128 + n], w2[(kk + 9) * 128 + n]);
        g_w2F[j] = v;
    }
}

// ---------------- K0b: bias+mask table ----------------
__device__ __forceinline__ float bm_val(const float* __restrict__ rel, int w, int h, int q, int k) {
    if (q >= 49 || k >= 49) return -1e30f;
    int qi = q / 7, qj = q % 7, ki = k / 7, kj = k % 7;
    int r0 = (ki - qi) % 13; if (r0 < 0) r0 += 13;
    int r1 = (kj - qj) % 13; if (r1 < 0) r1 += 13;
    float bias = rel[(r0 * 13 + r1) * HEADS + h];
    int wr = w >> 3, wc = w & 7;
    int idq = region_of(wr * 7 + qi) * 3 + region_of(wc * 7 + qj);
    int idk = region_of(wr * 7 + ki) * 3 + region_of(wc * 7 + kj);
    return bias + (idq == idk ? 0.f : -100.f);
}
__global__ void build_bm(const float* __restrict__ rel) {
    int i = blockIdx.x * blockDim.x + threadIdx.x;   // 262144
    int lane = i & 31, nt = (i >> 5) & 7, mtile = (i >> 8) & 3, h = (i >> 10) & 3, w = i >> 12;
    int g = lane >> 2, s = lane & 3;
    int rA = mtile * 16 + g, rB = rA + 8, cc = nt * 8 + 2 * s;
    float4 v;
    v.x = bm_val(rel, w, h, rA, cc);
    v.y = bm_val(rel, w, h, rA, cc + 1);
    v.z = bm_val(rel, w, h, rB, cc);
    v.w = bm_val(rel, w, h, rB, cc + 1);
    g_bm4[i] = v;
}

// ---------------- K1: fused LN1 + window attention + O-proj + residual ----------------
__global__ void __launch_bounds__(256, 2) attn_kernel(const float* __restrict__ x,
                                                      const float* __restrict__ gam,
                                                      const float* __restrict__ bet,
                                                      const float* __restrict__ bq,
                                                      const float* __restrict__ bk,
                                                      const float* __restrict__ bv,
                                                      const float* __restrict__ bo) {
    extern __shared__ char smraw[];
    __nv_bfloat16* hS = (__nv_bfloat16*)smraw;
    __nv_bfloat16* qS = (__nv_bfloat16*)(smraw + 17408);
    __nv_bfloat16* kS = (__nv_bfloat16*)(smraw + 34816);
    __nv_bfloat16* vT = (__nv_bfloat16*)(smraw + 52224);
    __nv_bfloat16* oS = hS;

    const int win = blockIdx.x, b = win >> 6, w = win & 63;
    const int wr = w >> 3, wc = w & 7;
    const int warp = threadIdx.x >> 5, lane = threadIdx.x & 31;
    const int g = lane >> 2, s = lane & 3;

    const uint2* wqp = g_wqkvF + warp * 6 * 8 * 32 + lane;
    const uint2* wop = g_woF   + warp * 2 * 8 * 32 + lane;

    // prefetch QKV pass-0 weights (overlaps with LN gather below)
    uint2 bfr[3][8];
    #pragma unroll
    for (int nt = 0; nt < 3; nt++)
        #pragma unroll
        for (int ks = 0; ks < 8; ks++)
            bfr[nt][ks] = wqp[(nt * 8 + ks) * 32];

    // ---- LN1 + roll(+3) gather into smem, with batched gather preload
    {
        const float4 gm = *(const float4*)(gam + lane * 4);
        const float4 bt = *(const float4*)(bet + lane * 4);
        float4 vv[8];
        #pragma unroll
        for (int it = 0; it < 8; it++) {
            const int n = warp + it * 8;
            if (n < 49) {
                const int i = n / 7, j = n % 7;
                const int sh = (wr * 7 + i + 3) % 56, sw = (wc * 7 + j + 3) % 56;
                vv[it] = *(const float4*)(x + ((size_t)b * 3136 + sh * 56 + sw) * CD + lane * 4);
            }
        }
        #pragma unroll
        for (int it = 0; it < 8; it++) {
            const int n = warp + it * 8;
            __nv_bfloat16* dst = hS + n * SH;
            if (n >= 49) {
                ((unsigned*)dst)[lane]      = 0u;
                ((unsigned*)dst)[lane + 32] = 0u;
                continue;
            }
            float4 v = vv[it];
            float sum = v.x + v.y + v.z + v.w;
            float sq  = v.x * v.x + v.y * v.y + v.z * v.z + v.w * v.w;
            #pragma unroll
            for (int o = 16; o; o >>= 1) {
                sum += __shfl_xor_sync(0xffffffffu, sum, o);
                sq  += __shfl_xor_sync(0xffffffffu, sq, o);
            }
            const float mu = sum * (1.f / 128.f);
            const float inv = rsqrtf(sq * (1.f / 128.f) - mu * mu + 1e-5f);
            uint2 o2;
            o2.x = pack_bf2((v.x - mu) * inv * gm.x + bt.x, (v.y - mu) * inv * gm.y + bt.y);
            o2.y = pack_bf2((v.z - mu) * inv * gm.z + bt.z, (v.w - mu) * inv * gm.w + bt.w);
            *(uint2*)(dst + lane * 4) = o2;
        }
    }
    __syncthreads();

    const uint32_t hA = smemA_base(hS, SH, lane);
    const uint32_t qA = smemA_base(qS, SH, lane);
    const uint32_t kB = smemB_base(kS, SH, lane);
    const uint32_t vB = smemB_base(vT, SV, lane);

    // ---- QKV gemm: M=64 N=384 K=128; 2 passes of 24 cols per warp
    const float invs = 0.17677669529663687f;  // 1/sqrt(32)
    #pragma unroll
    for (int pass = 0; pass < 2; pass++) {
        float acc[4][3][4];
        #pragma unroll
        for (int mt = 0; mt < 4; mt++)
            #pragma unroll
            for (int nt = 0; nt < 3; nt++)
                #pragma unroll
                for (int r = 0; r < 4; r++) acc[mt][nt][r] = 0.f;
        #pragma unroll
        for (int ks = 0; ks < 8; ks++) {
            #pragma unroll
            for (int mt = 0; mt < 4; mt++) {
                unsigned afr[4];
                ldsm4(afr, hA + (mt * 16 * SH + ks * 16) * 2);
                #pragma unroll
                for (int nt = 0; nt < 3; nt++) mma_bf16_u2(acc[mt][nt], afr, bfr[nt][ks]);
            }
        }
        // reload weights for pass 1 (overlaps with epilogue below)
        if (pass == 0) {
            #pragma unroll
            for (int nt = 0; nt < 3; nt++)
                #pragma unroll
                for (int ks = 0; ks < 8; ks++)
                    bfr[nt][ks] = wqp[((3 + nt) * 8 + ks) * 32];
        }
        #pragma unroll
        for (int mt = 0; mt < 4; mt++) {
            #pragma unroll
            for (int nt = 0; nt < 3; nt++) {
                const int nb = warp * 48 + (pass * 3 + nt) * 8;
                const int c0 = nb + 2 * s;
                const int r0 = mt * 16 + g;
                float v0 = acc[mt][nt][0], v1 = acc[mt][nt][1], v2 = acc[mt][nt][2], v3 = acc[mt][nt][3];
                if (nb < 128) {
                    float b0 = bq[c0], b1 = bq[c0 + 1];
                    *(unsigned*)(qS + r0 * SH + c0)       = pack_bf2((v0 + b0) * invs, (v1 + b1) * invs);
                    *(unsigned*)(qS + (r0 + 8) * SH + c0) = pack_bf2((v2 + b0) * invs, (v3 + b1) * invs);
                } else if (nb < 256) {
                    int cc = c0 - 128;
                    float b0 = bk[cc], b1 = bk[cc + 1];
                    *(unsigned*)(kS + r0 * SH + cc)       = pack_bf2(v0 + b0, v1 + b1);
                    *(unsigned*)(kS + (r0 + 8) * SH + cc) = pack_bf2(v2 + b0, v3 + b1);
                } else {
                    int d0 = c0 - 256;
                    float b0 = bv[d0], b1 = bv[d0 + 1];
                    vT[d0 * SV + r0]           = __float2bfloat16_rn(v0 + b0);
                    vT[(d0 + 1) * SV + r0]     = __float2bfloat16_rn(v1 + b1);
                    vT[d0 * SV + r0 + 8]       = __float2bfloat16_rn(v2 + b0);
                    vT[(d0 + 1) * SV + r0 + 8] = __float2bfloat16_rn(v3 + b1);
                }
            }
        }
    }
    __syncthreads();

    // ---- logits: warp -> head hw, row-half mh
    const int hw = warp >> 1, mh = warp & 1;
    float lac[2][8][4];
    #pragma unroll
    for (int mt = 0; mt < 2; mt++)
        #pragma unroll
        for (int nt = 0; nt < 8; nt++)
            #pragma unroll
            for (int r = 0; r < 4; r++) lac[mt][nt][r] = 0.f;

    {
        const uint32_t qBase = qA + (mh * 32 * SH + hw * 32) * 2;
        const uint32_t kBase = kB + (hw * 32) * 2;
        #pragma unroll
        for (int ks = 0; ks < 2; ks++) {
            unsigned bfk[8][2];
            #pragma unroll
            for (int nt = 0; nt < 8; nt++) ldsm2(bfk[nt], kBase + (nt * 8 * SH + ks * 16) * 2);
            #pragma unroll
            for (int mt = 0; mt < 2; mt++) {
                unsigned afr[4];
                ldsm4(afr, qBase + (mt * 16 * SH + ks * 16) * 2);
                #pragma unroll
                for (int nt = 0; nt < 8; nt++) mma_bf16(lac[mt][nt], afr, bfk[nt]);
            }
        }
    }

    // bias + mask + softmax
    const float4* bmp = g_bm4 + (((size_t)(w * HEADS + hw) * 4 + mh * 2) * 8) * 32 + lane;
    #pragma unroll
    for (int mt = 0; mt < 2; mt++) {
        float mA = -1e30f, mB = -1e30f;
        #pragma unroll
        for (int nt = 0; nt < 8; nt++) {
            float4 bv4 = bmp[(mt * 8 + nt) * 32];
            lac[mt][nt][0] += bv4.x;
            lac[mt][nt][1] += bv4.y;
            lac[mt][nt][2] += bv4.z;
            lac[mt][nt][3] += bv4.w;
            mA = fmaxf(mA, fmaxf(lac[mt][nt][0], lac[mt][nt][1]));
            mB = fmaxf(mB, fmaxf(lac[mt][nt][2], lac[mt][nt][3]));
        }
        mA = fmaxf(mA, __shfl_xor_sync(0xffffffffu, mA, 1));
        mA = fmaxf(mA, __shfl_xor_sync(0xffffffffu, mA, 2));
        mB = fmaxf(mB, __shfl_xor_sync(0xffffffffu, mB, 1));
        mB = fmaxf(mB, __shfl_xor_sync(0xffffffffu, mB, 2));
        float sA = 0.f, sB = 0.f;
        #pragma unroll
        for (int nt = 0; nt < 8; nt++) {
            lac[mt][nt][0] = __expf(lac[mt][nt][0] - mA);
            lac[mt][nt][1] = __expf(lac[mt][nt][1] - mA);
            lac[mt][nt][2] = __expf(lac[mt][nt][2] - mB);
            lac[mt][nt][3] = __expf(lac[mt][nt][3] - mB);
            sA += lac[mt][nt][0] + lac[mt][nt][1];
            sB += lac[mt][nt][2] + lac[mt][nt][3];
        }
        sA += __shfl_xor_sync(0xffffffffu, sA, 1);
        sA += __shfl_xor_sync(0xffffffffu, sA, 2);
        sB += __shfl_xor_sync(0xffffffffu, sB, 1);
        sB += __shfl_xor_sync(0xffffffffu, sB, 2);
        const float iA = 1.f / sA, iB = 1.f / sB;
        #pragma unroll
        for (int nt = 0; nt < 8; nt++) {
            lac[mt][nt][0] *= iA; lac[mt][nt][1] *= iA;
            lac[mt][nt][2] *= iB; lac[mt][nt][3] *= iB;
        }
    }

    // ---- attn @ V (P stays in registers)
    float oac[2][4][4];
    #pragma unroll
    for (int mt = 0; mt < 2; mt++)
        #pragma unroll
        for (int nt = 0; nt < 4; nt++)
            #pragma unroll
            for (int r = 0; r < 4; r++) oac[mt][nt][r] = 0.f;

    {
        const uint32_t vBase = vB + (hw * 32 * SV) * 2;
        #pragma unroll
        for (int kt = 0; kt < 4; kt++) {
            unsigned bfv[4][2];
            #pragma unroll
            for (int nt = 0; nt < 4; nt++) ldsm2(bfv[nt], vBase + (nt * 8 * SV + kt * 16) * 2);
            #pragma unroll
            for (int mt = 0; mt < 2; mt++) {
                unsigned pa[4];
                pa[0] = pack_bf2(lac[mt][2 * kt][0],     lac[mt][2 * kt][1]);
                pa[1] = pack_bf2(lac[mt][2 * kt][2],     lac[mt][2 * kt][3]);
                pa[2] = pack_bf2(lac[mt][2 * kt + 1][0], lac[mt][2 * kt + 1][1]);
                pa[3] = pack_bf2(lac[mt][2 * kt + 1][2], lac[mt][2 * kt + 1][3]);
                #pragma unroll
                for (int nt = 0; nt < 4; nt++) mma_bf16(oac[mt][nt], pa, bfv[nt]);
            }
        }
    }

    // ---- prefetch O-proj weights while storing P@V tile
    uint2 bfo[2][8];
    #pragma unroll
    for (int nt = 0; nt < 2; nt++)
        #pragma unroll
        for (int ks = 0; ks < 8; ks++)
            bfo[nt][ks] = wop[(nt * 8 + ks) * 32];

    #pragma unroll
    for (int mt = 0; mt < 2; mt++) {
        #pragma unroll
        for (int nt = 0; nt < 4; nt++) {
            const int r0 = mh * 32 + mt * 16 + g;
            const int c0 = hw * 32 + nt * 8 + 2 * s;
            *(unsigned*)(oS + r0 * SH + c0)       = pack_bf2(oac[mt][nt][0], oac[mt][nt][1]);
            *(unsigned*)(oS + (r0 + 8) * SH + c0) = pack_bf2(oac[mt][nt][2], oac[mt][nt][3]);
        }
    }
    __syncthreads();

    // ---- O projection: M=64 N=128 K=128
    float fac[4][2][4];
    #pragma unroll
    for (int mt = 0; mt < 4; mt++)
        #pragma unroll
        for (int nt = 0; nt < 2; nt++)
            #pragma unroll
            for (int r = 0; r < 4; r++) fac[mt][nt][r] = 0.f;

    #pragma unroll
    for (int ks = 0; ks < 8; ks++) {
        #pragma unroll
        for (int mt = 0; mt < 4; mt++) {
            unsigned afr[4];
            ldsm4(afr, hA + (mt * 16 * SH + ks * 16) * 2);
            #pragma unroll
            for (int nt = 0; nt < 2; nt++) mma_bf16_u2(fac[mt][nt], afr, bfo[nt][ks]);
        }
    }

    // epilogue: + bo + residual x -> g_y (window-order tokens)
    #pragma unroll
    for (int mt = 0; mt < 4; mt++) {
        #pragma unroll
        for (int nt = 0; nt < 2; nt++) {
            const int c = warp * 16 + nt * 8 + 2 * s;
            const float bo0 = bo[c], bo1 = bo[c + 1];
            const int r0 = mt * 16 + g, r1 = r0 + 8;
            if (r0 < 49) {
                size_t p = ((size_t)b * 3136 + w * 49 + r0) * CD + c;
                float2 xr = *(const float2*)(x + p);
                float2 o;
                o.x = fac[mt][nt][0] + bo0 + xr.x;
                o.y = fac[mt][nt][1] + bo1 + xr.y;
                *(float2*)(g_y + p) = o;
            }
            if (r1 < 49) {
                size_t p = ((size_t)b * 3136 + w * 49 + r1) * CD + c;
                float2 xr = *(const float2*)(x + p);
                float2 o;
                o.x = fac[mt][nt][2] + bo0 + xr.x;
                o.y = fac[mt][nt][3] + bo1 + xr.y;
                *(float2*)(g_y + p) = o;
            }
        }
    }
}

// ---------------- K2: fused LN2 + MLP + residual (R8 single-barrier schedule) ----------------
__global__ void __launch_bounds__(256, 2) mlp_kernel(const float* __restrict__ g2,
                                                     const float* __restrict__ be2,
                                                     const float* __restrict__ b1,
                                                     const float* __restrict__ b2,
                                                     float* __restrict__ out) {
    extern __shared__ char smraw[];
    __nv_bfloat16* mS = (__nv_bfloat16*)smraw;                   // 64 x SH   (17408 B)
    __nv_bfloat16* hS = (__nv_bfloat16*)(smraw + 17408);         // 64 x SH2  (66560 B)

    const int t0 = blockIdx.x * 64;
    const int warp = threadIdx.x >> 5, lane = threadIdx.x & 31;
    const int wm = warp >> 2, wn = warp & 3;          // 2x4 warp grid

    // ---- LN2 into mS, batched gather preload
    {
        const float4 gm = *(const float4*)(g2 + lane * 4);
        const float4 bt = *(const float4*)(be2 + lane * 4);
        float4 vv[8];
        #pragma unroll
        for (int it = 0; it < 8; it++) {
            const int r = warp + it * 8;
            vv[it] = *(const float4*)(g_y + ((size_t)(t0 + r)) * CD + lane * 4);
        }
        #pragma unroll
        for (int it = 0; it < 8; it++) {
            const int r = warp + it * 8;
            float4 v = vv[it];
            float sum = v.x + v.y + v.z + v.w;
            float sq  = v.x * v.x + v.y * v.y + v.z * v.z + v.w * v.w;
            #pragma unroll
            for (int o = 16; o; o >>= 1) {
                sum += __shfl_xor_sync(0xffffffffu, sum, o);
                sq  += __shfl_xor_sync(0xffffffffu, sq, o);
            }
            const float mu = sum * (1.f / 128.f);
            const float inv = rsqrtf(sq * (1.f / 128.f) - mu * mu + 1e-5f);
            uint2 o2;
            o2.x = pack_bf2((v.x - mu) * inv * gm.x + bt.x, (v.y - mu) * inv * gm.y + bt.y);
            o2.y = pack_bf2((v.z - mu) * inv * gm.z + bt.z, (v.w - mu) * inv * gm.w + bt.w);
            *(uint2*)(mS + r * SH + lane * 4) = o2;
        }
    }
    __syncthreads();

    const int g = lane >> 2, s = lane & 3;
    const uint32_t mA = smemA_base(mS, SH,  lane) + (wm * 32 * SH)  * 2;
    const uint32_t hA = smemA_base(hS, SH2, lane) + (wm * 32 * SH2) * 2;
    const uint2* w1p = g_w1F + lane;
    const uint2* w2p = g_w2F + lane;

    // ---- GEMM1 over full N=512, 4 sub-chunks per warp, NO intermediate syncs
    #pragma unroll
    for (int sc = 0; sc < 4; sc++) {
        const int ntb = sc * 16 + wn * 4;              // global ntile base (of 64)
        uint2 bf[4][8];
        #pragma unroll
        for (int nt = 0; nt < 4; nt++)
            #pragma unroll
            for (int ks = 0; ks < 8; ks++)
                bf[nt][ks] = w1p[((ntb + nt) * 8 + ks) * 32];

        float acc[2][4][4];
        #pragma unroll
        for (int mt = 0; mt < 2; mt++)
            #pragma unroll
            for (int nt = 0; nt < 4; nt++)
                #pragma unroll
                for (int r = 0; r < 4; r++) acc[mt][nt][r] = 0.f;

        #pragma unroll
        for (int ks = 0; ks < 8; ks++) {
            #pragma unroll
            for (int mt = 0; mt < 2; mt++) {
                unsigned afr[4];
                ldsm4(afr, mA + (mt * 16 * SH + ks * 16) * 2);
                #pragma unroll
                for (int nt = 0; nt < 4; nt++) mma_bf16_u2(acc[mt][nt], afr, bf[nt][ks]);
            }
        }

        // bias + fast GELU -> hS (warp-private 32x32 region of the 512-wide row block)
        #pragma unroll
        for (int mt = 0; mt < 2; mt++) {
            #pragma unroll
            for (int nt = 0; nt < 4; nt++) {
                const int cg = (ntb + nt) * 8 + 2 * s;      // global hidden col
                const float bb0 = b1[cg], bb1 = b1[cg + 1];
                const int r0 = wm * 32 + mt * 16 + g;
                *(unsigned*)(hS + r0 * SH2 + cg) =
                    pack_bf2(gelu_fast(acc[mt][nt][0] + bb0), gelu_fast(acc[mt][nt][1] + bb1));
                *(unsigned*)(hS + (r0 + 8) * SH2 + cg) =
                    pack_bf2(gelu_fast(acc[mt][nt][2] + bb0), gelu_fast(acc[mt][nt][3] + bb1));
            }
        }
    }
    __syncthreads();   // the ONLY inter-phase barrier

    // ---- GEMM2: M=64, N=128 (warp 32x32), K=512 uninterrupted
    float fac[2][4][4];
    #pragma unroll
    for (int mt = 0; mt < 2; mt++)
        #pragma unroll
        for (int nt = 0; nt < 4; nt++)
            #pragma unroll
            for (int r = 0; r < 4; r++) fac[mt][nt][r] = 0.f;

    #pragma unroll
    for (int kb = 0; kb < 4; kb++) {
        uint2 cf[4][8];
        #pragma unroll
        for (int nt = 0; nt < 4; nt++)
            #pragma unroll
            for (int ks = 0; ks < 8; ks++)
                cf[nt][ks] = w2p[(wn * 4 + nt) * 1024 + (kb * 8 + ks) * 32];

        #pragma unroll
        for (int ks = 0; ks < 8; ks++) {
            const int kk = kb * 8 + ks;
            #pragma unroll
            for (int mt = 0; mt < 2; mt++) {
                unsigned afr[4];
                ldsm4(afr, hA + (mt * 16 * SH2 + kk * 16) * 2);
                #pragma unroll
                for (int nt = 0; nt < 4; nt++) mma_bf16_u2(fac[mt][nt], afr, cf[nt][ks]);
            }
        }
    }

    // epilogue: + b2 + residual g_y -> out
    #pragma unroll
    for (int mt = 0; mt < 2; mt++) {
        #pragma unroll
        for (int nt = 0; nt < 4; nt++) {
            const int c = wn * 32 + nt * 8 + 2 * s;
            const float bb0 = b2[c], bb1 = b2[c + 1];
            const int r0 = wm * 32 + mt * 16 + g;
            size_t p0 = ((size_t)(t0 + r0)) * CD + c;
            size_t p1 = ((size_t)(t0 + r0 + 8)) * CD + c;
            float2 y0 = *(const float2*)(g_y + p0);
            float2 y1 = *(const float2*)(g_y + p1);
            float2 o0, o1;
            o0.x = fac[mt][nt][0] + bb0 + y0.x;
            o0.y = fac[mt][nt][1] + bb1 + y0.y;
            o1.x = fac[mt][nt][2] + bb0 + y1.x;
            o1.y = fac[mt][nt][3] + bb1 + y1.y;
            *(float2*)(out + p0) = o0;
            *(float2*)(out + p1) = o1;
        }
    }
}

// ---------------- launch ----------------
extern "C" void kernel_launch(void* const* d_in, const int* in_sizes, int n_in,
                              void* d_out, int out_size) {
    const float* x   = (const float*)d_in[0];
    const float* wq  = (const float*)d_in[1];
    const float* bq  = (const float*)d_in[2];
    const float* wk  = (const float*)d_in[3];
    const float* bk  = (const float*)d_in[4];
    const float* wv  = (const float*)d_in[5];
    const float* bv  = (const float*)d_in[6];
    const float* wo  = (const float*)d_in[7];
    const float* bo  = (const float*)d_in[8];
    const float* rel = (const float*)d_in[9];
    const float* g1  = (const float*)d_in[10];
    const float* be1 = (const float*)d_in[11];
    const float* g2  = (const float*)d_in[12];
    const float* be2 = (const float*)d_in[13];
    const float* w1  = (const float*)d_in[14];
    const float* b1  = (const float*)d_in[15];
    const float* w2  = (const float*)d_in[16];
    const float* b2  = (const float*)d_in[17];
    float* out = (float*)d_out;

    cudaFuncSetAttribute(attn_kernel, cudaFuncAttributeMaxDynamicSharedMemorySize, 70656);
    cudaFuncSetAttribute(mlp_kernel,  cudaFuncAttributeMaxDynamicSharedMemorySize, 83968);

    pack_weights<<<192, 256>>>(wq, wk, wv, wo, w1, w2);
    build_bm<<<1024, 256>>>(rel);
    attn_kernel<<<4096, 256, 70656>>>(x, g1, be1, bq, bk, bv, bo);
    mlp_kernel<<<3136, 256, 83968>>>(g2, be2, b1, b2, out);
}

// round 12
// speedup vs baseline: 1.2000x; 1.0016x over previous
#include <cuda_runtime.h>
#include <cuda_bf16.h>
#include <math.h>
#include <stdint.h>

#define HEADS 4
#define CD    128
#define TOK   200704          // B * 3136
#define SH    136             // smem stride (bf16) for 128-wide tiles
#define SH2   520             // smem stride (bf16) for 512-wide hidden
#define SV    72              // smem stride (bf16) for vT (64-wide)

// ---------------- scratch ----------------
__device__ float  g_y[(size_t)TOK * CD];          // x + attn_out
__device__ uint2  g_wqkvF[48 * 8 * 32];
__device__ uint2  g_woF  [16 * 8 * 32];
__device__ uint2  g_w1F  [64 * 8 * 32];
__device__ uint2  g_w2F  [16 * 32 * 32];
__device__ float4 g_bm4[64 * HEADS * 4 * 8 * 32];

// ---------------- helpers ----------------
__device__ __forceinline__ void mma_bf16(float d[4], const unsigned a[4], const unsigned b[2]) {
    asm volatile("mma.sync.aligned.m16n8k16.row.col.f32.bf16.bf16.f32 "
                 "{%0,%1,%2,%3}, {%4,%5,%6,%7}, {%8,%9}, {%0,%1,%2,%3};\n"
                 : "+f"(d[0]), "+f"(d[1]), "+f"(d[2]), "+f"(d[3])
                 : "r"(a[0]), "r"(a[1]), "r"(a[2]), "r"(a[3]), "r"(b[0]), "r"(b[1]));
}
__device__ __forceinline__ void mma_bf16_u2(float d[4], const unsigned a[4], uint2 b) {
    asm volatile("mma.sync.aligned.m16n8k16.row.col.f32.bf16.bf16.f32 "
                 "{%0,%1,%2,%3}, {%4,%5,%6,%7}, {%8,%9}, {%0,%1,%2,%3};\n"
                 : "+f"(d[0]), "+f"(d[1]), "+f"(d[2]), "+f"(d[3])
                 : "r"(a[0]), "r"(a[1]), "r"(a[2]), "r"(a[3]), "r"(b.x), "r"(b.y));
}
__device__ __forceinline__ void ldsm4(unsigned a[4], uint32_t addr) {
    asm volatile("ldmatrix.sync.aligned.m8n8.x4.shared.b16 {%0,%1,%2,%3}, [%4];"
                 : "=r"(a[0]), "=r"(a[1]), "=r"(a[2]), "=r"(a[3]) : "r"(addr));
}
__device__ __forceinline__ void ldsm2(unsigned b[2], uint32_t addr) {
    asm volatile("ldmatrix.sync.aligned.m8n8.x2.shared.b16 {%0,%1}, [%2];"
                 : "=r"(b[0]), "=r"(b[1]) : "r"(addr));
}
__device__ __forceinline__ uint32_t smemA_base(const void* p, int stride, int lane) {
    return (uint32_t)__cvta_generic_to_shared(p) +
           (uint32_t)(((lane & 15) * stride + ((lane >> 4) << 3)) * 2);
}
__device__ __forceinline__ uint32_t smemB_base(const void* p, int stride, int lane) {
    return (uint32_t)__cvta_generic_to_shared(p) +
           (uint32_t)(((lane & 7) * stride + (lane & 8)) * 2);
}
__device__ __forceinline__ unsigned pack_bf2(float lo, float hi) {
    unsigned r;
    asm("cvt.rn.bf16x2.f32 %0, %1, %2;" : "=r"(r) : "f"(hi), "f"(lo));
    return r;
}
__device__ __forceinline__ float gelu_fast(float v) {
    float u2 = v * v;
    float u = v * (1.5957691216f + 0.1426926424f * u2);
    float e = __expf(u);
    return __fdividef(v * e, e + 1.f);
}
__device__ __forceinline__ int region_of(int p) { return p < 49 ? 0 : (p < 53 ? 1 : 2); }

// ---------------- K0a: pack weights into fragment layout ----------------
__global__ void pack_weights(const float* __restrict__ wq, const float* __restrict__ wk,
                             const float* __restrict__ wv, const float* __restrict__ wo,
                             const float* __restrict__ w1, const float* __restrict__ w2) {
    int i = blockIdx.x * blockDim.x + threadIdx.x;   // 49152 threads
    if (i < 12288) {
        int lane = i & 31, kt = (i >> 5) & 7, nt = i >> 8;
        int n = nt * 8 + (lane >> 2), kk = kt * 16 + 2 * (lane & 3);
        const float* wsrc = (n < 128) ? wq : (n < 256) ? wk : wv;
        int nn = n & 127;
        uint2 v;
        v.x = pack_bf2(wsrc[kk * 128 + nn],       wsrc[(kk + 1) * 128 + nn]);
        v.y = pack_bf2(wsrc[(kk + 8) * 128 + nn], wsrc[(kk + 9) * 128 + nn]);
        g_wqkvF[i] = v;
    } else if (i < 16384) {
        int j = i - 12288;
        int lane = j & 31, kt = (j >> 5) & 7, nt = j >> 8;
        int n = nt * 8 + (lane >> 2), kk = kt * 16 + 2 * (lane & 3);
        uint2 v;
        v.x = pack_bf2(wo[kk * 128 + n],       wo[(kk + 1) * 128 + n]);
        v.y = pack_bf2(wo[(kk + 8) * 128 + n], wo[(kk + 9) * 128 + n]);
        g_woF[j] = v;
    } else if (i < 32768) {
        int j = i - 16384;
        int lane = j & 31, kt = (j >> 5) & 7, nt = j >> 8;
        int n = nt * 8 + (lane >> 2), kk = kt * 16 + 2 * (lane & 3);
        uint2 v;
        v.x = pack_bf2(w1[kk * 512 + n],       w1[(kk + 1) * 512 + n]);
        v.y = pack_bf2(w1[(kk + 8) * 512 + n], w1[(kk + 9) * 512 + n]);
        g_w1F[j] = v;
    } else {
        int j = i - 32768;
        int lane = j & 31, kt = (j >> 5) & 31, nt = j >> 10;
        int n = nt * 8 + (lane >> 2), kk = kt * 16 + 2 * (lane & 3);
        uint2 v;
        v.x = pack_bf2(w2[kk * 128 + n],       w2[(kk + 1) * 128 + n]);
        v.y = pack_bf2(w2[(kk + 8) * 128 + n], w2[(kk + 9) * 128 + n]);
        g_w2F[j] = v;
    }
}

// ---------------- K0b: bias+mask table ----------------
__device__ __forceinline__ float bm_val(const float* __restrict__ rel, int w, int h, int q, int k) {
    if (q >= 49 || k >= 49) return -1e30f;
    int qi = q / 7, qj = q % 7, ki = k / 7, kj = k % 7;
    int r0 = (ki - qi) % 13; if (r0 < 0) r0 += 13;
    int r1 = (kj - qj) % 13; if (r1 < 0) r1 += 13;
    float bias = rel[(r0 * 13 + r1) * HEADS + h];
    int wr = w >> 3, wc = w & 7;
    int idq = region_of(wr * 7 + qi) * 3 + region_of(wc * 7 + qj);
    int idk = region_of(wr * 7 + ki) * 3 + region_of(wc * 7 + kj);
    return bias + (idq == idk ? 0.f : -100.f);
}
__global__ void build_bm(const float* __restrict__ rel) {
    int i = blockIdx.x * blockDim.x + threadIdx.x;   // 262144
    int lane = i & 31, nt = (i >> 5) & 7, mtile = (i >> 8) & 3, h = (i >> 10) & 3, w = i >> 12;
    int g = lane >> 2, s = lane & 3;
    int rA = mtile * 16 + g, rB = rA + 8, cc = nt * 8 + 2 * s;
    float4 v;
    v.x = bm_val(rel, w, h, rA, cc);
    v.y = bm_val(rel, w, h, rA, cc + 1);
    v.z = bm_val(rel, w, h, rB, cc);
    v.w = bm_val(rel, w, h, rB, cc + 1);
    g_bm4[i] = v;
}

// ---------------- K1: fused LN1 + window attention + O-proj + residual ----------------
__global__ void __launch_bounds__(256, 2) attn_kernel(const float* __restrict__ x,
                                                      const float* __restrict__ gam,
                                                      const float* __restrict__ bet,
                                                      const float* __restrict__ bq,
                                                      const float* __restrict__ bk,
                                                      const float* __restrict__ bv,
                                                      const float* __restrict__ bo) {
    extern __shared__ char smraw[];
    __nv_bfloat16* hS = (__nv_bfloat16*)smraw;
    __nv_bfloat16* qS = (__nv_bfloat16*)(smraw + 17408);
    __nv_bfloat16* kS = (__nv_bfloat16*)(smraw + 34816);
    __nv_bfloat16* vT = (__nv_bfloat16*)(smraw + 52224);
    __nv_bfloat16* oS = hS;

    const int win = blockIdx.x, b = win >> 6, w = win & 63;
    const int wr = w >> 3, wc = w & 7;
    const int warp = threadIdx.x >> 5, lane = threadIdx.x & 31;
    const int g = lane >> 2, s = lane & 3;

    const uint2* wqp = g_wqkvF + warp * 6 * 8 * 32 + lane;
    const uint2* wop = g_woF   + warp * 2 * 8 * 32 + lane;

    // prefetch QKV pass-0 weights (overlaps with LN gather below)
    uint2 bfr[3][8];
    #pragma unroll
    for (int nt = 0; nt < 3; nt++)
        #pragma unroll
        for (int ks = 0; ks < 8; ks++)
            bfr[nt][ks] = wqp[(nt * 8 + ks) * 32];

    // ---- LN1 + roll(+3) gather into smem, with batched gather preload
    {
        const float4 gm = *(const float4*)(gam + lane * 4);
        const float4 bt = *(const float4*)(bet + lane * 4);
        float4 vv[8];
        #pragma unroll
        for (int it = 0; it < 8; it++) {
            const int n = warp + it * 8;
            if (n < 49) {
                const int i = n / 7, j = n % 7;
                const int sh = (wr * 7 + i + 3) % 56, sw = (wc * 7 + j + 3) % 56;
                vv[it] = *(const float4*)(x + ((size_t)b * 3136 + sh * 56 + sw) * CD + lane * 4);
            }
        }
        #pragma unroll
        for (int it = 0; it < 8; it++) {
            const int n = warp + it * 8;
            __nv_bfloat16* dst = hS + n * SH;
            if (n >= 49) {
                ((unsigned*)dst)[lane]      = 0u;
                ((unsigned*)dst)[lane + 32] = 0u;
                continue;
            }
            float4 v = vv[it];
            float sum = v.x + v.y + v.z + v.w;
            float sq  = v.x * v.x + v.y * v.y + v.z * v.z + v.w * v.w;
            #pragma unroll
            for (int o = 16; o; o >>= 1) {
                sum += __shfl_xor_sync(0xffffffffu, sum, o);
                sq  += __shfl_xor_sync(0xffffffffu, sq, o);
            }
            const float mu = sum * (1.f / 128.f);
            const float inv = rsqrtf(sq * (1.f / 128.f) - mu * mu + 1e-5f);
            uint2 o2;
            o2.x = pack_bf2((v.x - mu) * inv * gm.x + bt.x, (v.y - mu) * inv * gm.y + bt.y);
            o2.y = pack_bf2((v.z - mu) * inv * gm.z + bt.z, (v.w - mu) * inv * gm.w + bt.w);
            *(uint2*)(dst + lane * 4) = o2;
        }
    }
    __syncthreads();

    const uint32_t hA = smemA_base(hS, SH, lane);
    const uint32_t qA = smemA_base(qS, SH, lane);
    const uint32_t kB = smemB_base(kS, SH, lane);
    const uint32_t vB = smemB_base(vT, SV, lane);

    // ---- QKV gemm: M=64 N=384 K=128; 2 passes of 24 cols per warp
    const float invs = 0.17677669529663687f;  // 1/sqrt(32)
    #pragma unroll
    for (int pass = 0; pass < 2; pass++) {
        float acc[4][3][4];
        #pragma unroll
        for (int mt = 0; mt < 4; mt++)
            #pragma unroll
            for (int nt = 0; nt < 3; nt++)
                #pragma unroll
                for (int r = 0; r < 4; r++) acc[mt][nt][r] = 0.f;
        #pragma unroll
        for (int ks = 0; ks < 8; ks++) {
            #pragma unroll
            for (int mt = 0; mt < 4; mt++) {
                unsigned afr[4];
                ldsm4(afr, hA + (mt * 16 * SH + ks * 16) * 2);
                #pragma unroll
                for (int nt = 0; nt < 3; nt++) mma_bf16_u2(acc[mt][nt], afr, bfr[nt][ks]);
            }
        }
        // reload weights for pass 1 (overlaps with epilogue below)
        if (pass == 0) {
            #pragma unroll
            for (int nt = 0; nt < 3; nt++)
                #pragma unroll
                for (int ks = 0; ks < 8; ks++)
                    bfr[nt][ks] = wqp[((3 + nt) * 8 + ks) * 32];
        }
        #pragma unroll
        for (int mt = 0; mt < 4; mt++) {
            #pragma unroll
            for (int nt = 0; nt < 3; nt++) {
                const int nb = warp * 48 + (pass * 3 + nt) * 8;
                const int c0 = nb + 2 * s;
                const int r0 = mt * 16 + g;
                float v0 = acc[mt][nt][0], v1 = acc[mt][nt][1], v2 = acc[mt][nt][2], v3 = acc[mt][nt][3];
                if (nb < 128) {
                    float b0 = bq[c0], b1 = bq[c0 + 1];
                    *(unsigned*)(qS + r0 * SH + c0)       = pack_bf2((v0 + b0) * invs, (v1 + b1) * invs);
                    *(unsigned*)(qS + (r0 + 8) * SH + c0) = pack_bf2((v2 + b0) * invs, (v3 + b1) * invs);
                } else if (nb < 256) {
                    int cc = c0 - 128;
                    float b0 = bk[cc], b1 = bk[cc + 1];
                    *(unsigned*)(kS + r0 * SH + cc)       = pack_bf2(v0 + b0, v1 + b1);
                    *(unsigned*)(kS + (r0 + 8) * SH + cc) = pack_bf2(v2 + b0, v3 + b1);
                } else {
                    int d0 = c0 - 256;
                    float b0 = bv[d0], b1 = bv[d0 + 1];
                    vT[d0 * SV + r0]           = __float2bfloat16_rn(v0 + b0);
                    vT[(d0 + 1) * SV + r0]     = __float2bfloat16_rn(v1 + b1);
                    vT[d0 * SV + r0 + 8]       = __float2bfloat16_rn(v2 + b0);
                    vT[(d0 + 1) * SV + r0 + 8] = __float2bfloat16_rn(v3 + b1);
                }
            }
        }
    }
    __syncthreads();

    // ---- logits: warp -> head hw, row-half mh
    const int hw = warp >> 1, mh = warp & 1;
    const float4* bmp = g_bm4 + (((size_t)(w * HEADS + hw) * 4 + mh * 2) * 8) * 32 + lane;

    // prefetch bm for mt=0 (overlaps logits MMAs below)
    float4 bmf0[8];
    #pragma unroll
    for (int nt = 0; nt < 8; nt++) bmf0[nt] = bmp[nt * 32];

    float lac[2][8][4];
    #pragma unroll
    for (int mt = 0; mt < 2; mt++)
        #pragma unroll
        for (int nt = 0; nt < 8; nt++)
            #pragma unroll
            for (int r = 0; r < 4; r++) lac[mt][nt][r] = 0.f;

    {
        const uint32_t qBase = qA + (mh * 32 * SH + hw * 32) * 2;
        const uint32_t kBase = kB + (hw * 32) * 2;
        #pragma unroll
        for (int ks = 0; ks < 2; ks++) {
            unsigned bfk[8][2];
            #pragma unroll
            for (int nt = 0; nt < 8; nt++) ldsm2(bfk[nt], kBase + (nt * 8 * SH + ks * 16) * 2);
            #pragma unroll
            for (int mt = 0; mt < 2; mt++) {
                unsigned afr[4];
                ldsm4(afr, qBase + (mt * 16 * SH + ks * 16) * 2);
                #pragma unroll
                for (int nt = 0; nt < 8; nt++) mma_bf16(lac[mt][nt], afr, bfk[nt]);
            }
        }
    }

    // ---- softmax mt=0 (bm prefetched); prefetch mt=1 bm during mt=0 exp chain
    float4 bmf1[8];
    #pragma unroll
    for (int mt = 0; mt < 2; mt++) {
        float mA = -1e30f, mB = -1e30f;
        #pragma unroll
        for (int nt = 0; nt < 8; nt++) {
            float4 bv4 = (mt == 0) ? bmf0[nt] : bmf1[nt];
            lac[mt][nt][0] += bv4.x;
            lac[mt][nt][1] += bv4.y;
            lac[mt][nt][2] += bv4.z;
            lac[mt][nt][3] += bv4.w;
            mA = fmaxf(mA, fmaxf(lac[mt][nt][0], lac[mt][nt][1]));
            mB = fmaxf(mB, fmaxf(lac[mt][nt][2], lac[mt][nt][3]));
        }
        if (mt == 0) {   // issue mt=1 bm loads; they complete under the exp/shuffle chain
            #pragma unroll
            for (int nt = 0; nt < 8; nt++) bmf1[nt] = bmp[(8 + nt) * 32];
        }
        mA = fmaxf(mA, __shfl_xor_sync(0xffffffffu, mA, 1));
        mA = fmaxf(mA, __shfl_xor_sync(0xffffffffu, mA, 2));
        mB = fmaxf(mB, __shfl_xor_sync(0xffffffffu, mB, 1));
        mB = fmaxf(mB, __shfl_xor_sync(0xffffffffu, mB, 2));
        float sA = 0.f, sB = 0.f;
        #pragma unroll
        for (int nt = 0; nt < 8; nt++) {
            lac[mt][nt][0] = __expf(lac[mt][nt][0] - mA);
            lac[mt][nt][1] = __expf(lac[mt][nt][1] - mA);
            lac[mt][nt][2] = __expf(lac[mt][nt][2] - mB);
            lac[mt][nt][3] = __expf(lac[mt][nt][3] - mB);
            sA += lac[mt][nt][0] + lac[mt][nt][1];
            sB += lac[mt][nt][2] + lac[mt][nt][3];
        }
        sA += __shfl_xor_sync(0xffffffffu, sA, 1);
        sA += __shfl_xor_sync(0xffffffffu, sA, 2);
        sB += __shfl_xor_sync(0xffffffffu, sB, 1);
        sB += __shfl_xor_sync(0xffffffffu, sB, 2);
        const float iA = 1.f / sA, iB = 1.f / sB;
        #pragma unroll
        for (int nt = 0; nt < 8; nt++) {
            lac[mt][nt][0] *= iA; lac[mt][nt][1] *= iA;
            lac[mt][nt][2] *= iB; lac[mt][nt][3] *= iB;
        }
    }

    // ---- attn @ V (P stays in registers)
    float oac[2][4][4];
    #pragma unroll
    for (int mt = 0; mt < 2; mt++)
        #pragma unroll
        for (int nt = 0; nt < 4; nt++)
            #pragma unroll
            for (int r = 0; r < 4; r++) oac[mt][nt][r] = 0.f;

    {
        const uint32_t vBase = vB + (hw * 32 * SV) * 2;
        #pragma unroll
        for (int kt = 0; kt < 4; kt++) {
            unsigned bfv[4][2];
            #pragma unroll
            for (int nt = 0; nt < 4; nt++) ldsm2(bfv[nt], vBase + (nt * 8 * SV + kt * 16) * 2);
            #pragma unroll
            for (int mt = 0; mt < 2; mt++) {
                unsigned pa[4];
                pa[0] = pack_bf2(lac[mt][2 * kt][0],     lac[mt][2 * kt][1]);
                pa[1] = pack_bf2(lac[mt][2 * kt][2],     lac[mt][2 * kt][3]);
                pa[2] = pack_bf2(lac[mt][2 * kt + 1][0], lac[mt][2 * kt + 1][1]);
                pa[3] = pack_bf2(lac[mt][2 * kt + 1][2], lac[mt][2 * kt + 1][3]);
                #pragma unroll
                for (int nt = 0; nt < 4; nt++) mma_bf16(oac[mt][nt], pa, bfv[nt]);
            }
        }
    }

    // ---- prefetch O-proj weights while storing P@V tile
    uint2 bfo[2][8];
    #pragma unroll
    for (int nt = 0; nt < 2; nt++)
        #pragma unroll
        for (int ks = 0; ks < 8; ks++)
            bfo[nt][ks] = wop[(nt * 8 + ks) * 32];

    #pragma unroll
    for (int mt = 0; mt < 2; mt++) {
        #pragma unroll
        for (int nt = 0; nt < 4; nt++) {
            const int r0 = mh * 32 + mt * 16 + g;
            const int c0 = hw * 32 + nt * 8 + 2 * s;
            *(unsigned*)(oS + r0 * SH + c0)       = pack_bf2(oac[mt][nt][0], oac[mt][nt][1]);
            *(unsigned*)(oS + (r0 + 8) * SH + c0) = pack_bf2(oac[mt][nt][2], oac[mt][nt][3]);
        }
    }
    __syncthreads();

    // ---- prefetch residual x rows (overlaps O-proj MMAs)
    float2 xr[4][2][2];
    #pragma unroll
    for (int mt = 0; mt < 4; mt++) {
        #pragma unroll
        for (int nt = 0; nt < 2; nt++) {
            const int c = warp * 16 + nt * 8 + 2 * s;
            const int r0 = mt * 16 + g, r1 = r0 + 8;
            if (r0 < 49)
                xr[mt][nt][0] = *(const float2*)(x + ((size_t)b * 3136 + w * 49 + r0) * CD + c);
            if (r1 < 49)
                xr[mt][nt][1] = *(const float2*)(x + ((size_t)b * 3136 + w * 49 + r1) * CD + c);
        }
    }

    // ---- O projection: M=64 N=128 K=128
    float fac[4][2][4];
    #pragma unroll
    for (int mt = 0; mt < 4; mt++)
        #pragma unroll
        for (int nt = 0; nt < 2; nt++)
            #pragma unroll
            for (int r = 0; r < 4; r++) fac[mt][nt][r] = 0.f;

    #pragma unroll
    for (int ks = 0; ks < 8; ks++) {
        #pragma unroll
        for (int mt = 0; mt < 4; mt++) {
            unsigned afr[4];
            ldsm4(afr, hA + (mt * 16 * SH + ks * 16) * 2);
            #pragma unroll
            for (int nt = 0; nt < 2; nt++) mma_bf16_u2(fac[mt][nt], afr, bfo[nt][ks]);
        }
    }

    // epilogue: + bo + residual x -> g_y (window-order tokens)
    #pragma unroll
    for (int mt = 0; mt < 4; mt++) {
        #pragma unroll
        for (int nt = 0; nt < 2; nt++) {
            const int c = warp * 16 + nt * 8 + 2 * s;
            const float bo0 = bo[c], bo1 = bo[c + 1];
            const int r0 = mt * 16 + g, r1 = r0 + 8;
            if (r0 < 49) {
                size_t p = ((size_t)b * 3136 + w * 49 + r0) * CD + c;
                float2 o;
                o.x = fac[mt][nt][0] + bo0 + xr[mt][nt][0].x;
                o.y = fac[mt][nt][1] + bo1 + xr[mt][nt][0].y;
                *(float2*)(g_y + p) = o;
            }
            if (r1 < 49) {
                size_t p = ((size_t)b * 3136 + w * 49 + r1) * CD + c;
                float2 o;
                o.x = fac[mt][nt][2] + bo0 + xr[mt][nt][1].x;
                o.y = fac[mt][nt][3] + bo1 + xr[mt][nt][1].y;
                *(float2*)(g_y + p) = o;
            }
        }
    }
}

// ---------------- K2: fused LN2 + MLP + residual (R8/R11 single-barrier schedule) ----------------
__global__ void __launch_bounds__(256, 2) mlp_kernel(const float* __restrict__ g2,
                                                     const float* __restrict__ be2,
                                                     const float* __restrict__ b1,
                                                     const float* __restrict__ b2,
                                                     float* __restrict__ out) {
    extern __shared__ char smraw[];
    __nv_bfloat16* mS = (__nv_bfloat16*)smraw;                   // 64 x SH   (17408 B)
    __nv_bfloat16* hS = (__nv_bfloat16*)(smraw + 17408);         // 64 x SH2  (66560 B)

    const int t0 = blockIdx.x * 64;
    const int warp = threadIdx.x >> 5, lane = threadIdx.x & 31;
    const int wm = warp >> 2, wn = warp & 3;          // 2x4 warp grid

    // ---- LN2 into mS, batched gather preload
    {
        const float4 gm = *(const float4*)(g2 + lane * 4);
        const float4 bt = *(const float4*)(be2 + lane * 4);
        float4 vv[8];
        #pragma unroll
        for (int it = 0; it < 8; it++) {
            const int r = warp + it * 8;
            vv[it] = *(const float4*)(g_y + ((size_t)(t0 + r)) * CD + lane * 4);
        }
        #pragma unroll
        for (int it = 0; it < 8; it++) {
            const int r = warp + it * 8;
            float4 v = vv[it];
            float sum = v.x + v.y + v.z + v.w;
            float sq  = v.x * v.x + v.y * v.y + v.z * v.z + v.w * v.w;
            #pragma unroll
            for (int o = 16; o; o >>= 1) {
                sum += __shfl_xor_sync(0xffffffffu, sum, o);
                sq  += __shfl_xor_sync(0xffffffffu, sq, o);
            }
            const float mu = sum * (1.f / 128.f);
            const float inv = rsqrtf(sq * (1.f / 128.f) - mu * mu + 1e-5f);
            uint2 o2;
            o2.x = pack_bf2((v.x - mu) * inv * gm.x + bt.x, (v.y - mu) * inv * gm.y + bt.y);
            o2.y = pack_bf2((v.z - mu) * inv * gm.z + bt.z, (v.w - mu) * inv * gm.w + bt.w);
            *(uint2*)(mS + r * SH + lane * 4) = o2;
        }
    }
    __syncthreads();

    const int g = lane >> 2, s = lane & 3;
    const uint32_t mA = smemA_base(mS, SH,  lane) + (wm * 32 * SH)  * 2;
    const uint32_t hA = smemA_base(hS, SH2, lane) + (wm * 32 * SH2) * 2;
    const uint2* w1p = g_w1F + lane;
    const uint2* w2p = g_w2F + lane;

    // ---- GEMM1 over full N=512, 4 sub-chunks per warp, NO intermediate syncs
    #pragma unroll
    for (int sc = 0; sc < 4; sc++) {
        const int ntb = sc * 16 + wn * 4;              // global ntile base (of 64)
        uint2 bf[4][8];
        #pragma unroll
        for (int nt = 0; nt < 4; nt++)
            #pragma unroll
            for (int ks = 0; ks < 8; ks++)
                bf[nt][ks] = w1p[((ntb + nt) * 8 + ks) * 32];

        float acc[2][4][4];
        #pragma unroll
        for (int mt = 0; mt < 2; mt++)
            #pragma unroll
            for (int nt = 0; nt < 4; nt++)
                #pragma unroll
                for (int r = 0; r < 4; r++) acc[mt][nt][r] = 0.f;

        #pragma unroll
        for (int ks = 0; ks < 8; ks++) {
            #pragma unroll
            for (int mt = 0; mt < 2; mt++) {
                unsigned afr[4];
                ldsm4(afr, mA + (mt * 16 * SH + ks * 16) * 2);
                #pragma unroll
                for (int nt = 0; nt < 4; nt++) mma_bf16_u2(acc[mt][nt], afr, bf[nt][ks]);
            }
        }

        // bias + fast GELU -> hS (warp-private 32x32 region of the 512-wide row block)
        #pragma unroll
        for (int mt = 0; mt < 2; mt++) {
            #pragma unroll
            for (int nt = 0; nt < 4; nt++) {
                const int cg = (ntb + nt) * 8 + 2 * s;      // global hidden col
                const float bb0 = b1[cg], bb1 = b1[cg + 1];
                const int r0 = wm * 32 + mt * 16 + g;
                *(unsigned*)(hS + r0 * SH2 + cg) =
                    pack_bf2(gelu_fast(acc[mt][nt][0] + bb0), gelu_fast(acc[mt][nt][1] + bb1));
                *(unsigned*)(hS + (r0 + 8) * SH2 + cg) =
                    pack_bf2(gelu_fast(acc[mt][nt][2] + bb0), gelu_fast(acc[mt][nt][3] + bb1));
            }
        }
    }
    __syncthreads();   // the ONLY inter-phase barrier

    // ---- GEMM2: M=64, N=128 (warp 32x32), K=512 uninterrupted
    float fac[2][4][4];
    #pragma unroll
    for (int mt = 0; mt < 2; mt++)
        #pragma unroll
        for (int nt = 0; nt < 4; nt++)
            #pragma unroll
            for (int r = 0; r < 4; r++) fac[mt][nt][r] = 0.f;

    #pragma unroll
    for (int kb = 0; kb < 4; kb++) {
        uint2 cf[4][8];
        #pragma unroll
        for (int nt = 0; nt < 4; nt++)
            #pragma unroll
            for (int ks = 0; ks < 8; ks++)
                cf[nt][ks] = w2p[(wn * 4 + nt) * 1024 + (kb * 8 + ks) * 32];

        #pragma unroll
        for (int ks = 0; ks < 8; ks++) {
            const int kk = kb * 8 + ks;
            #pragma unroll
            for (int mt = 0; mt < 2; mt++) {
                unsigned afr[4];
                ldsm4(afr, hA + (mt * 16 * SH2 + kk * 16) * 2);
                #pragma unroll
                for (int nt = 0; nt < 4; nt++) mma_bf16_u2(fac[mt][nt], afr, cf[nt][ks]);
            }
        }
    }

    // epilogue: + b2 + residual g_y -> out
    #pragma unroll
    for (int mt = 0; mt < 2; mt++) {
        #pragma unroll
        for (int nt = 0; nt < 4; nt++) {
            const int c = wn * 32 + nt * 8 + 2 * s;
            const float bb0 = b2[c], bb1 = b2[c + 1];
            const int r0 = wm * 32 + mt * 16 + g;
            size_t p0 = ((size_t)(t0 + r0)) * CD + c;
            size_t p1 = ((size_t)(t0 + r0 + 8)) * CD + c;
            float2 y0 = *(const float2*)(g_y + p0);
            float2 y1 = *(const float2*)(g_y + p1);
            float2 o0, o1;
            o0.x = fac[mt][nt][0] + bb0 + y0.x;
            o0.y = fac[mt][nt][1] + bb1 + y0.y;
            o1.x = fac[mt][nt][2] + bb0 + y1.x;
            o1.y = fac[mt][nt][3] + bb1 + y1.y;
            *(float2*)(out + p0) = o0;
            *(float2*)(out + p1) = o1;
        }
    }
}

// ---------------- launch ----------------
extern "C" void kernel_launch(void* const* d_in, const int* in_sizes, int n_in,
                              void* d_out, int out_size) {
    const float* x   = (const float*)d_in[0];
    const float* wq  = (const float*)d_in[1];
    const float* bq  = (const float*)d_in[2];
    const float* wk  = (const float*)d_in[3];
    const float* bk  = (const float*)d_in[4];
    const float* wv  = (const float*)d_in[5];
    const float* bv  = (const float*)d_in[6];
    const float* wo  = (const float*)d_in[7];
    const float* bo  = (const float*)d_in[8];
    const float* rel = (const float*)d_in[9];
    const float* g1  = (const float*)d_in[10];
    const float* be1 = (const float*)d_in[11];
    const float* g2  = (const float*)d_in[12];
    const float* be2 = (const float*)d_in[13];
    const float* w1  = (const float*)d_in[14];
    const float* b1  = (const float*)d_in[15];
    const float* w2  = (const float*)d_in[16];
    const float* b2  = (const float*)d_in[17];
    float* out = (float*)d_out;

    cudaFuncSetAttribute(attn_kernel, cudaFuncAttributeMaxDynamicSharedMemorySize, 70656);
    cudaFuncSetAttribute(mlp_kernel,  cudaFuncAttributeMaxDynamicSharedMemorySize, 83968);

    pack_weights<<<192, 256>>>(wq, wk, wv, wo, w1, w2);
    build_bm<<<1024, 256>>>(rel);
    attn_kernel<<<4096, 256, 70656>>>(x, g1, be1, bq, bk, bv, bo);
    mlp_kernel<<<3136, 256, 83968>>>(g2, be2, b1, b2, out);
}

// round 13
// speedup vs baseline: 1.2540x; 1.0450x over previous
#include <cuda_runtime.h>
#include <cuda_bf16.h>
#include <math.h>
#include <stdint.h>

#define HEADS 4
#define CD    128
#define TOK   200704          // B * 3136
#define SH    136             // smem stride (bf16) for 128-wide tiles
#define SH2   520             // smem stride (bf16) for 512-wide hidden
#define SV    72              // smem stride (bf16) for vT (64-wide)

// ---------------- scratch ----------------
__device__ float  g_y[(size_t)TOK * CD];          // x + attn_out
__device__ uint2  g_wqkvF[48 * 8 * 32];
__device__ uint2  g_woF  [16 * 8 * 32];
__device__ uint2  g_w1F  [64 * 8 * 32];
__device__ uint2  g_w2F  [16 * 32 * 32];
__device__ float4 g_bm4[64 * HEADS * 4 * 8 * 32];

// ---------------- helpers ----------------
__device__ __forceinline__ void mma_bf16(float d[4], const unsigned a[4], const unsigned b[2]) {
    asm volatile("mma.sync.aligned.m16n8k16.row.col.f32.bf16.bf16.f32 "
                 "{%0,%1,%2,%3}, {%4,%5,%6,%7}, {%8,%9}, {%0,%1,%2,%3};\n"
                 : "+f"(d[0]), "+f"(d[1]), "+f"(d[2]), "+f"(d[3])
                 : "r"(a[0]), "r"(a[1]), "r"(a[2]), "r"(a[3]), "r"(b[0]), "r"(b[1]));
}
__device__ __forceinline__ void mma_bf16_u2(float d[4], const unsigned a[4], uint2 b) {
    asm volatile("mma.sync.aligned.m16n8k16.row.col.f32.bf16.bf16.f32 "
                 "{%0,%1,%2,%3}, {%4,%5,%6,%7}, {%8,%9}, {%0,%1,%2,%3};\n"
                 : "+f"(d[0]), "+f"(d[1]), "+f"(d[2]), "+f"(d[3])
                 : "r"(a[0]), "r"(a[1]), "r"(a[2]), "r"(a[3]), "r"(b.x), "r"(b.y));
}
__device__ __forceinline__ void ldsm4(unsigned a[4], uint32_t addr) {
    asm volatile("ldmatrix.sync.aligned.m8n8.x4.shared.b16 {%0,%1,%2,%3}, [%4];"
                 : "=r"(a[0]), "=r"(a[1]), "=r"(a[2]), "=r"(a[3]) : "r"(addr));
}
__device__ __forceinline__ void ldsm2(unsigned b[2], uint32_t addr) {
    asm volatile("ldmatrix.sync.aligned.m8n8.x2.shared.b16 {%0,%1}, [%2];"
                 : "=r"(b[0]), "=r"(b[1]) : "r"(addr));
}
__device__ __forceinline__ uint32_t smemA_base(const void* p, int stride, int lane) {
    return (uint32_t)__cvta_generic_to_shared(p) +
           (uint32_t)(((lane & 15) * stride + ((lane >> 4) << 3)) * 2);
}
__device__ __forceinline__ uint32_t smemB_base(const void* p, int stride, int lane) {
    return (uint32_t)__cvta_generic_to_shared(p) +
           (uint32_t)(((lane & 7) * stride + (lane & 8)) * 2);
}
__device__ __forceinline__ unsigned pack_bf2(float lo, float hi) {
    unsigned r;
    asm("cvt.rn.bf16x2.f32 %0, %1, %2;" : "=r"(r) : "f"(hi), "f"(lo));
    return r;
}
__device__ __forceinline__ float gelu_fast(float v) {
    float u2 = v * v;
    float u = v * (1.5957691216f + 0.1426926424f * u2);
    float e = __expf(u);
    return __fdividef(v * e, e + 1.f);
}
__device__ __forceinline__ int region_of(int p) { return p < 49 ? 0 : (p < 53 ? 1 : 2); }

// ---------------- K0a: pack weights into fragment layout ----------------
__global__ void pack_weights(const float* __restrict__ wq, const float* __restrict__ wk,
                             const float* __restrict__ wv, const float* __restrict__ wo,
                             const float* __restrict__ w1, const float* __restrict__ w2) {
    int i = blockIdx.x * blockDim.x + threadIdx.x;   // 49152 threads
    if (i < 12288) {
        int lane = i & 31, kt = (i >> 5) & 7, nt = i >> 8;
        int n = nt * 8 + (lane >> 2), kk = kt * 16 + 2 * (lane & 3);
        const float* wsrc = (n < 128) ? wq : (n < 256) ? wk : wv;
        int nn = n & 127;
        uint2 v;
        v.x = pack_bf2(wsrc[kk * 128 + nn],       wsrc[(kk + 1) * 128 + nn]);
        v.y = pack_bf2(wsrc[(kk + 8) * 128 + nn], wsrc[(kk + 9) * 128 + nn]);
        g_wqkvF[i] = v;
    } else if (i < 16384) {
        int j = i - 12288;
        int lane = j & 31, kt = (j >> 5) & 7, nt = j >> 8;
        int n = nt * 8 + (lane >> 2), kk = kt * 16 + 2 * (lane & 3);
        uint2 v;
        v.x = pack_bf2(wo[kk * 128 + n],       wo[(kk + 1) * 128 + n]);
        v.y = pack_bf2(wo[(kk + 8) * 128 + n], wo[(kk + 9) * 128 + n]);
        g_woF[j] = v;
    } else if (i < 32768) {
        int j = i - 16384;
        int lane = j & 31, kt = (j >> 5) & 7, nt = j >> 8;
        int n = nt * 8 + (lane >> 2), kk = kt * 16 + 2 * (lane & 3);
        uint2 v;
        v.x = pack_bf2(w1[kk * 512 + n],       w1[(kk + 1) * 512 + n]);
        v.y = pack_bf2(w1[(kk + 8) * 512 + n], w1[(kk + 9) * 512 + n]);
        g_w1F[j] = v;
    } else {
        int j = i - 32768;
        int lane = j & 31, kt = (j >> 5) & 31, nt = j >> 10;
        int n = nt * 8 + (lane >> 2), kk = kt * 16 + 2 * (lane & 3);
        uint2 v;
        v.x = pack_bf2(w2[kk * 128 + n],       w2[(kk + 1) * 128 + n]);
        v.y = pack_bf2(w2[(kk + 8) * 128 + n], w2[(kk + 9) * 128 + n]);
        g_w2F[j] = v;
    }
}

// ---------------- K0b: bias+mask table ----------------
__device__ __forceinline__ float bm_val(const float* __restrict__ rel, int w, int h, int q, int k) {
    if (q >= 49 || k >= 49) return -1e30f;
    int qi = q / 7, qj = q % 7, ki = k / 7, kj = k % 7;
    int r0 = (ki - qi) % 13; if (r0 < 0) r0 += 13;
    int r1 = (kj - qj) % 13; if (r1 < 0) r1 += 13;
    float bias = rel[(r0 * 13 + r1) * HEADS + h];
    int wr = w >> 3, wc = w & 7;
    int idq = region_of(wr * 7 + qi) * 3 + region_of(wc * 7 + qj);
    int idk = region_of(wr * 7 + ki) * 3 + region_of(wc * 7 + kj);
    return bias + (idq == idk ? 0.f : -100.f);
}
__global__ void build_bm(const float* __restrict__ rel) {
    int i = blockIdx.x * blockDim.x + threadIdx.x;   // 262144
    int lane = i & 31, nt = (i >> 5) & 7, mtile = (i >> 8) & 3, h = (i >> 10) & 3, w = i >> 12;
    int g = lane >> 2, s = lane & 3;
    int rA = mtile * 16 + g, rB = rA + 8, cc = nt * 8 + 2 * s;
    float4 v;
    v.x = bm_val(rel, w, h, rA, cc);
    v.y = bm_val(rel, w, h, rA, cc + 1);
    v.z = bm_val(rel, w, h, rB, cc);
    v.w = bm_val(rel, w, h, rB, cc + 1);
    g_bm4[i] = v;
}

// ---------------- K1: fused LN1 + window attention + O-proj + residual (R12) ----------------
__global__ void __launch_bounds__(256, 2) attn_kernel(const float* __restrict__ x,
                                                      const float* __restrict__ gam,
                                                      const float* __restrict__ bet,
                                                      const float* __restrict__ bq,
                                                      const float* __restrict__ bk,
                                                      const float* __restrict__ bv,
                                                      const float* __restrict__ bo) {
    extern __shared__ char smraw[];
    __nv_bfloat16* hS = (__nv_bfloat16*)smraw;
    __nv_bfloat16* qS = (__nv_bfloat16*)(smraw + 17408);
    __nv_bfloat16* kS = (__nv_bfloat16*)(smraw + 34816);
    __nv_bfloat16* vT = (__nv_bfloat16*)(smraw + 52224);
    __nv_bfloat16* oS = hS;

    const int win = blockIdx.x, b = win >> 6, w = win & 63;
    const int wr = w >> 3, wc = w & 7;
    const int warp = threadIdx.x >> 5, lane = threadIdx.x & 31;
    const int g = lane >> 2, s = lane & 3;

    const uint2* wqp = g_wqkvF + warp * 6 * 8 * 32 + lane;
    const uint2* wop = g_woF   + warp * 2 * 8 * 32 + lane;

    uint2 bfr[3][8];
    #pragma unroll
    for (int nt = 0; nt < 3; nt++)
        #pragma unroll
        for (int ks = 0; ks < 8; ks++)
            bfr[nt][ks] = wqp[(nt * 8 + ks) * 32];

    {
        const float4 gm = *(const float4*)(gam + lane * 4);
        const float4 bt = *(const float4*)(bet + lane * 4);
        float4 vv[8];
        #pragma unroll
        for (int it = 0; it < 8; it++) {
            const int n = warp + it * 8;
            if (n < 49) {
                const int i = n / 7, j = n % 7;
                const int sh = (wr * 7 + i + 3) % 56, sw = (wc * 7 + j + 3) % 56;
                vv[it] = *(const float4*)(x + ((size_t)b * 3136 + sh * 56 + sw) * CD + lane * 4);
            }
        }
        #pragma unroll
        for (int it = 0; it < 8; it++) {
            const int n = warp + it * 8;
            __nv_bfloat16* dst = hS + n * SH;
            if (n >= 49) {
                ((unsigned*)dst)[lane]      = 0u;
                ((unsigned*)dst)[lane + 32] = 0u;
                continue;
            }
            float4 v = vv[it];
            float sum = v.x + v.y + v.z + v.w;
            float sq  = v.x * v.x + v.y * v.y + v.z * v.z + v.w * v.w;
            #pragma unroll
            for (int o = 16; o; o >>= 1) {
                sum += __shfl_xor_sync(0xffffffffu, sum, o);
                sq  += __shfl_xor_sync(0xffffffffu, sq, o);
            }
            const float mu = sum * (1.f / 128.f);
            const float inv = rsqrtf(sq * (1.f / 128.f) - mu * mu + 1e-5f);
            uint2 o2;
            o2.x = pack_bf2((v.x - mu) * inv * gm.x + bt.x, (v.y - mu) * inv * gm.y + bt.y);
            o2.y = pack_bf2((v.z - mu) * inv * gm.z + bt.z, (v.w - mu) * inv * gm.w + bt.w);
            *(uint2*)(dst + lane * 4) = o2;
        }
    }
    __syncthreads();

    const uint32_t hA = smemA_base(hS, SH, lane);
    const uint32_t qA = smemA_base(qS, SH, lane);
    const uint32_t kB = smemB_base(kS, SH, lane);
    const uint32_t vB = smemB_base(vT, SV, lane);

    const float invs = 0.17677669529663687f;  // 1/sqrt(32)
    #pragma unroll
    for (int pass = 0; pass < 2; pass++) {
        float acc[4][3][4];
        #pragma unroll
        for (int mt = 0; mt < 4; mt++)
            #pragma unroll
            for (int nt = 0; nt < 3; nt++)
                #pragma unroll
                for (int r = 0; r < 4; r++) acc[mt][nt][r] = 0.f;
        #pragma unroll
        for (int ks = 0; ks < 8; ks++) {
            #pragma unroll
            for (int mt = 0; mt < 4; mt++) {
                unsigned afr[4];
                ldsm4(afr, hA + (mt * 16 * SH + ks * 16) * 2);
                #pragma unroll
                for (int nt = 0; nt < 3; nt++) mma_bf16_u2(acc[mt][nt], afr, bfr[nt][ks]);
            }
        }
        if (pass == 0) {
            #pragma unroll
            for (int nt = 0; nt < 3; nt++)
                #pragma unroll
                for (int ks = 0; ks < 8; ks++)
                    bfr[nt][ks] = wqp[((3 + nt) * 8 + ks) * 32];
        }
        #pragma unroll
        for (int mt = 0; mt < 4; mt++) {
            #pragma unroll
            for (int nt = 0; nt < 3; nt++) {
                const int nb = warp * 48 + (pass * 3 + nt) * 8;
                const int c0 = nb + 2 * s;
                const int r0 = mt * 16 + g;
                float v0 = acc[mt][nt][0], v1 = acc[mt][nt][1], v2 = acc[mt][nt][2], v3 = acc[mt][nt][3];
                if (nb < 128) {
                    float b0 = bq[c0], b1 = bq[c0 + 1];
                    *(unsigned*)(qS + r0 * SH + c0)       = pack_bf2((v0 + b0) * invs, (v1 + b1) * invs);
                    *(unsigned*)(qS + (r0 + 8) * SH + c0) = pack_bf2((v2 + b0) * invs, (v3 + b1) * invs);
                } else if (nb < 256) {
                    int cc = c0 - 128;
                    float b0 = bk[cc], b1 = bk[cc + 1];
                    *(unsigned*)(kS + r0 * SH + cc)       = pack_bf2(v0 + b0, v1 + b1);
                    *(unsigned*)(kS + (r0 + 8) * SH + cc) = pack_bf2(v2 + b0, v3 + b1);
                } else {
                    int d0 = c0 - 256;
                    float b0 = bv[d0], b1 = bv[d0 + 1];
                    vT[d0 * SV + r0]           = __float2bfloat16_rn(v0 + b0);
                    vT[(d0 + 1) * SV + r0]     = __float2bfloat16_rn(v1 + b1);
                    vT[d0 * SV + r0 + 8]       = __float2bfloat16_rn(v2 + b0);
                    vT[(d0 + 1) * SV + r0 + 8] = __float2bfloat16_rn(v3 + b1);
                }
            }
        }
    }
    __syncthreads();

    const int hw = warp >> 1, mh = warp & 1;
    const float4* bmp = g_bm4 + (((size_t)(w * HEADS + hw) * 4 + mh * 2) * 8) * 32 + lane;

    float4 bmf0[8];
    #pragma unroll
    for (int nt = 0; nt < 8; nt++) bmf0[nt] = bmp[nt * 32];

    float lac[2][8][4];
    #pragma unroll
    for (int mt = 0; mt < 2; mt++)
        #pragma unroll
        for (int nt = 0; nt < 8; nt++)
            #pragma unroll
            for (int r = 0; r < 4; r++) lac[mt][nt][r] = 0.f;

    {
        const uint32_t qBase = qA + (mh * 32 * SH + hw * 32) * 2;
        const uint32_t kBase = kB + (hw * 32) * 2;
        #pragma unroll
        for (int ks = 0; ks < 2; ks++) {
            unsigned bfk[8][2];
            #pragma unroll
            for (int nt = 0; nt < 8; nt++) ldsm2(bfk[nt], kBase + (nt * 8 * SH + ks * 16) * 2);
            #pragma unroll
            for (int mt = 0; mt < 2; mt++) {
                unsigned afr[4];
                ldsm4(afr, qBase + (mt * 16 * SH + ks * 16) * 2);
                #pragma unroll
                for (int nt = 0; nt < 8; nt++) mma_bf16(lac[mt][nt], afr, bfk[nt]);
            }
        }
    }

    float4 bmf1[8];
    #pragma unroll
    for (int mt = 0; mt < 2; mt++) {
        float mA = -1e30f, mB = -1e30f;
        #pragma unroll
        for (int nt = 0; nt < 8; nt++) {
            float4 bv4 = (mt == 0) ? bmf0[nt] : bmf1[nt];
            lac[mt][nt][0] += bv4.x;
            lac[mt][nt][1] += bv4.y;
            lac[mt][nt][2] += bv4.z;
            lac[mt][nt][3] += bv4.w;
            mA = fmaxf(mA, fmaxf(lac[mt][nt][0], lac[mt][nt][1]));
            mB = fmaxf(mB, fmaxf(lac[mt][nt][2], lac[mt][nt][3]));
        }
        if (mt == 0) {
            #pragma unroll
            for (int nt = 0; nt < 8; nt++) bmf1[nt] = bmp[(8 + nt) * 32];
        }
        mA = fmaxf(mA, __shfl_xor_sync(0xffffffffu, mA, 1));
        mA = fmaxf(mA, __shfl_xor_sync(0xffffffffu, mA, 2));
        mB = fmaxf(mB, __shfl_xor_sync(0xffffffffu, mB, 1));
        mB = fmaxf(mB, __shfl_xor_sync(0xffffffffu, mB, 2));
        float sA = 0.f, sB = 0.f;
        #pragma unroll
        for (int nt = 0; nt < 8; nt++) {
            lac[mt][nt][0] = __expf(lac[mt][nt][0] - mA);
            lac[mt][nt][1] = __expf(lac[mt][nt][1] - mA);
            lac[mt][nt][2] = __expf(lac[mt][nt][2] - mB);
            lac[mt][nt][3] = __expf(lac[mt][nt][3] - mB);
            sA += lac[mt][nt][0] + lac[mt][nt][1];
            sB += lac[mt][nt][2] + lac[mt][nt][3];
        }
        sA += __shfl_xor_sync(0xffffffffu, sA, 1);
        sA += __shfl_xor_sync(0xffffffffu, sA, 2);
        sB += __shfl_xor_sync(0xffffffffu, sB, 1);
        sB += __shfl_xor_sync(0xffffffffu, sB, 2);
        const float iA = 1.f / sA, iB = 1.f / sB;
        #pragma unroll
        for (int nt = 0; nt < 8; nt++) {
            lac[mt][nt][0] *= iA; lac[mt][nt][1] *= iA;
            lac[mt][nt][2] *= iB; lac[mt][nt][3] *= iB;
        }
    }

    float oac[2][4][4];
    #pragma unroll
    for (int mt = 0; mt < 2; mt++)
        #pragma unroll
        for (int nt = 0; nt < 4; nt++)
            #pragma unroll
            for (int r = 0; r < 4; r++) oac[mt][nt][r] = 0.f;

    {
        const uint32_t vBase = vB + (hw * 32 * SV) * 2;
        #pragma unroll
        for (int kt = 0; kt < 4; kt++) {
            unsigned bfv[4][2];
            #pragma unroll
            for (int nt = 0; nt < 4; nt++) ldsm2(bfv[nt], vBase + (nt * 8 * SV + kt * 16) * 2);
            #pragma unroll
            for (int mt = 0; mt < 2; mt++) {
                unsigned pa[4];
                pa[0] = pack_bf2(lac[mt][2 * kt][0],     lac[mt][2 * kt][1]);
                pa[1] = pack_bf2(lac[mt][2 * kt][2],     lac[mt][2 * kt][3]);
                pa[2] = pack_bf2(lac[mt][2 * kt + 1][0], lac[mt][2 * kt + 1][1]);
                pa[3] = pack_bf2(lac[mt][2 * kt + 1][2], lac[mt][2 * kt + 1][3]);
                #pragma unroll
                for (int nt = 0; nt < 4; nt++) mma_bf16(oac[mt][nt], pa, bfv[nt]);
            }
        }
    }

    uint2 bfo[2][8];
    #pragma unroll
    for (int nt = 0; nt < 2; nt++)
        #pragma unroll
        for (int ks = 0; ks < 8; ks++)
            bfo[nt][ks] = wop[(nt * 8 + ks) * 32];

    #pragma unroll
    for (int mt = 0; mt < 2; mt++) {
        #pragma unroll
        for (int nt = 0; nt < 4; nt++) {
            const int r0 = mh * 32 + mt * 16 + g;
            const int c0 = hw * 32 + nt * 8 + 2 * s;
            *(unsigned*)(oS + r0 * SH + c0)       = pack_bf2(oac[mt][nt][0], oac[mt][nt][1]);
            *(unsigned*)(oS + (r0 + 8) * SH + c0) = pack_bf2(oac[mt][nt][2], oac[mt][nt][3]);
        }
    }
    __syncthreads();

    float2 xr[4][2][2];
    #pragma unroll
    for (int mt = 0; mt < 4; mt++) {
        #pragma unroll
        for (int nt = 0; nt < 2; nt++) {
            const int c = warp * 16 + nt * 8 + 2 * s;
            const int r0 = mt * 16 + g, r1 = r0 + 8;
            if (r0 < 49)
                xr[mt][nt][0] = *(const float2*)(x + ((size_t)b * 3136 + w * 49 + r0) * CD + c);
            if (r1 < 49)
                xr[mt][nt][1] = *(const float2*)(x + ((size_t)b * 3136 + w * 49 + r1) * CD + c);
        }
    }

    float fac[4][2][4];
    #pragma unroll
    for (int mt = 0; mt < 4; mt++)
        #pragma unroll
        for (int nt = 0; nt < 2; nt++)
            #pragma unroll
            for (int r = 0; r < 4; r++) fac[mt][nt][r] = 0.f;

    #pragma unroll
    for (int ks = 0; ks < 8; ks++) {
        #pragma unroll
        for (int mt = 0; mt < 4; mt++) {
            unsigned afr[4];
            ldsm4(afr, hA + (mt * 16 * SH + ks * 16) * 2);
            #pragma unroll
            for (int nt = 0; nt < 2; nt++) mma_bf16_u2(fac[mt][nt], afr, bfo[nt][ks]);
        }
    }

    #pragma unroll
    for (int mt = 0; mt < 4; mt++) {
        #pragma unroll
        for (int nt = 0; nt < 2; nt++) {
            const int c = warp * 16 + nt * 8 + 2 * s;
            const float bo0 = bo[c], bo1 = bo[c + 1];
            const int r0 = mt * 16 + g, r1 = r0 + 8;
            if (r0 < 49) {
                size_t p = ((size_t)b * 3136 + w * 49 + r0) * CD + c;
                float2 o;
                o.x = fac[mt][nt][0] + bo0 + xr[mt][nt][0].x;
                o.y = fac[mt][nt][1] + bo1 + xr[mt][nt][0].y;
                *(float2*)(g_y + p) = o;
            }
            if (r1 < 49) {
                size_t p = ((size_t)b * 3136 + w * 49 + r1) * CD + c;
                float2 o;
                o.x = fac[mt][nt][2] + bo0 + xr[mt][nt][1].x;
                o.y = fac[mt][nt][3] + bo1 + xr[mt][nt][1].y;
                *(float2*)(g_y + p) = o;
            }
        }
    }
}

// ---------------- K2: fused LN2 + MLP + residual (pipelined GEMM2 weights + residual prefetch) ----------------
__global__ void __launch_bounds__(256, 2) mlp_kernel(const float* __restrict__ g2,
                                                     const float* __restrict__ be2,
                                                     const float* __restrict__ b1,
                                                     const float* __restrict__ b2,
                                                     float* __restrict__ out) {
    extern __shared__ char smraw[];
    __nv_bfloat16* mS = (__nv_bfloat16*)smraw;                   // 64 x SH   (17408 B)
    __nv_bfloat16* hS = (__nv_bfloat16*)(smraw + 17408);         // 64 x SH2  (66560 B)

    const int t0 = blockIdx.x * 64;
    const int warp = threadIdx.x >> 5, lane = threadIdx.x & 31;
    const int wm = warp >> 2, wn = warp & 3;          // 2x4 warp grid

    // ---- LN2 into mS, batched gather preload
    {
        const float4 gm = *(const float4*)(g2 + lane * 4);
        const float4 bt = *(const float4*)(be2 + lane * 4);
        float4 vv[8];
        #pragma unroll
        for (int it = 0; it < 8; it++) {
            const int r = warp + it * 8;
            vv[it] = *(const float4*)(g_y + ((size_t)(t0 + r)) * CD + lane * 4);
        }
        #pragma unroll
        for (int it = 0; it < 8; it++) {
            const int r = warp + it * 8;
            float4 v = vv[it];
            float sum = v.x + v.y + v.z + v.w;
            float sq  = v.x * v.x + v.y * v.y + v.z * v.z + v.w * v.w;
            #pragma unroll
            for (int o = 16; o; o >>= 1) {
                sum += __shfl_xor_sync(0xffffffffu, sum, o);
                sq  += __shfl_xor_sync(0xffffffffu, sq, o);
            }
            const float mu = sum * (1.f / 128.f);
            const float inv = rsqrtf(sq * (1.f / 128.f) - mu * mu + 1e-5f);
            uint2 o2;
            o2.x = pack_bf2((v.x - mu) * inv * gm.x + bt.x, (v.y - mu) * inv * gm.y + bt.y);
            o2.y = pack_bf2((v.z - mu) * inv * gm.z + bt.z, (v.w - mu) * inv * gm.w + bt.w);
            *(uint2*)(mS + r * SH + lane * 4) = o2;
        }
    }
    __syncthreads();

    const int g = lane >> 2, s = lane & 3;
    const uint32_t mA = smemA_base(mS, SH,  lane) + (wm * 32 * SH)  * 2;
    const uint32_t hA = smemA_base(hS, SH2, lane) + (wm * 32 * SH2) * 2;
    const uint2* w1p = g_w1F + lane;
    const uint2* w2p = g_w2F + lane;

    // ---- GEMM1 over full N=512, 4 sub-chunks per warp, NO intermediate syncs
    #pragma unroll
    for (int sc = 0; sc < 4; sc++) {
        const int ntb = sc * 16 + wn * 4;              // global ntile base (of 64)
        uint2 bf[4][8];
        #pragma unroll
        for (int nt = 0; nt < 4; nt++)
            #pragma unroll
            for (int ks = 0; ks < 8; ks++)
                bf[nt][ks] = w1p[((ntb + nt) * 8 + ks) * 32];

        float acc[2][4][4];
        #pragma unroll
        for (int mt = 0; mt < 2; mt++)
            #pragma unroll
            for (int nt = 0; nt < 4; nt++)
                #pragma unroll
                for (int r = 0; r < 4; r++) acc[mt][nt][r] = 0.f;

        #pragma unroll
        for (int ks = 0; ks < 8; ks++) {
            #pragma unroll
            for (int mt = 0; mt < 2; mt++) {
                unsigned afr[4];
                ldsm4(afr, mA + (mt * 16 * SH + ks * 16) * 2);
                #pragma unroll
                for (int nt = 0; nt < 4; nt++) mma_bf16_u2(acc[mt][nt], afr, bf[nt][ks]);
            }
        }

        // bias + fast GELU -> hS
        #pragma unroll
        for (int mt = 0; mt < 2; mt++) {
            #pragma unroll
            for (int nt = 0; nt < 4; nt++) {
                const int cg = (ntb + nt) * 8 + 2 * s;      // global hidden col
                const float bb0 = b1[cg], bb1 = b1[cg + 1];
                const int r0 = wm * 32 + mt * 16 + g;
                *(unsigned*)(hS + r0 * SH2 + cg) =
                    pack_bf2(gelu_fast(acc[mt][nt][0] + bb0), gelu_fast(acc[mt][nt][1] + bb1));
                *(unsigned*)(hS + (r0 + 8) * SH2 + cg) =
                    pack_bf2(gelu_fast(acc[mt][nt][2] + bb0), gelu_fast(acc[mt][nt][3] + bb1));
            }
        }
    }

    // ---- prefetch GEMM2 kb=0 weights BEFORE the barrier (hides L2 latency under barrier drain)
    uint2 cf[2][4][8];     // double-buffered GEMM2 weight fragments
    #pragma unroll
    for (int nt = 0; nt < 4; nt++)
        #pragma unroll
        for (int ks = 0; ks < 8; ks++)
            cf[0][nt][ks] = w2p[(wn * 4 + nt) * 1024 + ks * 32];

    __syncthreads();   // the ONLY inter-phase barrier

    // ---- GEMM2: M=64, N=128 (warp 32x32), K=512, weights software-pipelined across kb
    float fac[2][4][4];
    #pragma unroll
    for (int mt = 0; mt < 2; mt++)
        #pragma unroll
        for (int nt = 0; nt < 4; nt++)
            #pragma unroll
            for (int r = 0; r < 4; r++) fac[mt][nt][r] = 0.f;

    float2 yr[2][4][2];    // residual prefetch (filled during last kb)
    #pragma unroll
    for (int kb = 0; kb < 4; kb++) {
        const int cur = kb & 1;
        if (kb < 3) {      // prefetch next kb's weights (overlaps this kb's MMAs)
            #pragma unroll
            for (int nt = 0; nt < 4; nt++)
                #pragma unroll
                for (int ks = 0; ks < 8; ks++)
                    cf[cur ^ 1][nt][ks] = w2p[(wn * 4 + nt) * 1024 + ((kb + 1) * 8 + ks) * 32];
        } else {           // prefetch residual y block (overlaps last kb's MMAs)
            #pragma unroll
            for (int mt = 0; mt < 2; mt++)
                #pragma unroll
                for (int nt = 0; nt < 4; nt++) {
                    const int c = wn * 32 + nt * 8 + 2 * s;
                    const int r0 = wm * 32 + mt * 16 + g;
                    yr[mt][nt][0] = *(const float2*)(g_y + ((size_t)(t0 + r0)) * CD + c);
                    yr[mt][nt][1] = *(const float2*)(g_y + ((size_t)(t0 + r0 + 8)) * CD + c);
                }
        }
        #pragma unroll
        for (int ks = 0; ks < 8; ks++) {
            const int kk = kb * 8 + ks;
            #pragma unroll
            for (int mt = 0; mt < 2; mt++) {
                unsigned afr[4];
                ldsm4(afr, hA + (mt * 16 * SH2 + kk * 16) * 2);
                #pragma unroll
                for (int nt = 0; nt < 4; nt++) mma_bf16_u2(fac[mt][nt], afr, cf[cur][nt][ks]);
            }
        }
    }

    // epilogue: + b2 + residual (prefetched) -> out
    #pragma unroll
    for (int mt = 0; mt < 2; mt++) {
        #pragma unroll
        for (int nt = 0; nt < 4; nt++) {
            const int c = wn * 32 + nt * 8 + 2 * s;
            const float bb0 = b2[c], bb1 = b2[c + 1];
            const int r0 = wm * 32 + mt * 16 + g;
            size_t p0 = ((size_t)(t0 + r0)) * CD + c;
            size_t p1 = ((size_t)(t0 + r0 + 8)) * CD + c;
            float2 o0, o1;
            o0.x = fac[mt][nt][0] + bb0 + yr[mt][nt][0].x;
            o0.y = fac[mt][nt][1] + bb1 + yr[mt][nt][0].y;
            o1.x = fac[mt][nt][2] + bb0 + yr[mt][nt][1].x;
            o1.y = fac[mt][nt][3] + bb1 + yr[mt][nt][1].y;
            *(float2*)(out + p0) = o0;
            *(float2*)(out + p1) = o1;
        }
    }
}

// ---------------- launch ----------------
extern "C" void kernel_launch(void* const* d_in, const int* in_sizes, int n_in,
                              void* d_out, int out_size) {
    const float* x   = (const float*)d_in[0];
    const float* wq  = (const float*)d_in[1];
    const float* bq  = (const float*)d_in[2];
    const float* wk  = (const float*)d_in[3];
    const float* bk  = (const float*)d_in[4];
    const float* wv  = (const float*)d_in[5];
    const float* bv  = (const float*)d_in[6];
    const float* wo  = (const float*)d_in[7];
    const float* bo  = (const float*)d_in[8];
    const float* rel = (const float*)d_in[9];
    const float* g1  = (const float*)d_in[10];
    const float* be1 = (const float*)d_in[11];
    const float* g2  = (const float*)d_in[12];
    const float* be2 = (const float*)d_in[13];
    const float* w1  = (const float*)d_in[14];
    const float* b1  = (const float*)d_in[15];
    const float* w2  = (const float*)d_in[16];
    const float* b2  = (const float*)d_in[17];
    float* out = (float*)d_out;

    cudaFuncSetAttribute(attn_kernel, cudaFuncAttributeMaxDynamicSharedMemorySize, 70656);
    cudaFuncSetAttribute(mlp_kernel,  cudaFuncAttributeMaxDynamicSharedMemorySize, 83968);

    pack_weights<<<192, 256>>>(wq, wk, wv, wo, w1, w2);
    build_bm<<<1024, 256>>>(rel);
    attn_kernel<<<4096, 256, 70656>>>(x, g1, be1, bq, bk, bv, bo);
    mlp_kernel<<<3136, 256, 83968>>>(g2, be2, b1, b2, out);
}

// round 14
// speedup vs baseline: 1.2695x; 1.0124x over previous
#include <cuda_runtime.h>
#include <cuda_bf16.h>
#include <math.h>
#include <stdint.h>

#define HEADS 4
#define CD    128
#define TOK   200704          // B * 3136
#define SH    136             // smem stride (bf16) for 128-wide tiles
#define SH2   520             // smem stride (bf16) for 512-wide hidden
#define SV    72              // smem stride (bf16) for vT (64-wide)

// ---------------- scratch ----------------
__device__ float  g_y[(size_t)TOK * CD];          // x + attn_out
__device__ uint2  g_wqkvF[48 * 8 * 32];
__device__ uint2  g_woF  [16 * 8 * 32];
__device__ uint2  g_w1F  [64 * 8 * 32];
__device__ uint2  g_w2F  [16 * 32 * 32];
__device__ float4 g_bm4[64 * HEADS * 4 * 8 * 32];

// ---------------- helpers ----------------
__device__ __forceinline__ void mma_bf16(float d[4], const unsigned a[4], const unsigned b[2]) {
    asm volatile("mma.sync.aligned.m16n8k16.row.col.f32.bf16.bf16.f32 "
                 "{%0,%1,%2,%3}, {%4,%5,%6,%7}, {%8,%9}, {%0,%1,%2,%3};\n"
                 : "+f"(d[0]), "+f"(d[1]), "+f"(d[2]), "+f"(d[3])
                 : "r"(a[0]), "r"(a[1]), "r"(a[2]), "r"(a[3]), "r"(b[0]), "r"(b[1]));
}
__device__ __forceinline__ void mma_bf16_u2(float d[4], const unsigned a[4], uint2 b) {
    asm volatile("mma.sync.aligned.m16n8k16.row.col.f32.bf16.bf16.f32 "
                 "{%0,%1,%2,%3}, {%4,%5,%6,%7}, {%8,%9}, {%0,%1,%2,%3};\n"
                 : "+f"(d[0]), "+f"(d[1]), "+f"(d[2]), "+f"(d[3])
                 : "r"(a[0]), "r"(a[1]), "r"(a[2]), "r"(a[3]), "r"(b.x), "r"(b.y));
}
__device__ __forceinline__ void ldsm4(unsigned a[4], uint32_t addr) {
    asm volatile("ldmatrix.sync.aligned.m8n8.x4.shared.b16 {%0,%1,%2,%3}, [%4];"
                 : "=r"(a[0]), "=r"(a[1]), "=r"(a[2]), "=r"(a[3]) : "r"(addr));
}
__device__ __forceinline__ void ldsm2(unsigned b[2], uint32_t addr) {
    asm volatile("ldmatrix.sync.aligned.m8n8.x2.shared.b16 {%0,%1}, [%2];"
                 : "=r"(b[0]), "=r"(b[1]) : "r"(addr));
}
__device__ __forceinline__ uint32_t smemA_base(const void* p, int stride, int lane) {
    return (uint32_t)__cvta_generic_to_shared(p) +
           (uint32_t)(((lane & 15) * stride + ((lane >> 4) << 3)) * 2);
}
__device__ __forceinline__ uint32_t smemB_base(const void* p, int stride, int lane) {
    return (uint32_t)__cvta_generic_to_shared(p) +
           (uint32_t)(((lane & 7) * stride + (lane & 8)) * 2);
}
__device__ __forceinline__ unsigned pack_bf2(float lo, float hi) {
    unsigned r;
    asm("cvt.rn.bf16x2.f32 %0, %1, %2;" : "=r"(r) : "f"(hi), "f"(lo));
    return r;
}
__device__ __forceinline__ float gelu_fast(float v) {
    float u2 = v * v;
    float u = v * (1.5957691216f + 0.1426926424f * u2);
    float e = __expf(u);
    return __fdividef(v * e, e + 1.f);
}
__device__ __forceinline__ int region_of(int p) { return p < 49 ? 0 : (p < 53 ? 1 : 2); }

// ---------------- K0a: pack weights into fragment layout ----------------
__global__ void pack_weights(const float* __restrict__ wq, const float* __restrict__ wk,
                             const float* __restrict__ wv, const float* __restrict__ wo,
                             const float* __restrict__ w1, const float* __restrict__ w2) {
    int i = blockIdx.x * blockDim.x + threadIdx.x;   // 49152 threads
    if (i < 12288) {
        int lane = i & 31, kt = (i >> 5) & 7, nt = i >> 8;
        int n = nt * 8 + (lane >> 2), kk = kt * 16 + 2 * (lane & 3);
        const float* wsrc = (n < 128) ? wq : (n < 256) ? wk : wv;
        int nn = n & 127;
        uint2 v;
        v.x = pack_bf2(wsrc[kk * 128 + nn],       wsrc[(kk + 1) * 128 + nn]);
        v.y = pack_bf2(wsrc[(kk + 8) * 128 + nn], wsrc[(kk + 9) * 128 + nn]);
        g_wqkvF[i] = v;
    } else if (i < 16384) {
        int j = i - 12288;
        int lane = j & 31, kt = (j >> 5) & 7, nt = j >> 8;
        int n = nt * 8 + (lane >> 2), kk = kt * 16 + 2 * (lane & 3);
        uint2 v;
        v.x = pack_bf2(wo[kk * 128 + n],       wo[(kk + 1) * 128 + n]);
        v.y = pack_bf2(wo[(kk + 8) * 128 + n], wo[(kk + 9) * 128 + n]);
        g_woF[j] = v;
    } else if (i < 32768) {
        int j = i - 16384;
        int lane = j & 31, kt = (j >> 5) & 7, nt = j >> 8;
        int n = nt * 8 + (lane >> 2), kk = kt * 16 + 2 * (lane & 3);
        uint2 v;
        v.x = pack_bf2(w1[kk * 512 + n],       w1[(kk + 1) * 512 + n]);
        v.y = pack_bf2(w1[(kk + 8) * 512 + n], w1[(kk + 9) * 512 + n]);
        g_w1F[j] = v;
    } else {
        int j = i - 32768;
        int lane = j & 31, kt = (j >> 5) & 31, nt = j >> 10;
        int n = nt * 8 + (lane >> 2), kk = kt * 16 + 2 * (lane & 3);
        uint2 v;
        v.x = pack_bf2(w2[kk * 128 + n],       w2[(kk + 1) * 128 + n]);
        v.y = pack_bf2(w2[(kk + 8) * 128 + n], w2[(kk + 9) * 128 + n]);
        g_w2F[j] = v;
    }
}

// ---------------- K0b: bias+mask table ----------------
__device__ __forceinline__ float bm_val(const float* __restrict__ rel, int w, int h, int q, int k) {
    if (q >= 49 || k >= 49) return -1e30f;
    int qi = q / 7, qj = q % 7, ki = k / 7, kj = k % 7;
    int r0 = (ki - qi) % 13; if (r0 < 0) r0 += 13;
    int r1 = (kj - qj) % 13; if (r1 < 0) r1 += 13;
    float bias = rel[(r0 * 13 + r1) * HEADS + h];
    int wr = w >> 3, wc = w & 7;
    int idq = region_of(wr * 7 + qi) * 3 + region_of(wc * 7 + qj);
    int idk = region_of(wr * 7 + ki) * 3 + region_of(wc * 7 + kj);
    return bias + (idq == idk ? 0.f : -100.f);
}
__global__ void build_bm(const float* __restrict__ rel) {
    int i = blockIdx.x * blockDim.x + threadIdx.x;   // 262144
    int lane = i & 31, nt = (i >> 5) & 7, mtile = (i >> 8) & 3, h = (i >> 10) & 3, w = i >> 12;
    int g = lane >> 2, s = lane & 3;
    int rA = mtile * 16 + g, rB = rA + 8, cc = nt * 8 + 2 * s;
    float4 v;
    v.x = bm_val(rel, w, h, rA, cc);
    v.y = bm_val(rel, w, h, rA, cc + 1);
    v.z = bm_val(rel, w, h, rB, cc);
    v.w = bm_val(rel, w, h, rB, cc + 1);
    g_bm4[i] = v;
}

// ---------------- K1: fused LN1 + window attention + O-proj + residual (R13) ----------------
__global__ void __launch_bounds__(256, 2) attn_kernel(const float* __restrict__ x,
                                                      const float* __restrict__ gam,
                                                      const float* __restrict__ bet,
                                                      const float* __restrict__ bq,
                                                      const float* __restrict__ bk,
                                                      const float* __restrict__ bv,
                                                      const float* __restrict__ bo) {
    extern __shared__ char smraw[];
    __nv_bfloat16* hS = (__nv_bfloat16*)smraw;
    __nv_bfloat16* qS = (__nv_bfloat16*)(smraw + 17408);
    __nv_bfloat16* kS = (__nv_bfloat16*)(smraw + 34816);
    __nv_bfloat16* vT = (__nv_bfloat16*)(smraw + 52224);
    __nv_bfloat16* oS = hS;

    const int win = blockIdx.x, b = win >> 6, w = win & 63;
    const int wr = w >> 3, wc = w & 7;
    const int warp = threadIdx.x >> 5, lane = threadIdx.x & 31;
    const int g = lane >> 2, s = lane & 3;

    const uint2* wqp = g_wqkvF + warp * 6 * 8 * 32 + lane;
    const uint2* wop = g_woF   + warp * 2 * 8 * 32 + lane;

    uint2 bfr[3][8];
    #pragma unroll
    for (int nt = 0; nt < 3; nt++)
        #pragma unroll
        for (int ks = 0; ks < 8; ks++)
            bfr[nt][ks] = wqp[(nt * 8 + ks) * 32];

    {
        const float4 gm = *(const float4*)(gam + lane * 4);
        const float4 bt = *(const float4*)(bet + lane * 4);
        float4 vv[8];
        #pragma unroll
        for (int it = 0; it < 8; it++) {
            const int n = warp + it * 8;
            if (n < 49) {
                const int i = n / 7, j = n % 7;
                const int sh = (wr * 7 + i + 3) % 56, sw = (wc * 7 + j + 3) % 56;
                vv[it] = *(const float4*)(x + ((size_t)b * 3136 + sh * 56 + sw) * CD + lane * 4);
            }
        }
        #pragma unroll
        for (int it = 0; it < 8; it++) {
            const int n = warp + it * 8;
            __nv_bfloat16* dst = hS + n * SH;
            if (n >= 49) {
                ((unsigned*)dst)[lane]      = 0u;
                ((unsigned*)dst)[lane + 32] = 0u;
                continue;
            }
            float4 v = vv[it];
            float sum = v.x + v.y + v.z + v.w;
            float sq  = v.x * v.x + v.y * v.y + v.z * v.z + v.w * v.w;
            #pragma unroll
            for (int o = 16; o; o >>= 1) {
                sum += __shfl_xor_sync(0xffffffffu, sum, o);
                sq  += __shfl_xor_sync(0xffffffffu, sq, o);
            }
            const float mu = sum * (1.f / 128.f);
            const float inv = rsqrtf(sq * (1.f / 128.f) - mu * mu + 1e-5f);
            uint2 o2;
            o2.x = pack_bf2((v.x - mu) * inv * gm.x + bt.x, (v.y - mu) * inv * gm.y + bt.y);
            o2.y = pack_bf2((v.z - mu) * inv * gm.z + bt.z, (v.w - mu) * inv * gm.w + bt.w);
            *(uint2*)(dst + lane * 4) = o2;
        }
    }
    __syncthreads();

    const uint32_t hA = smemA_base(hS, SH, lane);
    const uint32_t qA = smemA_base(qS, SH, lane);
    const uint32_t kB = smemB_base(kS, SH, lane);
    const uint32_t vB = smemB_base(vT, SV, lane);

    const float invs = 0.17677669529663687f;  // 1/sqrt(32)
    #pragma unroll
    for (int pass = 0; pass < 2; pass++) {
        float acc[4][3][4];
        #pragma unroll
        for (int mt = 0; mt < 4; mt++)
            #pragma unroll
            for (int nt = 0; nt < 3; nt++)
                #pragma unroll
                for (int r = 0; r < 4; r++) acc[mt][nt][r] = 0.f;
        #pragma unroll
        for (int ks = 0; ks < 8; ks++) {
            #pragma unroll
            for (int mt = 0; mt < 4; mt++) {
                unsigned afr[4];
                ldsm4(afr, hA + (mt * 16 * SH + ks * 16) * 2);
                #pragma unroll
                for (int nt = 0; nt < 3; nt++) mma_bf16_u2(acc[mt][nt], afr, bfr[nt][ks]);
            }
        }
        if (pass == 0) {
            #pragma unroll
            for (int nt = 0; nt < 3; nt++)
                #pragma unroll
                for (int ks = 0; ks < 8; ks++)
                    bfr[nt][ks] = wqp[((3 + nt) * 8 + ks) * 32];
        }
        #pragma unroll
        for (int mt = 0; mt < 4; mt++) {
            #pragma unroll
            for (int nt = 0; nt < 3; nt++) {
                const int nb = warp * 48 + (pass * 3 + nt) * 8;
                const int c0 = nb + 2 * s;
                const int r0 = mt * 16 + g;
                float v0 = acc[mt][nt][0], v1 = acc[mt][nt][1], v2 = acc[mt][nt][2], v3 = acc[mt][nt][3];
                if (nb < 128) {
                    float b0 = bq[c0], b1 = bq[c0 + 1];
                    *(unsigned*)(qS + r0 * SH + c0)       = pack_bf2((v0 + b0) * invs, (v1 + b1) * invs);
                    *(unsigned*)(qS + (r0 + 8) * SH + c0) = pack_bf2((v2 + b0) * invs, (v3 + b1) * invs);
                } else if (nb < 256) {
                    int cc = c0 - 128;
                    float b0 = bk[cc], b1 = bk[cc + 1];
                    *(unsigned*)(kS + r0 * SH + cc)       = pack_bf2(v0 + b0, v1 + b1);
                    *(unsigned*)(kS + (r0 + 8) * SH + cc) = pack_bf2(v2 + b0, v3 + b1);
                } else {
                    int d0 = c0 - 256;
                    float b0 = bv[d0], b1 = bv[d0 + 1];
                    vT[d0 * SV + r0]           = __float2bfloat16_rn(v0 + b0);
                    vT[(d0 + 1) * SV + r0]     = __float2bfloat16_rn(v1 + b1);
                    vT[d0 * SV + r0 + 8]       = __float2bfloat16_rn(v2 + b0);
                    vT[(d0 + 1) * SV + r0 + 8] = __float2bfloat16_rn(v3 + b1);
                }
            }
        }
    }
    __syncthreads();

    const int hw = warp >> 1, mh = warp & 1;
    const float4* bmp = g_bm4 + (((size_t)(w * HEADS + hw) * 4 + mh * 2) * 8) * 32 + lane;

    float4 bmf0[8];
    #pragma unroll
    for (int nt = 0; nt < 8; nt++) bmf0[nt] = bmp[nt * 32];

    float lac[2][8][4];
    #pragma unroll
    for (int mt = 0; mt < 2; mt++)
        #pragma unroll
        for (int nt = 0; nt < 8; nt++)
            #pragma unroll
            for (int r = 0; r < 4; r++) lac[mt][nt][r] = 0.f;

    {
        const uint32_t qBase = qA + (mh * 32 * SH + hw * 32) * 2;
        const uint32_t kBase = kB + (hw * 32) * 2;
        #pragma unroll
        for (int ks = 0; ks < 2; ks++) {
            unsigned bfk[8][2];
            #pragma unroll
            for (int nt = 0; nt < 8; nt++) ldsm2(bfk[nt], kBase + (nt * 8 * SH + ks * 16) * 2);
            #pragma unroll
            for (int mt = 0; mt < 2; mt++) {
                unsigned afr[4];
                ldsm4(afr, qBase + (mt * 16 * SH + ks * 16) * 2);
                #pragma unroll
                for (int nt = 0; nt < 8; nt++) mma_bf16(lac[mt][nt], afr, bfk[nt]);
            }
        }
    }

    float4 bmf1[8];
    #pragma unroll
    for (int mt = 0; mt < 2; mt++) {
        float mA = -1e30f, mB = -1e30f;
        #pragma unroll
        for (int nt = 0; nt < 8; nt++) {
            float4 bv4 = (mt == 0) ? bmf0[nt] : bmf1[nt];
            lac[mt][nt][0] += bv4.x;
            lac[mt][nt][1] += bv4.y;
            lac[mt][nt][2] += bv4.z;
            lac[mt][nt][3] += bv4.w;
            mA = fmaxf(mA, fmaxf(lac[mt][nt][0], lac[mt][nt][1]));
            mB = fmaxf(mB, fmaxf(lac[mt][nt][2], lac[mt][nt][3]));
        }
        if (mt == 0) {
            #pragma unroll
            for (int nt = 0; nt < 8; nt++) bmf1[nt] = bmp[(8 + nt) * 32];
        }
        mA = fmaxf(mA, __shfl_xor_sync(0xffffffffu, mA, 1));
        mA = fmaxf(mA, __shfl_xor_sync(0xffffffffu, mA, 2));
        mB = fmaxf(mB, __shfl_xor_sync(0xffffffffu, mB, 1));
        mB = fmaxf(mB, __shfl_xor_sync(0xffffffffu, mB, 2));
        float sA = 0.f, sB = 0.f;
        #pragma unroll
        for (int nt = 0; nt < 8; nt++) {
            lac[mt][nt][0] = __expf(lac[mt][nt][0] - mA);
            lac[mt][nt][1] = __expf(lac[mt][nt][1] - mA);
            lac[mt][nt][2] = __expf(lac[mt][nt][2] - mB);
            lac[mt][nt][3] = __expf(lac[mt][nt][3] - mB);
            sA += lac[mt][nt][0] + lac[mt][nt][1];
            sB += lac[mt][nt][2] + lac[mt][nt][3];
        }
        sA += __shfl_xor_sync(0xffffffffu, sA, 1);
        sA += __shfl_xor_sync(0xffffffffu, sA, 2);
        sB += __shfl_xor_sync(0xffffffffu, sB, 1);
        sB += __shfl_xor_sync(0xffffffffu, sB, 2);
        const float iA = 1.f / sA, iB = 1.f / sB;
        #pragma unroll
        for (int nt = 0; nt < 8; nt++) {
            lac[mt][nt][0] *= iA; lac[mt][nt][1] *= iA;
            lac[mt][nt][2] *= iB; lac[mt][nt][3] *= iB;
        }
    }

    float oac[2][4][4];
    #pragma unroll
    for (int mt = 0; mt < 2; mt++)
        #pragma unroll
        for (int nt = 0; nt < 4; nt++)
            #pragma unroll
            for (int r = 0; r < 4; r++) oac[mt][nt][r] = 0.f;

    {
        const uint32_t vBase = vB + (hw * 32 * SV) * 2;
        #pragma unroll
        for (int kt = 0; kt < 4; kt++) {
            unsigned bfv[4][2];
            #pragma unroll
            for (int nt = 0; nt < 4; nt++) ldsm2(bfv[nt], vBase + (nt * 8 * SV + kt * 16) * 2);
            #pragma unroll
            for (int mt = 0; mt < 2; mt++) {
                unsigned pa[4];
                pa[0] = pack_bf2(lac[mt][2 * kt][0],     lac[mt][2 * kt][1]);
                pa[1] = pack_bf2(lac[mt][2 * kt][2],     lac[mt][2 * kt][3]);
                pa[2] = pack_bf2(lac[mt][2 * kt + 1][0], lac[mt][2 * kt + 1][1]);
                pa[3] = pack_bf2(lac[mt][2 * kt + 1][2], lac[mt][2 * kt + 1][3]);
                #pragma unroll
                for (int nt = 0; nt < 4; nt++) mma_bf16(oac[mt][nt], pa, bfv[nt]);
            }
        }
    }

    uint2 bfo[2][8];
    #pragma unroll
    for (int nt = 0; nt < 2; nt++)
        #pragma unroll
        for (int ks = 0; ks < 8; ks++)
            bfo[nt][ks] = wop[(nt * 8 + ks) * 32];

    #pragma unroll
    for (int mt = 0; mt < 2; mt++) {
        #pragma unroll
        for (int nt = 0; nt < 4; nt++) {
            const int r0 = mh * 32 + mt * 16 + g;
            const int c0 = hw * 32 + nt * 8 + 2 * s;
            *(unsigned*)(oS + r0 * SH + c0)       = pack_bf2(oac[mt][nt][0], oac[mt][nt][1]);
            *(unsigned*)(oS + (r0 + 8) * SH + c0) = pack_bf2(oac[mt][nt][2], oac[mt][nt][3]);
        }
    }
    __syncthreads();

    float2 xr[4][2][2];
    #pragma unroll
    for (int mt = 0; mt < 4; mt++) {
        #pragma unroll
        for (int nt = 0; nt < 2; nt++) {
            const int c = warp * 16 + nt * 8 + 2 * s;
            const int r0 = mt * 16 + g, r1 = r0 + 8;
            if (r0 < 49)
                xr[mt][nt][0] = *(const float2*)(x + ((size_t)b * 3136 + w * 49 + r0) * CD + c);
            if (r1 < 49)
                xr[mt][nt][1] = *(const float2*)(x + ((size_t)b * 3136 + w * 49 + r1) * CD + c);
        }
    }

    float fac[4][2][4];
    #pragma unroll
    for (int mt = 0; mt < 4; mt++)
        #pragma unroll
        for (int nt = 0; nt < 2; nt++)
            #pragma unroll
            for (int r = 0; r < 4; r++) fac[mt][nt][r] = 0.f;

    #pragma unroll
    for (int ks = 0; ks < 8; ks++) {
        #pragma unroll
        for (int mt = 0; mt < 4; mt++) {
            unsigned afr[4];
            ldsm4(afr, hA + (mt * 16 * SH + ks * 16) * 2);
            #pragma unroll
            for (int nt = 0; nt < 2; nt++) mma_bf16_u2(fac[mt][nt], afr, bfo[nt][ks]);
        }
    }

    #pragma unroll
    for (int mt = 0; mt < 4; mt++) {
        #pragma unroll
        for (int nt = 0; nt < 2; nt++) {
            const int c = warp * 16 + nt * 8 + 2 * s;
            const float bo0 = bo[c], bo1 = bo[c + 1];
            const int r0 = mt * 16 + g, r1 = r0 + 8;
            if (r0 < 49) {
                size_t p = ((size_t)b * 3136 + w * 49 + r0) * CD + c;
                float2 o;
                o.x = fac[mt][nt][0] + bo0 + xr[mt][nt][0].x;
                o.y = fac[mt][nt][1] + bo1 + xr[mt][nt][0].y;
                *(float2*)(g_y + p) = o;
            }
            if (r1 < 49) {
                size_t p = ((size_t)b * 3136 + w * 49 + r1) * CD + c;
                float2 o;
                o.x = fac[mt][nt][2] + bo0 + xr[mt][nt][1].x;
                o.y = fac[mt][nt][3] + bo1 + xr[mt][nt][1].y;
                *(float2*)(g_y + p) = o;
            }
        }
    }
}

// ---------------- K2: fused LN2 + MLP + residual (fully pipelined weights) ----------------
__global__ void __launch_bounds__(256, 2) mlp_kernel(const float* __restrict__ g2,
                                                     const float* __restrict__ be2,
                                                     const float* __restrict__ b1,
                                                     const float* __restrict__ b2,
                                                     float* __restrict__ out) {
    extern __shared__ char smraw[];
    __nv_bfloat16* mS = (__nv_bfloat16*)smraw;                   // 64 x SH   (17408 B)
    __nv_bfloat16* hS = (__nv_bfloat16*)(smraw + 17408);         // 64 x SH2  (66560 B)

    const int t0 = blockIdx.x * 64;
    const int warp = threadIdx.x >> 5, lane = threadIdx.x & 31;
    const int wm = warp >> 2, wn = warp & 3;          // 2x4 warp grid

    const uint2* w1p = g_w1F + lane;
    const uint2* w2p = g_w2F + lane;

    // prefetch GEMM1 sc=0 weights (overlaps LN2 gather)
    uint2 bf[4][8];
    #pragma unroll
    for (int nt = 0; nt < 4; nt++)
        #pragma unroll
        for (int ks = 0; ks < 8; ks++)
            bf[nt][ks] = w1p[((wn * 4 + nt) * 8 + ks) * 32];

    // ---- LN2 into mS, batched gather preload
    {
        const float4 gm = *(const float4*)(g2 + lane * 4);
        const float4 bt = *(const float4*)(be2 + lane * 4);
        float4 vv[8];
        #pragma unroll
        for (int it = 0; it < 8; it++) {
            const int r = warp + it * 8;
            vv[it] = *(const float4*)(g_y + ((size_t)(t0 + r)) * CD + lane * 4);
        }
        #pragma unroll
        for (int it = 0; it < 8; it++) {
            const int r = warp + it * 8;
            float4 v = vv[it];
            float sum = v.x + v.y + v.z + v.w;
            float sq  = v.x * v.x + v.y * v.y + v.z * v.z + v.w * v.w;
            #pragma unroll
            for (int o = 16; o; o >>= 1) {
                sum += __shfl_xor_sync(0xffffffffu, sum, o);
                sq  += __shfl_xor_sync(0xffffffffu, sq, o);
            }
            const float mu = sum * (1.f / 128.f);
            const float inv = rsqrtf(sq * (1.f / 128.f) - mu * mu + 1e-5f);
            uint2 o2;
            o2.x = pack_bf2((v.x - mu) * inv * gm.x + bt.x, (v.y - mu) * inv * gm.y + bt.y);
            o2.y = pack_bf2((v.z - mu) * inv * gm.z + bt.z, (v.w - mu) * inv * gm.w + bt.w);
            *(uint2*)(mS + r * SH + lane * 4) = o2;
        }
    }
    __syncthreads();

    const int g = lane >> 2, s = lane & 3;
    const uint32_t mA = smemA_base(mS, SH,  lane) + (wm * 32 * SH)  * 2;
    const uint32_t hA = smemA_base(hS, SH2, lane) + (wm * 32 * SH2) * 2;

    // ---- GEMM1 over full N=512, 4 sub-chunks per warp; sc+1 weights prefetched
    //      between each sub-chunk's MMA loop and its GELU epilogue.
    #pragma unroll
    for (int sc = 0; sc < 4; sc++) {
        const int ntb = sc * 16 + wn * 4;              // global ntile base (of 64)

        float acc[2][4][4];
        #pragma unroll
        for (int mt = 0; mt < 2; mt++)
            #pragma unroll
            for (int nt = 0; nt < 4; nt++)
                #pragma unroll
                for (int r = 0; r < 4; r++) acc[mt][nt][r] = 0.f;

        #pragma unroll
        for (int ks = 0; ks < 8; ks++) {
            #pragma unroll
            for (int mt = 0; mt < 2; mt++) {
                unsigned afr[4];
                ldsm4(afr, mA + (mt * 16 * SH + ks * 16) * 2);
                #pragma unroll
                for (int nt = 0; nt < 4; nt++) mma_bf16_u2(acc[mt][nt], afr, bf[nt][ks]);
            }
        }

        // prefetch next sub-chunk's weights (overlaps the GELU epilogue below)
        if (sc < 3) {
            const int ntb2 = (sc + 1) * 16 + wn * 4;
            #pragma unroll
            for (int nt = 0; nt < 4; nt++)
                #pragma unroll
                for (int ks = 0; ks < 8; ks++)
                    bf[nt][ks] = w1p[((ntb2 + nt) * 8 + ks) * 32];
        }

        // bias + fast GELU -> hS
        #pragma unroll
        for (int mt = 0; mt < 2; mt++) {
            #pragma unroll
            for (int nt = 0; nt < 4; nt++) {
                const int cg = (ntb + nt) * 8 + 2 * s;      // global hidden col
                const float bb0 = b1[cg], bb1 = b1[cg + 1];
                const int r0 = wm * 32 + mt * 16 + g;
                *(unsigned*)(hS + r0 * SH2 + cg) =
                    pack_bf2(gelu_fast(acc[mt][nt][0] + bb0), gelu_fast(acc[mt][nt][1] + bb1));
                *(unsigned*)(hS + (r0 + 8) * SH2 + cg) =
                    pack_bf2(gelu_fast(acc[mt][nt][2] + bb0), gelu_fast(acc[mt][nt][3] + bb1));
            }
        }
    }

    // ---- prefetch GEMM2 kb=0 weights BEFORE the barrier
    uint2 cf[2][4][8];     // double-buffered GEMM2 weight fragments
    #pragma unroll
    for (int nt = 0; nt < 4; nt++)
        #pragma unroll
        for (int ks = 0; ks < 8; ks++)
            cf[0][nt][ks] = w2p[(wn * 4 + nt) * 1024 + ks * 32];

    __syncthreads();   // the ONLY inter-phase barrier

    // ---- GEMM2: M=64, N=128 (warp 32x32), K=512, weights software-pipelined across kb
    float fac[2][4][4];
    #pragma unroll
    for (int mt = 0; mt < 2; mt++)
        #pragma unroll
        for (int nt = 0; nt < 4; nt++)
            #pragma unroll
            for (int r = 0; r < 4; r++) fac[mt][nt][r] = 0.f;

    float2 yr[2][4][2];    // residual prefetch (filled during last kb)
    #pragma unroll
    for (int kb = 0; kb < 4; kb++) {
        const int cur = kb & 1;
        if (kb < 3) {
            #pragma unroll
            for (int nt = 0; nt < 4; nt++)
                #pragma unroll
                for (int ks = 0; ks < 8; ks++)
                    cf[cur ^ 1][nt][ks] = w2p[(wn * 4 + nt) * 1024 + ((kb + 1) * 8 + ks) * 32];
        } else {
            #pragma unroll
            for (int mt = 0; mt < 2; mt++)
                #pragma unroll
                for (int nt = 0; nt < 4; nt++) {
                    const int c = wn * 32 + nt * 8 + 2 * s;
                    const int r0 = wm * 32 + mt * 16 + g;
                    yr[mt][nt][0] = *(const float2*)(g_y + ((size_t)(t0 + r0)) * CD + c);
                    yr[mt][nt][1] = *(const float2*)(g_y + ((size_t)(t0 + r0 + 8)) * CD + c);
                }
        }
        #pragma unroll
        for (int ks = 0; ks < 8; ks++) {
            const int kk = kb * 8 + ks;
            #pragma unroll
            for (int mt = 0; mt < 2; mt++) {
                unsigned afr[4];
                ldsm4(afr, hA + (mt * 16 * SH2 + kk * 16) * 2);
                #pragma unroll
                for (int nt = 0; nt < 4; nt++) mma_bf16_u2(fac[mt][nt], afr, cf[cur][nt][ks]);
            }
        }
    }

    // epilogue: + b2 + residual (prefetched) -> out
    #pragma unroll
    for (int mt = 0; mt < 2; mt++) {
        #pragma unroll
        for (int nt = 0; nt < 4; nt++) {
            const int c = wn * 32 + nt * 8 + 2 * s;
            const float bb0 = b2[c], bb1 = b2[c + 1];
            const int r0 = wm * 32 + mt * 16 + g;
            size_t p0 = ((size_t)(t0 + r0)) * CD + c;
            size_t p1 = ((size_t)(t0 + r0 + 8)) * CD + c;
            float2 o0, o1;
            o0.x = fac[mt][nt][0] + bb0 + yr[mt][nt][0].x;
            o0.y = fac[mt][nt][1] + bb1 + yr[mt][nt][0].y;
            o1.x = fac[mt][nt][2] + bb0 + yr[mt][nt][1].x;
            o1.y = fac[mt][nt][3] + bb1 + yr[mt][nt][1].y;
            *(float2*)(out + p0) = o0;
            *(float2*)(out + p1) = o1;
        }
    }
}

// ---------------- launch ----------------
extern "C" void kernel_launch(void* const* d_in, const int* in_sizes, int n_in,
                              void* d_out, int out_size) {
    const float* x   = (const float*)d_in[0];
    const float* wq  = (const float*)d_in[1];
    const float* bq  = (const float*)d_in[2];
    const float* wk  = (const float*)d_in[3];
    const float* bk  = (const float*)d_in[4];
    const float* wv  = (const float*)d_in[5];
    const float* bv  = (const float*)d_in[6];
    const float* wo  = (const float*)d_in[7];
    const float* bo  = (const float*)d_in[8];
    const float* rel = (const float*)d_in[9];
    const float* g1  = (const float*)d_in[10];
    const float* be1 = (const float*)d_in[11];
    const float* g2  = (const float*)d_in[12];
    const float* be2 = (const float*)d_in[13];
    const float* w1  = (const float*)d_in[14];
    const float* b1  = (const float*)d_in[15];
    const float* w2  = (const float*)d_in[16];
    const float* b2  = (const float*)d_in[17];
    float* out = (float*)d_out;

    cudaFuncSetAttribute(attn_kernel, cudaFuncAttributeMaxDynamicSharedMemorySize, 70656);
    cudaFuncSetAttribute(mlp_kernel,  cudaFuncAttributeMaxDynamicSharedMemorySize, 83968);

    pack_weights<<<192, 256>>>(wq, wk, wv, wo, w1, w2);
    build_bm<<<1024, 256>>>(rel);
    attn_kernel<<<4096, 256, 70656>>>(x, g1, be1, bq, bk, bv, bo);
    mlp_kernel<<<3136, 256, 83968>>>(g2, be2, b1, b2, out);
}

// round 15
// speedup vs baseline: 1.2746x; 1.0040x over previous
#include <cuda_runtime.h>
#include <cuda_bf16.h>
#include <math.h>
#include <stdint.h>

#define HEADS 4
#define CD    128
#define TOK   200704          // B * 3136
#define SH    136             // smem stride (bf16) for 128-wide tiles
#define SH2   520             // smem stride (bf16) for 512-wide hidden
#define SV    72              // smem stride (bf16) for vT (64-wide)

// ---------------- scratch ----------------
__device__ float  g_y[(size_t)TOK * CD];          // x + attn_out
__device__ uint2  g_wqkvF[48 * 8 * 32];
__device__ uint2  g_woF  [16 * 8 * 32];
__device__ uint2  g_w1F  [64 * 8 * 32];
__device__ uint2  g_w2F  [16 * 32 * 32];
__device__ float4 g_bm4[64 * HEADS * 4 * 8 * 32];

// ---------------- helpers ----------------
__device__ __forceinline__ void mma_bf16(float d[4], const unsigned a[4], const unsigned b[2]) {
    asm volatile("mma.sync.aligned.m16n8k16.row.col.f32.bf16.bf16.f32 "
                 "{%0,%1,%2,%3}, {%4,%5,%6,%7}, {%8,%9}, {%0,%1,%2,%3};\n"
                 : "+f"(d[0]), "+f"(d[1]), "+f"(d[2]), "+f"(d[3])
                 : "r"(a[0]), "r"(a[1]), "r"(a[2]), "r"(a[3]), "r"(b[0]), "r"(b[1]));
}
__device__ __forceinline__ void mma_bf16_u2(float d[4], const unsigned a[4], uint2 b) {
    asm volatile("mma.sync.aligned.m16n8k16.row.col.f32.bf16.bf16.f32 "
                 "{%0,%1,%2,%3}, {%4,%5,%6,%7}, {%8,%9}, {%0,%1,%2,%3};\n"
                 : "+f"(d[0]), "+f"(d[1]), "+f"(d[2]), "+f"(d[3])
                 : "r"(a[0]), "r"(a[1]), "r"(a[2]), "r"(a[3]), "r"(b.x), "r"(b.y));
}
__device__ __forceinline__ void ldsm4(unsigned a[4], uint32_t addr) {
    asm volatile("ldmatrix.sync.aligned.m8n8.x4.shared.b16 {%0,%1,%2,%3}, [%4];"
                 : "=r"(a[0]), "=r"(a[1]), "=r"(a[2]), "=r"(a[3]) : "r"(addr));
}
__device__ __forceinline__ uint32_t smemA_base(const void* p, int stride, int lane) {
    return (uint32_t)__cvta_generic_to_shared(p) +
           (uint32_t)(((lane & 15) * stride + ((lane >> 4) << 3)) * 2);
}
// x4 B-pair base: lanes 0-7 -> n0..7@k0, 8-15 -> n0..7@k8, 16-23 -> n8..15@k0, 24-31 -> n8..15@k8
__device__ __forceinline__ uint32_t smemB4_base(const void* p, int stride, int lane) {
    return (uint32_t)__cvta_generic_to_shared(p) +
           (uint32_t)((((lane & 7) + ((lane >> 4) << 3)) * stride + (lane & 8)) * 2);
}
__device__ __forceinline__ unsigned pack_bf2(float lo, float hi) {
    unsigned r;
    asm("cvt.rn.bf16x2.f32 %0, %1, %2;" : "=r"(r) : "f"(hi), "f"(lo));
    return r;
}
__device__ __forceinline__ float gelu_fast(float v) {
    float u2 = v * v;
    float u = v * (1.5957691216f + 0.1426926424f * u2);
    float e = __expf(u);
    return __fdividef(v * e, e + 1.f);
}
__device__ __forceinline__ int region_of(int p) { return p < 49 ? 0 : (p < 53 ? 1 : 2); }

// ---------------- K0a: pack weights into fragment layout ----------------
__global__ void pack_weights(const float* __restrict__ wq, const float* __restrict__ wk,
                             const float* __restrict__ wv, const float* __restrict__ wo,
                             const float* __restrict__ w1, const float* __restrict__ w2) {
    int i = blockIdx.x * blockDim.x + threadIdx.x;   // 49152 threads
    if (i < 12288) {
        int lane = i & 31, kt = (i >> 5) & 7, nt = i >> 8;
        int n = nt * 8 + (lane >> 2), kk = kt * 16 + 2 * (lane & 3);
        const float* wsrc = (n < 128) ? wq : (n < 256) ? wk : wv;
        int nn = n & 127;
        uint2 v;
        v.x = pack_bf2(wsrc[kk * 128 + nn],       wsrc[(kk + 1) * 128 + nn]);
        v.y = pack_bf2(wsrc[(kk + 8) * 128 + nn], wsrc[(kk + 9) * 128 + nn]);
        g_wqkvF[i] = v;
    } else if (i < 16384) {
        int j = i - 12288;
        int lane = j & 31, kt = (j >> 5) & 7, nt = j >> 8;
        int n = nt * 8 + (lane >> 2), kk = kt * 16 + 2 * (lane & 3);
        uint2 v;
        v.x = pack_bf2(wo[kk * 128 + n],       wo[(kk + 1) * 128 + n]);
        v.y = pack_bf2(wo[(kk + 8) * 128 + n], wo[(kk + 9) * 128 + n]);
        g_woF[j] = v;
    } else if (i < 32768) {
        int j = i - 16384;
        int lane = j & 31, kt = (j >> 5) & 7, nt = j >> 8;
        int n = nt * 8 + (lane >> 2), kk = kt * 16 + 2 * (lane & 3);
        uint2 v;
        v.x = pack_bf2(w1[kk * 512 + n],       w1[(kk + 1) * 512 + n]);
        v.y = pack_bf2(w1[(kk + 8) * 512 + n], w1[(kk + 9) * 512 + n]);
        g_w1F[j] = v;
    } else {
        int j = i - 32768;
        int lane = j & 31, kt = (j >> 5) & 31, nt = j >> 10;
        int n = nt * 8 + (lane >> 2), kk = kt * 16 + 2 * (lane & 3);
        uint2 v;
        v.x = pack_bf2(w2[kk * 128 + n],       w2[(kk + 1) * 128 + n]);
        v.y = pack_bf2(w2[(kk + 8) * 128 + n], w2[(kk + 9) * 128 + n]);
        g_w2F[j] = v;
    }
}

// ---------------- K0b: bias+mask table ----------------
__device__ __forceinline__ float bm_val(const float* __restrict__ rel, int w, int h, int q, int k) {
    if (q >= 49 || k >= 49) return -1e30f;
    int qi = q / 7, qj = q % 7, ki = k / 7, kj = k % 7;
    int r0 = (ki - qi) % 13; if (r0 < 0) r0 += 13;
    int r1 = (kj - qj) % 13; if (r1 < 0) r1 += 13;
    float bias = rel[(r0 * 13 + r1) * HEADS + h];
    int wr = w >> 3, wc = w & 7;
    int idq = region_of(wr * 7 + qi) * 3 + region_of(wc * 7 + qj);
    int idk = region_of(wr * 7 + ki) * 3 + region_of(wc * 7 + kj);
    return bias + (idq == idk ? 0.f : -100.f);
}
__global__ void build_bm(const float* __restrict__ rel) {
    int i = blockIdx.x * blockDim.x + threadIdx.x;   // 262144
    int lane = i & 31, nt = (i >> 5) & 7, mtile = (i >> 8) & 3, h = (i >> 10) & 3, w = i >> 12;
    int g = lane >> 2, s = lane & 3;
    int rA = mtile * 16 + g, rB = rA + 8, cc = nt * 8 + 2 * s;
    float4 v;
    v.x = bm_val(rel, w, h, rA, cc);
    v.y = bm_val(rel, w, h, rA, cc + 1);
    v.z = bm_val(rel, w, h, rB, cc);
    v.w = bm_val(rel, w, h, rB, cc + 1);
    g_bm4[i] = v;
}

// ---------------- K1: fused LN1 + window attention + O-proj + residual ----------------
__global__ void __launch_bounds__(256, 2) attn_kernel(const float* __restrict__ x,
                                                      const float* __restrict__ gam,
                                                      const float* __restrict__ bet,
                                                      const float* __restrict__ bq,
                                                      const float* __restrict__ bk,
                                                      const float* __restrict__ bv,
                                                      const float* __restrict__ bo) {
    extern __shared__ char smraw[];
    __nv_bfloat16* hS = (__nv_bfloat16*)smraw;
    __nv_bfloat16* qS = (__nv_bfloat16*)(smraw + 17408);
    __nv_bfloat16* kS = (__nv_bfloat16*)(smraw + 34816);
    __nv_bfloat16* vT = (__nv_bfloat16*)(smraw + 52224);
    __nv_bfloat16* oS = hS;

    const int win = blockIdx.x, b = win >> 6, w = win & 63;
    const int wr = w >> 3, wc = w & 7;
    const int warp = threadIdx.x >> 5, lane = threadIdx.x & 31;
    const int g = lane >> 2, s = lane & 3;

    const uint2* wqp = g_wqkvF + warp * 6 * 8 * 32 + lane;
    const uint2* wop = g_woF   + warp * 2 * 8 * 32 + lane;

    uint2 bfr[3][8];
    #pragma unroll
    for (int nt = 0; nt < 3; nt++)
        #pragma unroll
        for (int ks = 0; ks < 8; ks++)
            bfr[nt][ks] = wqp[(nt * 8 + ks) * 32];

    {
        const float4 gm = *(const float4*)(gam + lane * 4);
        const float4 bt = *(const float4*)(bet + lane * 4);
        float4 vv[8];
        #pragma unroll
        for (int it = 0; it < 8; it++) {
            const int n = warp + it * 8;
            if (n < 49) {
                const int i = n / 7, j = n % 7;
                const int sh = (wr * 7 + i + 3) % 56, sw = (wc * 7 + j + 3) % 56;
                vv[it] = *(const float4*)(x + ((size_t)b * 3136 + sh * 56 + sw) * CD + lane * 4);
            }
        }
        #pragma unroll
        for (int it = 0; it < 8; it++) {
            const int n = warp + it * 8;
            __nv_bfloat16* dst = hS + n * SH;
            if (n >= 49) {
                ((unsigned*)dst)[lane]      = 0u;
                ((unsigned*)dst)[lane + 32] = 0u;
                continue;
            }
            float4 v = vv[it];
            float sum = v.x + v.y + v.z + v.w;
            float sq  = v.x * v.x + v.y * v.y + v.z * v.z + v.w * v.w;
            #pragma unroll
            for (int o = 16; o; o >>= 1) {
                sum += __shfl_xor_sync(0xffffffffu, sum, o);
                sq  += __shfl_xor_sync(0xffffffffu, sq, o);
            }
            const float mu = sum * (1.f / 128.f);
            const float inv = rsqrtf(sq * (1.f / 128.f) - mu * mu + 1e-5f);
            uint2 o2;
            o2.x = pack_bf2((v.x - mu) * inv * gm.x + bt.x, (v.y - mu) * inv * gm.y + bt.y);
            o2.y = pack_bf2((v.z - mu) * inv * gm.z + bt.z, (v.w - mu) * inv * gm.w + bt.w);
            *(uint2*)(dst + lane * 4) = o2;
        }
    }
    __syncthreads();

    const uint32_t hA  = smemA_base(hS, SH, lane);
    const uint32_t qA  = smemA_base(qS, SH, lane);
    const uint32_t kB4 = smemB4_base(kS, SH, lane);
    const uint32_t vB4 = smemB4_base(vT, SV, lane);

    const float invs = 0.17677669529663687f;  // 1/sqrt(32)
    #pragma unroll
    for (int pass = 0; pass < 2; pass++) {
        float acc[4][3][4];
        #pragma unroll
        for (int mt = 0; mt < 4; mt++)
            #pragma unroll
            for (int nt = 0; nt < 3; nt++)
                #pragma unroll
                for (int r = 0; r < 4; r++) acc[mt][nt][r] = 0.f;
        #pragma unroll
        for (int ks = 0; ks < 8; ks++) {
            #pragma unroll
            for (int mt = 0; mt < 4; mt++) {
                unsigned afr[4];
                ldsm4(afr, hA + (mt * 16 * SH + ks * 16) * 2);
                #pragma unroll
                for (int nt = 0; nt < 3; nt++) mma_bf16_u2(acc[mt][nt], afr, bfr[nt][ks]);
            }
        }
        if (pass == 0) {
            #pragma unroll
            for (int nt = 0; nt < 3; nt++)
                #pragma unroll
                for (int ks = 0; ks < 8; ks++)
                    bfr[nt][ks] = wqp[((3 + nt) * 8 + ks) * 32];
        }
        #pragma unroll
        for (int mt = 0; mt < 4; mt++) {
            #pragma unroll
            for (int nt = 0; nt < 3; nt++) {
                const int nb = warp * 48 + (pass * 3 + nt) * 8;
                const int c0 = nb + 2 * s;
                const int r0 = mt * 16 + g;
                float v0 = acc[mt][nt][0], v1 = acc[mt][nt][1], v2 = acc[mt][nt][2], v3 = acc[mt][nt][3];
                if (nb < 128) {
                    float b0 = bq[c0], b1 = bq[c0 + 1];
                    *(unsigned*)(qS + r0 * SH + c0)       = pack_bf2((v0 + b0) * invs, (v1 + b1) * invs);
                    *(unsigned*)(qS + (r0 + 8) * SH + c0) = pack_bf2((v2 + b0) * invs, (v3 + b1) * invs);
                } else if (nb < 256) {
                    int cc = c0 - 128;
                    float b0 = bk[cc], b1 = bk[cc + 1];
                    *(unsigned*)(kS + r0 * SH + cc)       = pack_bf2(v0 + b0, v1 + b1);
                    *(unsigned*)(kS + (r0 + 8) * SH + cc) = pack_bf2(v2 + b0, v3 + b1);
                } else {
                    int d0 = c0 - 256;
                    float b0 = bv[d0], b1 = bv[d0 + 1];
                    vT[d0 * SV + r0]           = __float2bfloat16_rn(v0 + b0);
                    vT[(d0 + 1) * SV + r0]     = __float2bfloat16_rn(v1 + b1);
                    vT[d0 * SV + r0 + 8]       = __float2bfloat16_rn(v2 + b0);
                    vT[(d0 + 1) * SV + r0 + 8] = __float2bfloat16_rn(v3 + b1);
                }
            }
        }
    }
    __syncthreads();

    const int hw = warp >> 1, mh = warp & 1;
    const float4* bmp = g_bm4 + (((size_t)(w * HEADS + hw) * 4 + mh * 2) * 8) * 32 + lane;

    float4 bmf0[8];
    #pragma unroll
    for (int nt = 0; nt < 8; nt++) bmf0[nt] = bmp[nt * 32];

    float lac[2][8][4];
    #pragma unroll
    for (int mt = 0; mt < 2; mt++)
        #pragma unroll
        for (int nt = 0; nt < 8; nt++)
            #pragma unroll
            for (int r = 0; r < 4; r++) lac[mt][nt][r] = 0.f;

    {
        const uint32_t qBase = qA + (mh * 32 * SH + hw * 32) * 2;
        const uint32_t kBase = kB4 + (hw * 32) * 2;
        #pragma unroll
        for (int ks = 0; ks < 2; ks++) {
            unsigned bfk[8][2];
            #pragma unroll
            for (int ntp = 0; ntp < 4; ntp++) {   // paired x4 B loads (2 n-tiles each)
                unsigned t4[4];
                ldsm4(t4, kBase + (ntp * 16 * SH + ks * 16) * 2);
                bfk[2 * ntp][0]     = t4[0];
                bfk[2 * ntp][1]     = t4[1];
                bfk[2 * ntp + 1][0] = t4[2];
                bfk[2 * ntp + 1][1] = t4[3];
            }
            #pragma unroll
            for (int mt = 0; mt < 2; mt++) {
                unsigned afr[4];
                ldsm4(afr, qBase + (mt * 16 * SH + ks * 16) * 2);
                #pragma unroll
                for (int nt = 0; nt < 8; nt++) mma_bf16(lac[mt][nt], afr, bfk[nt]);
            }
        }
    }

    float4 bmf1[8];
    #pragma unroll
    for (int mt = 0; mt < 2; mt++) {
        float mA = -1e30f, mB = -1e30f;
        #pragma unroll
        for (int nt = 0; nt < 8; nt++) {
            float4 bv4 = (mt == 0) ? bmf0[nt] : bmf1[nt];
            lac[mt][nt][0] += bv4.x;
            lac[mt][nt][1] += bv4.y;
            lac[mt][nt][2] += bv4.z;
            lac[mt][nt][3] += bv4.w;
            mA = fmaxf(mA, fmaxf(lac[mt][nt][0], lac[mt][nt][1]));
            mB = fmaxf(mB, fmaxf(lac[mt][nt][2], lac[mt][nt][3]));
        }
        if (mt == 0) {
            #pragma unroll
            for (int nt = 0; nt < 8; nt++) bmf1[nt] = bmp[(8 + nt) * 32];
        }
        mA = fmaxf(mA, __shfl_xor_sync(0xffffffffu, mA, 1));
        mA = fmaxf(mA, __shfl_xor_sync(0xffffffffu, mA, 2));
        mB = fmaxf(mB, __shfl_xor_sync(0xffffffffu, mB, 1));
        mB = fmaxf(mB, __shfl_xor_sync(0xffffffffu, mB, 2));
        float sA = 0.f, sB = 0.f;
        #pragma unroll
        for (int nt = 0; nt < 8; nt++) {
            lac[mt][nt][0] = __expf(lac[mt][nt][0] - mA);
            lac[mt][nt][1] = __expf(lac[mt][nt][1] - mA);
            lac[mt][nt][2] = __expf(lac[mt][nt][2] - mB);
            lac[mt][nt][3] = __expf(lac[mt][nt][3] - mB);
            sA += lac[mt][nt][0] + lac[mt][nt][1];
            sB += lac[mt][nt][2] + lac[mt][nt][3];
        }
        sA += __shfl_xor_sync(0xffffffffu, sA, 1);
        sA += __shfl_xor_sync(0xffffffffu, sA, 2);
        sB += __shfl_xor_sync(0xffffffffu, sB, 1);
        sB += __shfl_xor_sync(0xffffffffu, sB, 2);
        const float iA = 1.f / sA, iB = 1.f / sB;
        #pragma unroll
        for (int nt = 0; nt < 8; nt++) {
            lac[mt][nt][0] *= iA; lac[mt][nt][1] *= iA;
            lac[mt][nt][2] *= iB; lac[mt][nt][3] *= iB;
        }
    }

    float oac[2][4][4];
    #pragma unroll
    for (int mt = 0; mt < 2; mt++)
        #pragma unroll
        for (int nt = 0; nt < 4; nt++)
            #pragma unroll
            for (int r = 0; r < 4; r++) oac[mt][nt][r] = 0.f;

    {
        const uint32_t vBase = vB4 + (hw * 32 * SV) * 2;
        #pragma unroll
        for (int kt = 0; kt < 4; kt++) {
            unsigned bfv[4][2];
            #pragma unroll
            for (int ntp = 0; ntp < 2; ntp++) {   // paired x4 B loads
                unsigned t4[4];
                ldsm4(t4, vBase + (ntp * 16 * SV + kt * 16) * 2);
                bfv[2 * ntp][0]     = t4[0];
                bfv[2 * ntp][1]     = t4[1];
                bfv[2 * ntp + 1][0] = t4[2];
                bfv[2 * ntp + 1][1] = t4[3];
            }
            #pragma unroll
            for (int mt = 0; mt < 2; mt++) {
                unsigned pa[4];
                pa[0] = pack_bf2(lac[mt][2 * kt][0],     lac[mt][2 * kt][1]);
                pa[1] = pack_bf2(lac[mt][2 * kt][2],     lac[mt][2 * kt][3]);
                pa[2] = pack_bf2(lac[mt][2 * kt + 1][0], lac[mt][2 * kt + 1][1]);
                pa[3] = pack_bf2(lac[mt][2 * kt + 1][2], lac[mt][2 * kt + 1][3]);
                #pragma unroll
                for (int nt = 0; nt < 4; nt++) mma_bf16(oac[mt][nt], pa, bfv[nt]);
            }
        }
    }

    uint2 bfo[2][8];
    #pragma unroll
    for (int nt = 0; nt < 2; nt++)
        #pragma unroll
        for (int ks = 0; ks < 8; ks++)
            bfo[nt][ks] = wop[(nt * 8 + ks) * 32];

    #pragma unroll
    for (int mt = 0; mt < 2; mt++) {
        #pragma unroll
        for (int nt = 0; nt < 4; nt++) {
            const int r0 = mh * 32 + mt * 16 + g;
            const int c0 = hw * 32 + nt * 8 + 2 * s;
            *(unsigned*)(oS + r0 * SH + c0)       = pack_bf2(oac[mt][nt][0], oac[mt][nt][1]);
            *(unsigned*)(oS + (r0 + 8) * SH + c0) = pack_bf2(oac[mt][nt][2], oac[mt][nt][3]);
        }
    }
    __syncthreads();

    float2 xr[4][2][2];
    #pragma unroll
    for (int mt = 0; mt < 4; mt++) {
        #pragma unroll
        for (int nt = 0; nt < 2; nt++) {
            const int c = warp * 16 + nt * 8 + 2 * s;
            const int r0 = mt * 16 + g, r1 = r0 + 8;
            if (r0 < 49)
                xr[mt][nt][0] = *(const float2*)(x + ((size_t)b * 3136 + w * 49 + r0) * CD + c);
            if (r1 < 49)
                xr[mt][nt][1] = *(const float2*)(x + ((size_t)b * 3136 + w * 49 + r1) * CD + c);
        }
    }

    float fac[4][2][4];
    #pragma unroll
    for (int mt = 0; mt < 4; mt++)
        #pragma unroll
        for (int nt = 0; nt < 2; nt++)
            #pragma unroll
            for (int r = 0; r < 4; r++) fac[mt][nt][r] = 0.f;

    #pragma unroll
    for (int ks = 0; ks < 8; ks++) {
        #pragma unroll
        for (int mt = 0; mt < 4; mt++) {
            unsigned afr[4];
            ldsm4(afr, hA + (mt * 16 * SH + ks * 16) * 2);
            #pragma unroll
            for (int nt = 0; nt < 2; nt++) mma_bf16_u2(fac[mt][nt], afr, bfo[nt][ks]);
        }
    }

    #pragma unroll
    for (int mt = 0; mt < 4; mt++) {
        #pragma unroll
        for (int nt = 0; nt < 2; nt++) {
            const int c = warp * 16 + nt * 8 + 2 * s;
            const float bo0 = bo[c], bo1 = bo[c + 1];
            const int r0 = mt * 16 + g, r1 = r0 + 8;
            if (r0 < 49) {
                size_t p = ((size_t)b * 3136 + w * 49 + r0) * CD + c;
                float2 o;
                o.x = fac[mt][nt][0] + bo0 + xr[mt][nt][0].x;
                o.y = fac[mt][nt][1] + bo1 + xr[mt][nt][0].y;
                *(float2*)(g_y + p) = o;
            }
            if (r1 < 49) {
                size_t p = ((size_t)b * 3136 + w * 49 + r1) * CD + c;
                float2 o;
                o.x = fac[mt][nt][2] + bo0 + xr[mt][nt][1].x;
                o.y = fac[mt][nt][3] + bo1 + xr[mt][nt][1].y;
                *(float2*)(g_y + p) = o;
            }
        }
    }
}

// ---------------- K2: fused LN2 + MLP + residual (R14, fully pipelined weights) ----------------
__global__ void __launch_bounds__(256, 2) mlp_kernel(const float* __restrict__ g2,
                                                     const float* __restrict__ be2,
                                                     const float* __restrict__ b1,
                                                     const float* __restrict__ b2,
                                                     float* __restrict__ out) {
    extern __shared__ char smraw[];
    __nv_bfloat16* mS = (__nv_bfloat16*)smraw;                   // 64 x SH   (17408 B)
    __nv_bfloat16* hS = (__nv_bfloat16*)(smraw + 17408);         // 64 x SH2  (66560 B)

    const int t0 = blockIdx.x * 64;
    const int warp = threadIdx.x >> 5, lane = threadIdx.x & 31;
    const int wm = warp >> 2, wn = warp & 3;          // 2x4 warp grid

    const uint2* w1p = g_w1F + lane;
    const uint2* w2p = g_w2F + lane;

    // prefetch GEMM1 sc=0 weights (overlaps LN2 gather)
    uint2 bf[4][8];
    #pragma unroll
    for (int nt = 0; nt < 4; nt++)
        #pragma unroll
        for (int ks = 0; ks < 8; ks++)
            bf[nt][ks] = w1p[((wn * 4 + nt) * 8 + ks) * 32];

    // ---- LN2 into mS, batched gather preload
    {
        const float4 gm = *(const float4*)(g2 + lane * 4);
        const float4 bt = *(const float4*)(be2 + lane * 4);
        float4 vv[8];
        #pragma unroll
        for (int it = 0; it < 8; it++) {
            const int r = warp + it * 8;
            vv[it] = *(const float4*)(g_y + ((size_t)(t0 + r)) * CD + lane * 4);
        }
        #pragma unroll
        for (int it = 0; it < 8; it++) {
            const int r = warp + it * 8;
            float4 v = vv[it];
            float sum = v.x + v.y + v.z + v.w;
            float sq  = v.x * v.x + v.y * v.y + v.z * v.z + v.w * v.w;
            #pragma unroll
            for (int o = 16; o; o >>= 1) {
                sum += __shfl_xor_sync(0xffffffffu, sum, o);
                sq  += __shfl_xor_sync(0xffffffffu, sq, o);
            }
            const float mu = sum * (1.f / 128.f);
            const float inv = rsqrtf(sq * (1.f / 128.f) - mu * mu + 1e-5f);
            uint2 o2;
            o2.x = pack_bf2((v.x - mu) * inv * gm.x + bt.x, (v.y - mu) * inv * gm.y + bt.y);
            o2.y = pack_bf2((v.z - mu) * inv * gm.z + bt.z, (v.w - mu) * inv * gm.w + bt.w);
            *(uint2*)(mS + r * SH + lane * 4) = o2;
        }
    }
    __syncthreads();

    const int g = lane >> 2, s = lane & 3;
    const uint32_t mA = smemA_base(mS, SH,  lane) + (wm * 32 * SH)  * 2;
    const uint32_t hA = smemA_base(hS, SH2, lane) + (wm * 32 * SH2) * 2;

    // ---- GEMM1 over full N=512, 4 sub-chunks per warp; sc+1 weights prefetched
    #pragma unroll
    for (int sc = 0; sc < 4; sc++) {
        const int ntb = sc * 16 + wn * 4;

        float acc[2][4][4];
        #pragma unroll
        for (int mt = 0; mt < 2; mt++)
            #pragma unroll
            for (int nt = 0; nt < 4; nt++)
                #pragma unroll
                for (int r = 0; r < 4; r++) acc[mt][nt][r] = 0.f;

        #pragma unroll
        for (int ks = 0; ks < 8; ks++) {
            #pragma unroll
            for (int mt = 0; mt < 2; mt++) {
                unsigned afr[4];
                ldsm4(afr, mA + (mt * 16 * SH + ks * 16) * 2);
                #pragma unroll
                for (int nt = 0; nt < 4; nt++) mma_bf16_u2(acc[mt][nt], afr, bf[nt][ks]);
            }
        }

        if (sc < 3) {
            const int ntb2 = (sc + 1) * 16 + wn * 4;
            #pragma unroll
            for (int nt = 0; nt < 4; nt++)
                #pragma unroll
                for (int ks = 0; ks < 8; ks++)
                    bf[nt][ks] = w1p[((ntb2 + nt) * 8 + ks) * 32];
        }

        #pragma unroll
        for (int mt = 0; mt < 2; mt++) {
            #pragma unroll
            for (int nt = 0; nt < 4; nt++) {
                const int cg = (ntb + nt) * 8 + 2 * s;
                const float bb0 = b1[cg], bb1 = b1[cg + 1];
                const int r0 = wm * 32 + mt * 16 + g;
                *(unsigned*)(hS + r0 * SH2 + cg) =
                    pack_bf2(gelu_fast(acc[mt][nt][0] + bb0), gelu_fast(acc[mt][nt][1] + bb1));
                *(unsigned*)(hS + (r0 + 8) * SH2 + cg) =
                    pack_bf2(gelu_fast(acc[mt][nt][2] + bb0), gelu_fast(acc[mt][nt][3] + bb1));
            }
        }
    }

    // ---- prefetch GEMM2 kb=0 weights BEFORE the barrier
    uint2 cf[2][4][8];
    #pragma unroll
    for (int nt = 0; nt < 4; nt++)
        #pragma unroll
        for (int ks = 0; ks < 8; ks++)
            cf[0][nt][ks] = w2p[(wn * 4 + nt) * 1024 + ks * 32];

    __syncthreads();

    // ---- GEMM2: M=64, N=128 (warp 32x32), K=512, weights pipelined across kb
    float fac[2][4][4];
    #pragma unroll
    for (int mt = 0; mt < 2; mt++)
        #pragma unroll
        for (int nt = 0; nt < 4; nt++)
            #pragma unroll
            for (int r = 0; r < 4; r++) fac[mt][nt][r] = 0.f;

    float2 yr[2][4][2];
    #pragma unroll
    for (int kb = 0; kb < 4; kb++) {
        const int cur = kb & 1;
        if (kb < 3) {
            #pragma unroll
            for (int nt = 0; nt < 4; nt++)
                #pragma unroll
                for (int ks = 0; ks < 8; ks++)
                    cf[cur ^ 1][nt][ks] = w2p[(wn * 4 + nt) * 1024 + ((kb + 1) * 8 + ks) * 32];
        } else {
            #pragma unroll
            for (int mt = 0; mt < 2; mt++)
                #pragma unroll
                for (int nt = 0; nt < 4; nt++) {
                    const int c = wn * 32 + nt * 8 + 2 * s;
                    const int r0 = wm * 32 + mt * 16 + g;
                    yr[mt][nt][0] = *(const float2*)(g_y + ((size_t)(t0 + r0)) * CD + c);
                    yr[mt][nt][1] = *(const float2*)(g_y + ((size_t)(t0 + r0 + 8)) * CD + c);
                }
        }
        #pragma unroll
        for (int ks = 0; ks < 8; ks++) {
            const int kk = kb * 8 + ks;
            #pragma unroll
            for (int mt = 0; mt < 2; mt++) {
                unsigned afr[4];
                ldsm4(afr, hA + (mt * 16 * SH2 + kk * 16) * 2);
                #pragma unroll
                for (int nt = 0; nt < 4; nt++) mma_bf16_u2(fac[mt][nt], afr, cf[cur][nt][ks]);
            }
        }
    }

    // epilogue: + b2 + residual (prefetched) -> out
    #pragma unroll
    for (int mt = 0; mt < 2; mt++) {
        #pragma unroll
        for (int nt = 0; nt < 4; nt++) {
            const int c = wn * 32 + nt * 8 + 2 * s;
            const float bb0 = b2[c], bb1 = b2[c + 1];
            const int r0 = wm * 32 + mt * 16 + g;
            size_t p0 = ((size_t)(t0 + r0)) * CD + c;
            size_t p1 = ((size_t)(t0 + r0 + 8)) * CD + c;
            float2 o0, o1;
            o0.x = fac[mt][nt][0] + bb0 + yr[mt][nt][0].x;
            o0.y = fac[mt][nt][1] + bb1 + yr[mt][nt][0].y;
            o1.x = fac[mt][nt][2] + bb0 + yr[mt][nt][1].x;
            o1.y = fac[mt][nt][3] + bb1 + yr[mt][nt][1].y;
            *(float2*)(out + p0) = o0;
            *(float2*)(out + p1) = o1;
        }
    }
}

// ---------------- launch ----------------
extern "C" void kernel_launch(void* const* d_in, const int* in_sizes, int n_in,
                              void* d_out, int out_size) {
    const float* x   = (const float*)d_in[0];
    const float* wq  = (const float*)d_in[1];
    const float* bq  = (const float*)d_in[2];
    const float* wk  = (const float*)d_in[3];
    const float* bk  = (const float*)d_in[4];
    const float* wv  = (const float*)d_in[5];
    const float* bv  = (const float*)d_in[6];
    const float* wo  = (const float*)d_in[7];
    const float* bo  = (const float*)d_in[8];
    const float* rel = (const float*)d_in[9];
    const float* g1  = (const float*)d_in[10];
    const float* be1 = (const float*)d_in[11];
    const float* g2  = (const float*)d_in[12];
    const float* be2 = (const float*)d_in[13];
    const float* w1  = (const float*)d_in[14];
    const float* b1  = (const float*)d_in[15];
    const float* w2  = (const float*)d_in[16];
    const float* b2  = (const float*)d_in[17];
    float* out = (float*)d_out;

    cudaFuncSetAttribute(attn_kernel, cudaFuncAttributeMaxDynamicSharedMemorySize, 70656);
    cudaFuncSetAttribute(mlp_kernel,  cudaFuncAttributeMaxDynamicSharedMemorySize, 83968);

    pack_weights<<<192, 256>>>(wq, wk, wv, wo, w1, w2);
    build_bm<<<1024, 256>>>(rel);
    attn_kernel<<<4096, 256, 70656>>>(x, g1, be1, bq, bk, bv, bo);
    mlp_kernel<<<3136, 256, 83968>>>(g2, be2, b1, b2, out);
}

// round 16
// speedup vs baseline: 1.2764x; 1.0014x over previous
#include <cuda_runtime.h>
#include <cuda_bf16.h>
#include <math.h>
#include <stdint.h>

#define HEADS 4
#define CD    128
#define TOK   200704          // B * 3136
#define SH    136             // smem stride (bf16) for 128-wide tiles
#define SH2   520             // smem stride (bf16) for 512-wide hidden
#define SV    72              // smem stride (bf16) for vT (64-wide)

// ---------------- scratch ----------------
__device__ float  g_y[(size_t)TOK * CD];          // x + attn_out
__device__ uint2  g_wqkvF[48 * 8 * 32];
__device__ uint2  g_woF  [16 * 8 * 32];
__device__ uint2  g_w1F  [64 * 8 * 32];
__device__ uint2  g_w2F  [16 * 32 * 32];
__device__ float4 g_bm4[64 * HEADS * 4 * 8 * 32];

// ---------------- helpers ----------------
__device__ __forceinline__ void mma_bf16(float d[4], const unsigned a[4], const unsigned b[2]) {
    asm volatile("mma.sync.aligned.m16n8k16.row.col.f32.bf16.bf16.f32 "
                 "{%0,%1,%2,%3}, {%4,%5,%6,%7}, {%8,%9}, {%0,%1,%2,%3};\n"
                 : "+f"(d[0]), "+f"(d[1]), "+f"(d[2]), "+f"(d[3])
                 : "r"(a[0]), "r"(a[1]), "r"(a[2]), "r"(a[3]), "r"(b[0]), "r"(b[1]));
}
__device__ __forceinline__ void mma_bf16_u2(float d[4], const unsigned a[4], uint2 b) {
    asm volatile("mma.sync.aligned.m16n8k16.row.col.f32.bf16.bf16.f32 "
                 "{%0,%1,%2,%3}, {%4,%5,%6,%7}, {%8,%9}, {%0,%1,%2,%3};\n"
                 : "+f"(d[0]), "+f"(d[1]), "+f"(d[2]), "+f"(d[3])
                 : "r"(a[0]), "r"(a[1]), "r"(a[2]), "r"(a[3]), "r"(b.x), "r"(b.y));
}
__device__ __forceinline__ void ldsm4(unsigned a[4], uint32_t addr) {
    asm volatile("ldmatrix.sync.aligned.m8n8.x4.shared.b16 {%0,%1,%2,%3}, [%4];"
                 : "=r"(a[0]), "=r"(a[1]), "=r"(a[2]), "=r"(a[3]) : "r"(addr));
}
__device__ __forceinline__ uint32_t smemA_base(const void* p, int stride, int lane) {
    return (uint32_t)__cvta_generic_to_shared(p) +
           (uint32_t)(((lane & 15) * stride + ((lane >> 4) << 3)) * 2);
}
// x4 B-pair base: lanes 0-7 -> n0..7@k0, 8-15 -> n0..7@k8, 16-23 -> n8..15@k0, 24-31 -> n8..15@k8
__device__ __forceinline__ uint32_t smemB4_base(const void* p, int stride, int lane) {
    return (uint32_t)__cvta_generic_to_shared(p) +
           (uint32_t)((((lane & 7) + ((lane >> 4) << 3)) * stride + (lane & 8)) * 2);
}
__device__ __forceinline__ unsigned pack_bf2(float lo, float hi) {
    unsigned r;
    asm("cvt.rn.bf16x2.f32 %0, %1, %2;" : "=r"(r) : "f"(hi), "f"(lo));
    return r;
}
__device__ __forceinline__ float gelu_fast(float v) {
    float u2 = v * v;
    float u = v * (1.5957691216f + 0.1426926424f * u2);
    float e = __expf(u);
    return __fdividef(v * e, e + 1.f);
}
__device__ __forceinline__ int region_of(int p) { return p < 49 ? 0 : (p < 53 ? 1 : 2); }

// ---------------- K0a: pack weights into fragment layout ----------------
__global__ void pack_weights(const float* __restrict__ wq, const float* __restrict__ wk,
                             const float* __restrict__ wv, const float* __restrict__ wo,
                             const float* __restrict__ w1, const float* __restrict__ w2) {
    int i = blockIdx.x * blockDim.x + threadIdx.x;   // 49152 threads
    if (i < 12288) {
        int lane = i & 31, kt = (i >> 5) & 7, nt = i >> 8;
        int n = nt * 8 + (lane >> 2), kk = kt * 16 + 2 * (lane & 3);
        const float* wsrc = (n < 128) ? wq : (n < 256) ? wk : wv;
        int nn = n & 127;
        uint2 v;
        v.x = pack_bf2(wsrc[kk * 128 + nn],       wsrc[(kk + 1) * 128 + nn]);
        v.y = pack_bf2(wsrc[(kk + 8) * 128 + nn], wsrc[(kk + 9) * 128 + nn]);
        g_wqkvF[i] = v;
    } else if (i < 16384) {
        int j = i - 12288;
        int lane = j & 31, kt = (j >> 5) & 7, nt = j >> 8;
        int n = nt * 8 + (lane >> 2), kk = kt * 16 + 2 * (lane & 3);
        uint2 v;
        v.x = pack_bf2(wo[kk * 128 + n],       wo[(kk + 1) * 128 + n]);
        v.y = pack_bf2(wo[(kk + 8) * 128 + n], wo[(kk + 9) * 128 + n]);
        g_woF[j] = v;
    } else if (i < 32768) {
        int j = i - 16384;
        int lane = j & 31, kt = (j >> 5) & 7, nt = j >> 8;
        int n = nt * 8 + (lane >> 2), kk = kt * 16 + 2 * (lane & 3);
        uint2 v;
        v.x = pack_bf2(w1[kk * 512 + n],       w1[(kk + 1) * 512 + n]);
        v.y = pack_bf2(w1[(kk + 8) * 512 + n], w1[(kk + 9) * 512 + n]);
        g_w1F[j] = v;
    } else {
        int j = i - 32768;
        int lane = j & 31, kt = (j >> 5) & 31, nt = j >> 10;
        int n = nt * 8 + (lane >> 2), kk = kt * 16 + 2 * (lane & 3);
        uint2 v;
        v.x = pack_bf2(w2[kk * 128 + n],       w2[(kk + 1) * 128 + n]);
        v.y = pack_bf2(w2[(kk + 8) * 128 + n], w2[(kk + 9) * 128 + n]);
        g_w2F[j] = v;
    }
}

// ---------------- K0b: bias+mask table ----------------
__device__ __forceinline__ float bm_val(const float* __restrict__ rel, int w, int h, int q, int k) {
    if (q >= 49 || k >= 49) return -1e30f;
    int qi = q / 7, qj = q % 7, ki = k / 7, kj = k % 7;
    int r0 = (ki - qi) % 13; if (r0 < 0) r0 += 13;
    int r1 = (kj - qj) % 13; if (r1 < 0) r1 += 13;
    float bias = rel[(r0 * 13 + r1) * HEADS + h];
    int wr = w >> 3, wc = w & 7;
    int idq = region_of(wr * 7 + qi) * 3 + region_of(wc * 7 + qj);
    int idk = region_of(wr * 7 + ki) * 3 + region_of(wc * 7 + kj);
    return bias + (idq == idk ? 0.f : -100.f);
}
__global__ void build_bm(const float* __restrict__ rel) {
    int i = blockIdx.x * blockDim.x + threadIdx.x;   // 262144
    int lane = i & 31, nt = (i >> 5) & 7, mtile = (i >> 8) & 3, h = (i >> 10) & 3, w = i >> 12;
    int g = lane >> 2, s = lane & 3;
    int rA = mtile * 16 + g, rB = rA + 8, cc = nt * 8 + 2 * s;
    float4 v;
    v.x = bm_val(rel, w, h, rA, cc);
    v.y = bm_val(rel, w, h, rA, cc + 1);
    v.z = bm_val(rel, w, h, rB, cc);
    v.w = bm_val(rel, w, h, rB, cc + 1);
    g_bm4[i] = v;
}

// ---------------- K1: fused LN1 + window attention + O-proj + residual ----------------
__global__ void __launch_bounds__(256, 2) attn_kernel(const float* __restrict__ x,
                                                      const float* __restrict__ gam,
                                                      const float* __restrict__ bet,
                                                      const float* __restrict__ bq,
                                                      const float* __restrict__ bk,
                                                      const float* __restrict__ bv,
                                                      const float* __restrict__ bo) {
    extern __shared__ char smraw[];
    __nv_bfloat16* hS = (__nv_bfloat16*)smraw;
    __nv_bfloat16* qS = (__nv_bfloat16*)(smraw + 17408);
    __nv_bfloat16* kS = (__nv_bfloat16*)(smraw + 34816);
    __nv_bfloat16* vT = (__nv_bfloat16*)(smraw + 52224);
    __nv_bfloat16* oS = hS;

    const int win = blockIdx.x, b = win >> 6, w = win & 63;
    const int wr = w >> 3, wc = w & 7;
    const int warp = threadIdx.x >> 5, lane = threadIdx.x & 31;
    const int g = lane >> 2, s = lane & 3;

    const uint2* wqp = g_wqkvF + warp * 6 * 8 * 32 + lane;
    const uint2* wop = g_woF   + warp * 2 * 8 * 32 + lane;

    uint2 bfr[3][8];
    #pragma unroll
    for (int nt = 0; nt < 3; nt++)
        #pragma unroll
        for (int ks = 0; ks < 8; ks++)
            bfr[nt][ks] = wqp[(nt * 8 + ks) * 32];

    {
        const float4 gm = *(const float4*)(gam + lane * 4);
        const float4 bt = *(const float4*)(bet + lane * 4);
        float4 vv[8];
        #pragma unroll
        for (int it = 0; it < 8; it++) {
            const int n = warp + it * 8;
            if (n < 49) {
                const int i = n / 7, j = n % 7;
                const int sh = (wr * 7 + i + 3) % 56, sw = (wc * 7 + j + 3) % 56;
                vv[it] = *(const float4*)(x + ((size_t)b * 3136 + sh * 56 + sw) * CD + lane * 4);
            }
        }
        #pragma unroll
        for (int it = 0; it < 8; it++) {
            const int n = warp + it * 8;
            __nv_bfloat16* dst = hS + n * SH;
            if (n >= 49) {
                ((unsigned*)dst)[lane]      = 0u;
                ((unsigned*)dst)[lane + 32] = 0u;
                continue;
            }
            float4 v = vv[it];
            float sum = v.x + v.y + v.z + v.w;
            float sq  = v.x * v.x + v.y * v.y + v.z * v.z + v.w * v.w;
            #pragma unroll
            for (int o = 16; o; o >>= 1) {
                sum += __shfl_xor_sync(0xffffffffu, sum, o);
                sq  += __shfl_xor_sync(0xffffffffu, sq, o);
            }
            const float mu = sum * (1.f / 128.f);
            const float inv = rsqrtf(sq * (1.f / 128.f) - mu * mu + 1e-5f);
            uint2 o2;
            o2.x = pack_bf2((v.x - mu) * inv * gm.x + bt.x, (v.y - mu) * inv * gm.y + bt.y);
            o2.y = pack_bf2((v.z - mu) * inv * gm.z + bt.z, (v.w - mu) * inv * gm.w + bt.w);
            *(uint2*)(dst + lane * 4) = o2;
        }
    }
    __syncthreads();

    const uint32_t hA  = smemA_base(hS, SH, lane);
    const uint32_t qA  = smemA_base(qS, SH, lane);
    const uint32_t kB4 = smemB4_base(kS, SH, lane);
    const uint32_t vB4 = smemB4_base(vT, SV, lane);

    const float invs = 0.17677669529663687f;  // 1/sqrt(32)
    #pragma unroll
    for (int pass = 0; pass < 2; pass++) {
        float acc[4][3][4];
        #pragma unroll
        for (int mt = 0; mt < 4; mt++)
            #pragma unroll
            for (int nt = 0; nt < 3; nt++)
                #pragma unroll
                for (int r = 0; r < 4; r++) acc[mt][nt][r] = 0.f;
        #pragma unroll
        for (int ks = 0; ks < 8; ks++) {
            #pragma unroll
            for (int mt = 0; mt < 4; mt++) {
                unsigned afr[4];
                ldsm4(afr, hA + (mt * 16 * SH + ks * 16) * 2);
                #pragma unroll
                for (int nt = 0; nt < 3; nt++) mma_bf16_u2(acc[mt][nt], afr, bfr[nt][ks]);
            }
        }
        if (pass == 0) {
            #pragma unroll
            for (int nt = 0; nt < 3; nt++)
                #pragma unroll
                for (int ks = 0; ks < 8; ks++)
                    bfr[nt][ks] = wqp[((3 + nt) * 8 + ks) * 32];
        }
        #pragma unroll
        for (int mt = 0; mt < 4; mt++) {
            #pragma unroll
            for (int nt = 0; nt < 3; nt++) {
                const int nb = warp * 48 + (pass * 3 + nt) * 8;
                const int c0 = nb + 2 * s;
                const int r0 = mt * 16 + g;
                float v0 = acc[mt][nt][0], v1 = acc[mt][nt][1], v2 = acc[mt][nt][2], v3 = acc[mt][nt][3];
                if (nb < 128) {
                    float b0 = bq[c0], b1 = bq[c0 + 1];
                    *(unsigned*)(qS + r0 * SH + c0)       = pack_bf2((v0 + b0) * invs, (v1 + b1) * invs);
                    *(unsigned*)(qS + (r0 + 8) * SH + c0) = pack_bf2((v2 + b0) * invs, (v3 + b1) * invs);
                } else if (nb < 256) {
                    int cc = c0 - 128;
                    float b0 = bk[cc], b1 = bk[cc + 1];
                    *(unsigned*)(kS + r0 * SH + cc)       = pack_bf2(v0 + b0, v1 + b1);
                    *(unsigned*)(kS + (r0 + 8) * SH + cc) = pack_bf2(v2 + b0, v3 + b1);
                } else {
                    int d0 = c0 - 256;
                    float b0 = bv[d0], b1 = bv[d0 + 1];
                    vT[d0 * SV + r0]           = __float2bfloat16_rn(v0 + b0);
                    vT[(d0 + 1) * SV + r0]     = __float2bfloat16_rn(v1 + b1);
                    vT[d0 * SV + r0 + 8]       = __float2bfloat16_rn(v2 + b0);
                    vT[(d0 + 1) * SV + r0 + 8] = __float2bfloat16_rn(v3 + b1);
                }
            }
        }
    }
    __syncthreads();

    const int hw = warp >> 1, mh = warp & 1;
    const float4* bmp = g_bm4 + (((size_t)(w * HEADS + hw) * 4 + mh * 2) * 8) * 32 + lane;

    float4 bmf0[8];
    #pragma unroll
    for (int nt = 0; nt < 8; nt++) bmf0[nt] = bmp[nt * 32];

    float lac[2][8][4];
    #pragma unroll
    for (int mt = 0; mt < 2; mt++)
        #pragma unroll
        for (int nt = 0; nt < 8; nt++)
            #pragma unroll
            for (int r = 0; r < 4; r++) lac[mt][nt][r] = 0.f;

    {
        const uint32_t qBase = qA + (mh * 32 * SH + hw * 32) * 2;
        const uint32_t kBase = kB4 + (hw * 32) * 2;
        #pragma unroll
        for (int ks = 0; ks < 2; ks++) {
            unsigned bfk[8][2];
            #pragma unroll
            for (int ntp = 0; ntp < 4; ntp++) {
                unsigned t4[4];
                ldsm4(t4, kBase + (ntp * 16 * SH + ks * 16) * 2);
                bfk[2 * ntp][0]     = t4[0];
                bfk[2 * ntp][1]     = t4[1];
                bfk[2 * ntp + 1][0] = t4[2];
                bfk[2 * ntp + 1][1] = t4[3];
            }
            #pragma unroll
            for (int mt = 0; mt < 2; mt++) {
                unsigned afr[4];
                ldsm4(afr, qBase + (mt * 16 * SH + ks * 16) * 2);
                #pragma unroll
                for (int nt = 0; nt < 8; nt++) mma_bf16(lac[mt][nt], afr, bfk[nt]);
            }
        }
    }

    float4 bmf1[8];
    #pragma unroll
    for (int mt = 0; mt < 2; mt++) {
        float mA = -1e30f, mB = -1e30f;
        #pragma unroll
        for (int nt = 0; nt < 8; nt++) {
            float4 bv4 = (mt == 0) ? bmf0[nt] : bmf1[nt];
            lac[mt][nt][0] += bv4.x;
            lac[mt][nt][1] += bv4.y;
            lac[mt][nt][2] += bv4.z;
            lac[mt][nt][3] += bv4.w;
            mA = fmaxf(mA, fmaxf(lac[mt][nt][0], lac[mt][nt][1]));
            mB = fmaxf(mB, fmaxf(lac[mt][nt][2], lac[mt][nt][3]));
        }
        if (mt == 0) {
            #pragma unroll
            for (int nt = 0; nt < 8; nt++) bmf1[nt] = bmp[(8 + nt) * 32];
        }
        mA = fmaxf(mA, __shfl_xor_sync(0xffffffffu, mA, 1));
        mA = fmaxf(mA, __shfl_xor_sync(0xffffffffu, mA, 2));
        mB = fmaxf(mB, __shfl_xor_sync(0xffffffffu, mB, 1));
        mB = fmaxf(mB, __shfl_xor_sync(0xffffffffu, mB, 2));
        float sA = 0.f, sB = 0.f;
        #pragma unroll
        for (int nt = 0; nt < 8; nt++) {
            lac[mt][nt][0] = __expf(lac[mt][nt][0] - mA);
            lac[mt][nt][1] = __expf(lac[mt][nt][1] - mA);
            lac[mt][nt][2] = __expf(lac[mt][nt][2] - mB);
            lac[mt][nt][3] = __expf(lac[mt][nt][3] - mB);
            sA += lac[mt][nt][0] + lac[mt][nt][1];
            sB += lac[mt][nt][2] + lac[mt][nt][3];
        }
        sA += __shfl_xor_sync(0xffffffffu, sA, 1);
        sA += __shfl_xor_sync(0xffffffffu, sA, 2);
        sB += __shfl_xor_sync(0xffffffffu, sB, 1);
        sB += __shfl_xor_sync(0xffffffffu, sB, 2);
        const float iA = 1.f / sA, iB = 1.f / sB;
        #pragma unroll
        for (int nt = 0; nt < 8; nt++) {
            lac[mt][nt][0] *= iA; lac[mt][nt][1] *= iA;
            lac[mt][nt][2] *= iB; lac[mt][nt][3] *= iB;
        }
    }

    float oac[2][4][4];
    #pragma unroll
    for (int mt = 0; mt < 2; mt++)
        #pragma unroll
        for (int nt = 0; nt < 4; nt++)
            #pragma unroll
            for (int r = 0; r < 4; r++) oac[mt][nt][r] = 0.f;

    {
        const uint32_t vBase = vB4 + (hw * 32 * SV) * 2;
        #pragma unroll
        for (int kt = 0; kt < 4; kt++) {
            unsigned bfv[4][2];
            #pragma unroll
            for (int ntp = 0; ntp < 2; ntp++) {
                unsigned t4[4];
                ldsm4(t4, vBase + (ntp * 16 * SV + kt * 16) * 2);
                bfv[2 * ntp][0]     = t4[0];
                bfv[2 * ntp][1]     = t4[1];
                bfv[2 * ntp + 1][0] = t4[2];
                bfv[2 * ntp + 1][1] = t4[3];
            }
            #pragma unroll
            for (int mt = 0; mt < 2; mt++) {
                unsigned pa[4];
                pa[0] = pack_bf2(lac[mt][2 * kt][0],     lac[mt][2 * kt][1]);
                pa[1] = pack_bf2(lac[mt][2 * kt][2],     lac[mt][2 * kt][3]);
                pa[2] = pack_bf2(lac[mt][2 * kt + 1][0], lac[mt][2 * kt + 1][1]);
                pa[3] = pack_bf2(lac[mt][2 * kt + 1][2], lac[mt][2 * kt + 1][3]);
                #pragma unroll
                for (int nt = 0; nt < 4; nt++) mma_bf16(oac[mt][nt], pa, bfv[nt]);
            }
        }
    }

    // ---- prefetch O-proj weights AND residual x rows before the store+barrier
    //      (xr loads now overlap the oS stores, barrier drain, and O-proj MMAs)
    uint2 bfo[2][8];
    #pragma unroll
    for (int nt = 0; nt < 2; nt++)
        #pragma unroll
        for (int ks = 0; ks < 8; ks++)
            bfo[nt][ks] = wop[(nt * 8 + ks) * 32];

    float2 xr[4][2][2];
    #pragma unroll
    for (int mt = 0; mt < 4; mt++) {
        #pragma unroll
        for (int nt = 0; nt < 2; nt++) {
            const int c = warp * 16 + nt * 8 + 2 * s;
            const int r0 = mt * 16 + g, r1 = r0 + 8;
            if (r0 < 49)
                xr[mt][nt][0] = *(const float2*)(x + ((size_t)b * 3136 + w * 49 + r0) * CD + c);
            if (r1 < 49)
                xr[mt][nt][1] = *(const float2*)(x + ((size_t)b * 3136 + w * 49 + r1) * CD + c);
        }
    }

    #pragma unroll
    for (int mt = 0; mt < 2; mt++) {
        #pragma unroll
        for (int nt = 0; nt < 4; nt++) {
            const int r0 = mh * 32 + mt * 16 + g;
            const int c0 = hw * 32 + nt * 8 + 2 * s;
            *(unsigned*)(oS + r0 * SH + c0)       = pack_bf2(oac[mt][nt][0], oac[mt][nt][1]);
            *(unsigned*)(oS + (r0 + 8) * SH + c0) = pack_bf2(oac[mt][nt][2], oac[mt][nt][3]);
        }
    }
    __syncthreads();

    float fac[4][2][4];
    #pragma unroll
    for (int mt = 0; mt < 4; mt++)
        #pragma unroll
        for (int nt = 0; nt < 2; nt++)
            #pragma unroll
            for (int r = 0; r < 4; r++) fac[mt][nt][r] = 0.f;

    #pragma unroll
    for (int ks = 0; ks < 8; ks++) {
        #pragma unroll
        for (int mt = 0; mt < 4; mt++) {
            unsigned afr[4];
            ldsm4(afr, hA + (mt * 16 * SH + ks * 16) * 2);
            #pragma unroll
            for (int nt = 0; nt < 2; nt++) mma_bf16_u2(fac[mt][nt], afr, bfo[nt][ks]);
        }
    }

    #pragma unroll
    for (int mt = 0; mt < 4; mt++) {
        #pragma unroll
        for (int nt = 0; nt < 2; nt++) {
            const int c = warp * 16 + nt * 8 + 2 * s;
            const float bo0 = bo[c], bo1 = bo[c + 1];
            const int r0 = mt * 16 + g, r1 = r0 + 8;
            if (r0 < 49) {
                size_t p = ((size_t)b * 3136 + w * 49 + r0) * CD + c;
                float2 o;
                o.x = fac[mt][nt][0] + bo0 + xr[mt][nt][0].x;
                o.y = fac[mt][nt][1] + bo1 + xr[mt][nt][0].y;
                *(float2*)(g_y + p) = o;
            }
            if (r1 < 49) {
                size_t p = ((size_t)b * 3136 + w * 49 + r1) * CD + c;
                float2 o;
                o.x = fac[mt][nt][2] + bo0 + xr[mt][nt][1].x;
                o.y = fac[mt][nt][3] + bo1 + xr[mt][nt][1].y;
                *(float2*)(g_y + p) = o;
            }
        }
    }
}

// ---------------- K2: fused LN2 + MLP + residual (R14, fully pipelined weights) ----------------
__global__ void __launch_bounds__(256, 2) mlp_kernel(const float* __restrict__ g2,
                                                     const float* __restrict__ be2,
                                                     const float* __restrict__ b1,
                                                     const float* __restrict__ b2,
                                                     float* __restrict__ out) {
    extern __shared__ char smraw[];
    __nv_bfloat16* mS = (__nv_bfloat16*)smraw;                   // 64 x SH   (17408 B)
    __nv_bfloat16* hS = (__nv_bfloat16*)(smraw + 17408);         // 64 x SH2  (66560 B)

    const int t0 = blockIdx.x * 64;
    const int warp = threadIdx.x >> 5, lane = threadIdx.x & 31;
    const int wm = warp >> 2, wn = warp & 3;          // 2x4 warp grid

    const uint2* w1p = g_w1F + lane;
    const uint2* w2p = g_w2F + lane;

    // prefetch GEMM1 sc=0 weights (overlaps LN2 gather)
    uint2 bf[4][8];
    #pragma unroll
    for (int nt = 0; nt < 4; nt++)
        #pragma unroll
        for (int ks = 0; ks < 8; ks++)
            bf[nt][ks] = w1p[((wn * 4 + nt) * 8 + ks) * 32];

    // ---- LN2 into mS, batched gather preload
    {
        const float4 gm = *(const float4*)(g2 + lane * 4);
        const float4 bt = *(const float4*)(be2 + lane * 4);
        float4 vv[8];
        #pragma unroll
        for (int it = 0; it < 8; it++) {
            const int r = warp + it * 8;
            vv[it] = *(const float4*)(g_y + ((size_t)(t0 + r)) * CD + lane * 4);
        }
        #pragma unroll
        for (int it = 0; it < 8; it++) {
            const int r = warp + it * 8;
            float4 v = vv[it];
            float sum = v.x + v.y + v.z + v.w;
            float sq  = v.x * v.x + v.y * v.y + v.z * v.z + v.w * v.w;
            #pragma unroll
            for (int o = 16; o; o >>= 1) {
                sum += __shfl_xor_sync(0xffffffffu, sum, o);
                sq  += __shfl_xor_sync(0xffffffffu, sq, o);
            }
            const float mu = sum * (1.f / 128.f);
            const float inv = rsqrtf(sq * (1.f / 128.f) - mu * mu + 1e-5f);
            uint2 o2;
            o2.x = pack_bf2((v.x - mu) * inv * gm.x + bt.x, (v.y - mu) * inv * gm.y + bt.y);
            o2.y = pack_bf2((v.z - mu) * inv * gm.z + bt.z, (v.w - mu) * inv * gm.w + bt.w);
            *(uint2*)(mS + r * SH + lane * 4) = o2;
        }
    }
    __syncthreads();

    const int g = lane >> 2, s = lane & 3;
    const uint32_t mA = smemA_base(mS, SH,  lane) + (wm * 32 * SH)  * 2;
    const uint32_t hA = smemA_base(hS, SH2, lane) + (wm * 32 * SH2) * 2;

    // ---- GEMM1 over full N=512, 4 sub-chunks per warp; sc+1 weights prefetched
    #pragma unroll
    for (int sc = 0; sc < 4; sc++) {
        const int ntb = sc * 16 + wn * 4;

        float acc[2][4][4];
        #pragma unroll
        for (int mt = 0; mt < 2; mt++)
            #pragma unroll
            for (int nt = 0; nt < 4; nt++)
                #pragma unroll
                for (int r = 0; r < 4; r++) acc[mt][nt][r] = 0.f;

        #pragma unroll
        for (int ks = 0; ks < 8; ks++) {
            #pragma unroll
            for (int mt = 0; mt < 2; mt++) {
                unsigned afr[4];
                ldsm4(afr, mA + (mt * 16 * SH + ks * 16) * 2);
                #pragma unroll
                for (int nt = 0; nt < 4; nt++) mma_bf16_u2(acc[mt][nt], afr, bf[nt][ks]);
            }
        }

        if (sc < 3) {
            const int ntb2 = (sc + 1) * 16 + wn * 4;
            #pragma unroll
            for (int nt = 0; nt < 4; nt++)
                #pragma unroll
                for (int ks = 0; ks < 8; ks++)
                    bf[nt][ks] = w1p[((ntb2 + nt) * 8 + ks) * 32];
        }

        #pragma unroll
        for (int mt = 0; mt < 2; mt++) {
            #pragma unroll
            for (int nt = 0; nt < 4; nt++) {
                const int cg = (ntb + nt) * 8 + 2 * s;
                const float bb0 = b1[cg], bb1 = b1[cg + 1];
                const int r0 = wm * 32 + mt * 16 + g;
                *(unsigned*)(hS + r0 * SH2 + cg) =
                    pack_bf2(gelu_fast(acc[mt][nt][0] + bb0), gelu_fast(acc[mt][nt][1] + bb1));
                *(unsigned*)(hS + (r0 + 8) * SH2 + cg) =
                    pack_bf2(gelu_fast(acc[mt][nt][2] + bb0), gelu_fast(acc[mt][nt][3] + bb1));
            }
        }
    }

    // ---- prefetch GEMM2 kb=0 weights BEFORE the barrier
    uint2 cf[2][4][8];
    #pragma unroll
    for (int nt = 0; nt < 4; nt++)
        #pragma unroll
        for (int ks = 0; ks < 8; ks++)
            cf[0][nt][ks] = w2p[(wn * 4 + nt) * 1024 + ks * 32];

    __syncthreads();

    // ---- GEMM2: M=64, N=128 (warp 32x32), K=512, weights pipelined across kb
    float fac[2][4][4];
    #pragma unroll
    for (int mt = 0; mt < 2; mt++)
        #pragma unroll
        for (int nt = 0; nt < 4; nt++)
            #pragma unroll
            for (int r = 0; r < 4; r++) fac[mt][nt][r] = 0.f;

    float2 yr[2][4][2];
    #pragma unroll
    for (int kb = 0; kb < 4; kb++) {
        const int cur = kb & 1;
        if (kb < 3) {
            #pragma unroll
            for (int nt = 0; nt < 4; nt++)
                #pragma unroll
                for (int ks = 0; ks < 8; ks++)
                    cf[cur ^ 1][nt][ks] = w2p[(wn * 4 + nt) * 1024 + ((kb + 1) * 8 + ks) * 32];
        } else {
            #pragma unroll
            for (int mt = 0; mt < 2; mt++)
                #pragma unroll
                for (int nt = 0; nt < 4; nt++) {
                    const int c = wn * 32 + nt * 8 + 2 * s;
                    const int r0 = wm * 32 + mt * 16 + g;
                    yr[mt][nt][0] = *(const float2*)(g_y + ((size_t)(t0 + r0)) * CD + c);
                    yr[mt][nt][1] = *(const float2*)(g_y + ((size_t)(t0 + r0 + 8)) * CD + c);
                }
        }
        #pragma unroll
        for (int ks = 0; ks < 8; ks++) {
            const int kk = kb * 8 + ks;
            #pragma unroll
            for (int mt = 0; mt < 2; mt++) {
                unsigned afr[4];
                ldsm4(afr, hA + (mt * 16 * SH2 + kk * 16) * 2);
                #pragma unroll
                for (int nt = 0; nt < 4; nt++) mma_bf16_u2(fac[mt][nt], afr, cf[cur][nt][ks]);
            }
        }
    }

    // epilogue: + b2 + residual (prefetched) -> out
    #pragma unroll
    for (int mt = 0; mt < 2; mt++) {
        #pragma unroll
        for (int nt = 0; nt < 4; nt++) {
            const int c = wn * 32 + nt * 8 + 2 * s;
            const float bb0 = b2[c], bb1 = b2[c + 1];
            const int r0 = wm * 32 + mt * 16 + g;
            size_t p0 = ((size_t)(t0 + r0)) * CD + c;
            size_t p1 = ((size_t)(t0 + r0 + 8)) * CD + c;
            float2 o0, o1;
            o0.x = fac[mt][nt][0] + bb0 + yr[mt][nt][0].x;
            o0.y = fac[mt][nt][1] + bb1 + yr[mt][nt][0].y;
            o1.x = fac[mt][nt][2] + bb0 + yr[mt][nt][1].x;
            o1.y = fac[mt][nt][3] + bb1 + yr[mt][nt][1].y;
            *(float2*)(out + p0) = o0;
            *(float2*)(out + p1) = o1;
        }
    }
}

// ---------------- launch ----------------
extern "C" void kernel_launch(void* const* d_in, const int* in_sizes, int n_in,
                              void* d_out, int out_size) {
    const float* x   = (const float*)d_in[0];
    const float* wq  = (const float*)d_in[1];
    const float* bq  = (const float*)d_in[2];
    const float* wk  = (const float*)d_in[3];
    const float* bk  = (const float*)d_in[4];
    const float* wv  = (const float*)d_in[5];
    const float* bv  = (const float*)d_in[6];
    const float* wo  = (const float*)d_in[7];
    const float* bo  = (const float*)d_in[8];
    const float* rel = (const float*)d_in[9];
    const float* g1  = (const float*)d_in[10];
    const float* be1 = (const float*)d_in[11];
    const float* g2  = (const float*)d_in[12];
    const float* be2 = (const float*)d_in[13];
    const float* w1  = (const float*)d_in[14];
    const float* b1  = (const float*)d_in[15];
    const float* w2  = (const float*)d_in[16];
    const float* b2  = (const float*)d_in[17];
    float* out = (float*)d_out;

    cudaFuncSetAttribute(attn_kernel, cudaFuncAttributeMaxDynamicSharedMemorySize, 70656);
    cudaFuncSetAttribute(mlp_kernel,  cudaFuncAttributeMaxDynamicSharedMemorySize, 83968);

    pack_weights<<<192, 256>>>(wq, wk, wv, wo, w1, w2);
    build_bm<<<1024, 256>>>(rel);
    attn_kernel<<<4096, 256, 70656>>>(x, g1, be1, bq, bk, bv, bo);
    mlp_kernel<<<3136, 256, 83968>>>(g2, be2, b1, b2, out);
}